// round 9
// baseline (speedup 1.0000x reference)
#include <cuda_runtime.h>
#include <math.h>
#include <stdint.h>

#define D_NUM 1500
#define P_NUM 4500
#define NTOT  6000
#define EMB   128
#define CAP_DD 64
#define CAP_PP 128
#define DB (D_NUM*EMB)
#define PB (P_NUM*EMB)
#define MEGA_BLKS 296
#define MEGA_THREADS 256

// ---------------- scratch (static __device__, no allocs) ----------------
__device__ __align__(128) int g_idx2[D_NUM*CAP_DD]; __device__ int g_len2[D_NUM];
__device__ __align__(128) int g_idx4[D_NUM*CAP_DD]; __device__ int g_len4[D_NUM];
__device__ __align__(128) int g_idx3[P_NUM*CAP_PP]; __device__ int g_len3[P_NUM];
__device__ __align__(128) int g_idxR[D_NUM*CAP_PP]; __device__ int g_lenR[D_NUM];
__device__ __align__(128) int g_idxRT[P_NUM*CAP_DD]; __device__ int g_curRT[P_NUM];

__device__ float g_dinv2[D_NUM], g_cinv2[D_NUM];
__device__ float g_dinv3[P_NUM], g_cinv3[P_NUM];
__device__ float g_dinv4[D_NUM];
__device__ float g_dinvRd[D_NUM], g_cinvRd[D_NUM];
__device__ float g_dinvRp[P_NUM], g_cinvRp[P_NUM];

__device__ __align__(128) float g_dru_str[DB], g_pro_str[PB];
__device__ __align__(128) float g_nei2[DB],    g_nei3[PB];
__device__ __align__(128) float g_emb2[DB],    g_emb3[PB],  g_emb4[DB];
__device__ __align__(128) float g_curD[DB],    g_cur3[PB];
__device__ __align__(128) float g_x2a[DB], g_x2b[DB], g_x4a[DB], g_x4b[DB];
__device__ __align__(128) float g_x3a[PB], g_x3b[PB];
__device__ __align__(128) float g_acc2[DB], g_acc3[PB], g_acc4[DB];
__device__ __align__(128) float g_one_emb[DB], g_two_all[PB], g_one_all[DB], g_two_emb[PB];
__device__ __align__(128) float g_bd1[DB],  g_bp1[PB], g_bp2[PB];
__device__ __align__(128) float g_bdx[DB],  g_bpx[PB], g_bdy[DB];
__device__ __align__(128) float g_accd[DB], g_accp[PB];
__device__ __align__(128) float g_dru_int[DB], g_pro_int[PB];
__device__ __align__(128) float g_tmpp[PB], g_Wc[EMB*EMB];
__device__ __align__(128) float g_fin_d[DB], g_fin_p[PB];
__device__ float g_wdrug[D_NUM], g_wdrel[D_NUM], g_wdsim[D_NUM];
__device__ float g_wpro[P_NUM],  g_wprel[P_NUM];
__device__ __align__(128) float g_gd[EMB*EMB], g_gp[EMB*EMB];
__device__ float g_sd[EMB], g_sp[EMB];
__device__ float2 g_musig;
__device__ __align__(128) unsigned g_cnt8[8 * 32];  // bucket counters, 128B apart
__device__ unsigned g_master = 0;
__device__ unsigned g_gen = 0;
__device__ int g_nopsink;

// ---------------- ELL extraction: ballot-scan with sparse early-out --------
__global__ void k_ell_all(const float* __restrict__ A) {
    const size_t NN = (size_t)NTOT * NTOT;
    int b = blockIdx.x;
    // side job: zero g_curRT (blocks 0..17)
    {
        int gid = b * 256 + threadIdx.x;
        if (gid < P_NUM) g_curRT[gid] = 0;
    }
    const float* base; int r, row0, col0, ncols, cap; int *idx, *len;
    if (b < 1500)      { base = A + 2*NN; r = b;        row0 = 0;     col0 = 0;     ncols = D_NUM; cap = CAP_DD; idx = g_idx2; len = g_len2; }
    else if (b < 6000) { base = A + 3*NN; r = b - 1500; row0 = D_NUM; col0 = D_NUM; ncols = P_NUM; cap = CAP_PP; idx = g_idx3; len = g_len3; }
    else if (b < 7500) { base = A + 4*NN; r = b - 6000; row0 = 0;     col0 = 0;     ncols = D_NUM; cap = CAP_DD; idx = g_idx4; len = g_len4; }
    else               { base = A;        r = b - 7500; row0 = 0;     col0 = D_NUM; ncols = P_NUM; cap = CAP_PP; idx = g_idxR; len = g_lenR; }

    const float4* row4 = (const float4*)(base + (size_t)(row0 + r) * NTOT + col0);
    int nv = ncols >> 2;
    __shared__ int s_wsum[2][8];
    __shared__ int s_base[2];

    float4 v[5];
#pragma unroll
    for (int u = 0; u < 5; u++) {
        int i = threadIdx.x + (u << 8);
        if (i < nv) v[u] = __ldg(&row4[i]);
    }
    if (threadIdx.x == 0) s_base[0] = 0;
    __syncthreads();
    int nch = (nv + 255) >> 8;
    int lane = threadIdx.x & 31, wd = threadIdx.x >> 5;
    for (int u = 0; u < nch; u++) {
        int i = threadIdx.x + (u << 8);
        unsigned m = 0; int cnt = 0;
        if (i < nv) {
            m = (v[u].x == 1.0f ? 1u : 0u) | (v[u].y == 1.0f ? 2u : 0u)
              | (v[u].z == 1.0f ? 4u : 0u) | (v[u].w == 1.0f ? 8u : 0u);
            cnt = __popc(m);
        }
        int incl = cnt;
        // early-out: most warps have zero matches — skip the scan machinery
        if (__ballot_sync(0xffffffffu, cnt != 0)) {
#pragma unroll
            for (int o = 1; o < 32; o <<= 1) {
                int t2 = __shfl_up_sync(0xffffffffu, incl, o);
                if (lane >= o) incl += t2;
            }
        }
        if (lane == 31) s_wsum[u & 1][wd] = incl;
        __syncthreads();
        if (m) {
            int basev = s_base[u & 1];
            for (int w = 0; w < wd; w++) basev += s_wsum[u & 1][w];
            int off = basev + incl - cnt;
#pragma unroll
            for (int b2 = 0; b2 < 4; b2++)
                if ((m >> b2) & 1) {
                    if (off < cap) idx[(size_t)r * cap + off] = (i << 2) + b2;
                    off++;
                }
        }
        if (threadIdx.x == 0) {
            int s = s_base[u & 1];
            for (int w = 0; w < 8; w++) s += s_wsum[u & 1][w];
            s_base[(u + 1) & 1] = s;
        }
        __syncthreads();
    }
    if (threadIdx.x == 0) len[r] = min(s_base[nch & 1], cap);
}

// ------------- hierarchical grid barrier (8 buckets -> master -> gen) ------
__device__ __forceinline__ void gsync() {
    __syncthreads();
    if (threadIdx.x == 0) {
        unsigned mygen;
        asm volatile("ld.acquire.gpu.global.u32 %0, [%1];"
                     : "=r"(mygen) : "l"(&g_gen) : "memory");
        __threadfence();
        int bucket = blockIdx.x & 7;
        unsigned nb = (gridDim.x + 7u - bucket) >> 3;
        unsigned old = atomicAdd(&g_cnt8[bucket * 32], 1u);
        if (old == nb - 1) {
            g_cnt8[bucket * 32] = 0;
            __threadfence();
            unsigned mm = atomicAdd(&g_master, 1u);
            if (mm == 7) {
                g_master = 0;
                __threadfence();
                atomicAdd(&g_gen, 1u);
            }
        }
        unsigned vv;
        do {
            asm volatile("ld.acquire.gpu.global.u32 %0, [%1];"
                         : "=r"(vv) : "l"(&g_gen) : "memory");
        } while (vv == mygen);
        __threadfence();
    }
    __syncthreads();
}

// ---------------- register-tiled GEMM: C(n x 128) = A(n x k) @ W + bias ----
// 64-row x 128-col tile per block, 8x4 per thread, k-major smem, float4 LDS.
__device__ void gemm_dev(const float* A, int n, int k,
                         const float* W, const float* bias,
                         float* C, float* C2, float* C3, float* sbuf) {
    float* As = sbuf;            // [32][68] k-major
    float* Ws = sbuf + 32 * 68;  // [32][132]
    int ntiles = (n + 63) >> 6;
    int t = threadIdx.x;
    int tx = t & 31, ty = t >> 5;
    int m0 = ty << 3, n0 = tx << 2;
    for (int tile = blockIdx.x; tile < ntiles; tile += gridDim.x) {
        int r0 = tile << 6;
        float acc[8][4];
#pragma unroll
        for (int i = 0; i < 8; i++)
#pragma unroll
            for (int j = 0; j < 4; j++) acc[i][j] = 0.f;
        for (int k0 = 0; k0 < k; k0 += 32) {
            __syncthreads();
#pragma unroll
            for (int e = t; e < 512; e += 256) {       // A: 64 rows x 8 float4
                int rr = e >> 3, kv = e & 7;
                int gr = r0 + rr;
                float4 va = (gr < n) ? *(const float4*)&A[(size_t)gr * k + k0 + (kv << 2)]
                                     : make_float4(0.f, 0.f, 0.f, 0.f);
                As[(kv * 4 + 0) * 68 + rr] = va.x;
                As[(kv * 4 + 1) * 68 + rr] = va.y;
                As[(kv * 4 + 2) * 68 + rr] = va.z;
                As[(kv * 4 + 3) * 68 + rr] = va.w;
            }
#pragma unroll
            for (int e = t; e < 1024; e += 256) {      // W: 32 k x 32 float4
                int kk = e >> 5, cv = e & 31;
                *(float4*)&Ws[kk * 132 + (cv << 2)] =
                    *(const float4*)&W[(size_t)(k0 + kk) * EMB + (cv << 2)];
            }
            __syncthreads();
#pragma unroll
            for (int kk = 0; kk < 32; kk++) {
                float4 a0 = *(const float4*)&As[kk * 68 + m0];
                float4 a1 = *(const float4*)&As[kk * 68 + m0 + 4];
                float4 w  = *(const float4*)&Ws[kk * 132 + n0];
                float av[8] = {a0.x, a0.y, a0.z, a0.w, a1.x, a1.y, a1.z, a1.w};
#pragma unroll
                for (int i = 0; i < 8; i++) {
                    acc[i][0] += av[i] * w.x;
                    acc[i][1] += av[i] * w.y;
                    acc[i][2] += av[i] * w.z;
                    acc[i][3] += av[i] * w.w;
                }
            }
        }
        float4 bb = bias ? *(const float4*)&bias[n0] : make_float4(0.f, 0.f, 0.f, 0.f);
#pragma unroll
        for (int i = 0; i < 8; i++) {
            int gr = r0 + m0 + i;
            if (gr < n) {
                float4 vv = make_float4(acc[i][0] + bb.x, acc[i][1] + bb.y,
                                        acc[i][2] + bb.z, acc[i][3] + bb.w);
                *(float4*)&C[(size_t)gr * EMB + n0] = vv;
                if (C2) *(float4*)&C2[(size_t)gr * EMB + n0] = vv;
                if (C3) *(float4*)&C3[(size_t)gr * EMB + n0] = vv;
            }
        }
    }
}

// attention on the same tile: s[r] = sum_c relu(emb@W + B)[c]*H[c]
__device__ void att_dev(const float* emb, const float* W, const float* B,
                        const float* H, float* s, int n, float* sbuf) {
    float* As = sbuf;
    float* Ws = sbuf + 32 * 68;
    int ntiles = (n + 63) >> 6;
    int t = threadIdx.x;
    int tx = t & 31, ty = t >> 5;
    int m0 = ty << 3, n0 = tx << 2;
    for (int tile = blockIdx.x; tile < ntiles; tile += gridDim.x) {
        int r0 = tile << 6;
        float acc[8][4];
#pragma unroll
        for (int i = 0; i < 8; i++)
#pragma unroll
            for (int j = 0; j < 4; j++) acc[i][j] = 0.f;
        for (int k0 = 0; k0 < EMB; k0 += 32) {
            __syncthreads();
#pragma unroll
            for (int e = t; e < 512; e += 256) {
                int rr = e >> 3, kv = e & 7;
                int gr = r0 + rr;
                float4 va = (gr < n) ? *(const float4*)&emb[(size_t)gr * EMB + k0 + (kv << 2)]
                                     : make_float4(0.f, 0.f, 0.f, 0.f);
                As[(kv * 4 + 0) * 68 + rr] = va.x;
                As[(kv * 4 + 1) * 68 + rr] = va.y;
                As[(kv * 4 + 2) * 68 + rr] = va.z;
                As[(kv * 4 + 3) * 68 + rr] = va.w;
            }
#pragma unroll
            for (int e = t; e < 1024; e += 256) {
                int kk = e >> 5, cv = e & 31;
                *(float4*)&Ws[kk * 132 + (cv << 2)] =
                    *(const float4*)&W[(size_t)(k0 + kk) * EMB + (cv << 2)];
            }
            __syncthreads();
#pragma unroll
            for (int kk = 0; kk < 32; kk++) {
                float4 a0 = *(const float4*)&As[kk * 68 + m0];
                float4 a1 = *(const float4*)&As[kk * 68 + m0 + 4];
                float4 w  = *(const float4*)&Ws[kk * 132 + n0];
                float av[8] = {a0.x, a0.y, a0.z, a0.w, a1.x, a1.y, a1.z, a1.w};
#pragma unroll
                for (int i = 0; i < 8; i++) {
                    acc[i][0] += av[i] * w.x;
                    acc[i][1] += av[i] * w.y;
                    acc[i][2] += av[i] * w.z;
                    acc[i][3] += av[i] * w.w;
                }
            }
        }
        float4 bb = *(const float4*)&B[n0];
        float4 hh = *(const float4*)&H[n0];
#pragma unroll
        for (int i = 0; i < 8; i++) {
            float p = fmaxf(acc[i][0] + bb.x, 0.f) * hh.x
                    + fmaxf(acc[i][1] + bb.y, 0.f) * hh.y
                    + fmaxf(acc[i][2] + bb.z, 0.f) * hh.z
                    + fmaxf(acc[i][3] + bb.w, 0.f) * hh.w;
#pragma unroll
            for (int o = 16; o; o >>= 1) p += __shfl_down_sync(0xffffffffu, p, o);
            if (tx == 0) {
                int gr = r0 + m0 + i;
                if (gr < n) s[gr] = p;
            }
        }
    }
}

__device__ void spmm_dev(const int* idx, const int* len, int cap,
                         const float* rs, const float* cs, const float* x,
                         float* out, float* acc, float* fin, float fscale,
                         const float* mixb, float* mixo, int n) {
    int nw = (gridDim.x * blockDim.x) >> 5;
    int gw = (blockIdx.x * blockDim.x + threadIdx.x) >> 5;
    int lane = threadIdx.x & 31;
    const float4* x4 = (const float4*)x;
    for (int r = gw; r < n; r += nw) {
        int L = len[r];
        float4 s = make_float4(0.f, 0.f, 0.f, 0.f);
        for (int p0 = 0; p0 < L; p0 += 32) {
            int j = 0; float f = 0.f;
            if (p0 + lane < L) {
                j = idx[(size_t)r * cap + p0 + lane];
                f = cs ? cs[j] : 1.0f;
            }
            int m = min(32, L - p0);
            int q = 0;
            for (; q + 4 <= m; q += 4) {
                int j0 = __shfl_sync(0xffffffffu, j, q);
                int j1 = __shfl_sync(0xffffffffu, j, q + 1);
                int j2 = __shfl_sync(0xffffffffu, j, q + 2);
                int j3 = __shfl_sync(0xffffffffu, j, q + 3);
                float f0 = __shfl_sync(0xffffffffu, f, q);
                float f1 = __shfl_sync(0xffffffffu, f, q + 1);
                float f2 = __shfl_sync(0xffffffffu, f, q + 2);
                float f3 = __shfl_sync(0xffffffffu, f, q + 3);
                float4 v0 = x4[(size_t)j0 * 32 + lane];
                float4 v1 = x4[(size_t)j1 * 32 + lane];
                float4 v2 = x4[(size_t)j2 * 32 + lane];
                float4 v3 = x4[(size_t)j3 * 32 + lane];
                s.x += f0 * v0.x + f1 * v1.x + f2 * v2.x + f3 * v3.x;
                s.y += f0 * v0.y + f1 * v1.y + f2 * v2.y + f3 * v3.y;
                s.z += f0 * v0.z + f1 * v1.z + f2 * v2.z + f3 * v3.z;
                s.w += f0 * v0.w + f1 * v1.w + f2 * v2.w + f3 * v3.w;
            }
            for (; q < m; q++) {
                int j0 = __shfl_sync(0xffffffffu, j, q);
                float f0 = __shfl_sync(0xffffffffu, f, q);
                float4 v0 = x4[(size_t)j0 * 32 + lane];
                s.x += f0 * v0.x; s.y += f0 * v0.y;
                s.z += f0 * v0.z; s.w += f0 * v0.w;
            }
        }
        float rr = rs[r];
        s.x *= rr; s.y *= rr; s.z *= rr; s.w *= rr;
        size_t o = (size_t)r * 32 + lane;
        if (out) ((float4*)out)[o] = s;
        if (acc) {
            float4 a = ((const float4*)acc)[o];
            a.x += s.x; a.y += s.y; a.z += s.z; a.w += s.w;
            ((float4*)acc)[o] = a;
            if (fin) {
                float4 ff = make_float4(a.x * fscale, a.y * fscale, a.z * fscale, a.w * fscale);
                ((float4*)fin)[o] = ff;
            }
        }
        if (mixo) {
            float4 mb = ((const float4*)mixb)[o];
            float4 mo = make_float4(0.8f * mb.x + 0.2f * s.x, 0.8f * mb.y + 0.2f * s.y,
                                    0.8f * mb.z + 0.2f * s.z, 0.8f * mb.w + 0.2f * s.w);
            ((float4*)mixo)[o] = mo;
        }
    }
}

__device__ void ls_dev(float* s, int n, float* sh) {
    int t = threadIdx.x;
    float m = -1e30f;
    for (int i = t; i < n; i += MEGA_THREADS) m = fmaxf(m, s[i]);
    sh[t] = m; __syncthreads();
    for (int o = 128; o; o >>= 1) { if (t < o) sh[t] = fmaxf(sh[t], sh[t + o]); __syncthreads(); }
    float mall = sh[0]; __syncthreads();
    float sum = 0.0f;
    for (int i = t; i < n; i += MEGA_THREADS) sum += expf(s[i] - mall);
    sh[t] = sum; __syncthreads();
    for (int o = 128; o; o >>= 1) { if (t < o) sh[t] += sh[t + o]; __syncthreads(); }
    float lse = mall + logf(sh[0]);
    __syncthreads();
    for (int i = t; i < n; i += MEGA_THREADS) s[i] -= lse;
}

// ---------------- the megakernel ----------------
__global__ void __launch_bounds__(MEGA_THREADS, 2) k_mega(
    const float* __restrict__ drug_structure, const float* __restrict__ protein_structure,
    const float* __restrict__ lin_drug_w, const float* __restrict__ lin_drug_b,
    const float* __restrict__ lin_pro_w, const float* __restrict__ lin_pro_b,
    const float* __restrict__ p_weight, const float* __restrict__ d_weight_i,
    const float* __restrict__ pd_weight_p, const float* __restrict__ pd_weight_d,
    const float* __restrict__ dp_weight_p,
    const float* __restrict__ WA_drug, const float* __restrict__ BA_drug, const float* __restrict__ HA_drug,
    const float* __restrict__ WB_drug, const float* __restrict__ BB_drug, const float* __restrict__ HB_drug,
    const float* __restrict__ WA_pro, const float* __restrict__ BA_pro, const float* __restrict__ HA_pro,
    const float* __restrict__ WB_pro, const float* __restrict__ BB_pro, const float* __restrict__ HB_pro,
    const float* __restrict__ WA_sim, const float* __restrict__ BA_sim, const float* __restrict__ HA_sim) {
    __shared__ __align__(16) float sbuf[16 * 512];

    // ---- P1: build R^T + degree scales + zero gram accums + lifts + Wc
    {
        int nw = (gridDim.x * blockDim.x) >> 5;
        int gw = (blockIdx.x * blockDim.x + threadIdx.x) >> 5;
        int lane = threadIdx.x & 31;
        for (int r = gw; r < D_NUM; r += nw) {
            int L = g_lenR[r];
            for (int p = lane; p < L; p += 32) {
                int c = g_idxR[r * CAP_PP + p];
                int pos = atomicAdd(&g_curRT[c], 1);
                if (pos < CAP_DD) g_idxRT[c * CAP_DD + pos] = r;
            }
        }
        int i = blockIdx.x * blockDim.x + threadIdx.x;
        if (i < D_NUM) {
            int d;
            d = g_len2[i]; g_dinv2[i] = d > 0 ? rsqrtf((float)d) : 0.0f;
                           g_cinv2[i] = d > 0 ? 1.0f / (float)d : 0.0f;
            d = g_len4[i]; g_dinv4[i] = d > 0 ? rsqrtf((float)d) : 0.0f;
            d = g_lenR[i]; g_dinvRd[i] = d > 0 ? rsqrtf((float)d) : 0.0f;
                           g_cinvRd[i] = d > 0 ? 1.0f / (float)d : 0.0f;
        }
        if (i < P_NUM) {
            int d = g_len3[i];
            g_dinv3[i] = d > 0 ? rsqrtf((float)d) : 0.0f;
            g_cinv3[i] = d > 0 ? 1.0f / (float)d : 0.0f;
        }
        int stride = gridDim.x * blockDim.x;
        for (int q = i; q < EMB * EMB; q += stride) { g_gd[q] = 0.f; g_gp[q] = 0.f; }
        if (i < EMB) { g_sd[i] = 0.f; g_sp[i] = 0.f; }
        gemm_dev(drug_structure, D_NUM, 160, lin_drug_w, lin_drug_b, g_dru_str, 0, 0, sbuf);
        gemm_dev(protein_structure, P_NUM, 512, lin_pro_w, lin_pro_b, g_pro_str, 0, 0, sbuf);
        gemm_dev(dp_weight_p, 128, 128, pd_weight_d, 0, g_Wc, 0, 0, sbuf);
    }
    gsync();

    // ---- P2: sort R^T rows + protein-side R scales
    {
        int i = blockIdx.x * blockDim.x + threadIdx.x;
        if (i < P_NUM) {
            int L = min(g_curRT[i], CAP_DD);
            g_curRT[i] = L;
            int* a = &g_idxRT[i * CAP_DD];
            for (int q = 1; q < L; q++) {
                int v = a[q]; int jj = q - 1;
                while (jj >= 0 && a[jj] > v) { a[jj + 1] = a[jj]; jj--; }
                a[jj + 1] = v;
            }
            g_dinvRp[i] = L > 0 ? rsqrtf((float)L) : 0.0f;
            g_cinvRp[i] = L > 0 ? 1.0f / (float)L : 0.0f;
        }
    }
    gsync();

    // ---- P3: tower-input GEMMs (+acc inits) and neighbor means
    gemm_dev(g_dru_str, D_NUM, 128, d_weight_i, 0, g_curD, g_acc2, g_acc4, sbuf);
    gemm_dev(g_pro_str, P_NUM, 128, p_weight, 0, g_cur3, g_acc3, 0, sbuf);
    gemm_dev(g_dru_str, D_NUM, 128, pd_weight_d, 0, g_one_emb, g_accd, 0, sbuf);
    gemm_dev(g_pro_str, P_NUM, 128, pd_weight_p, 0, g_two_emb, g_accp, 0, sbuf);
    spmm_dev(g_idx2, g_len2, CAP_DD, g_cinv2, 0, g_dru_str, g_nei2, 0, 0, 0.f, 0, 0, D_NUM);
    spmm_dev(g_idx3, g_len3, CAP_PP, g_cinv3, 0, g_pro_str, g_nei3, 0, 0, 0.f, 0, 0, P_NUM);
    gsync();

    // ---- P4: GCN layer 1 + cross-domain neighbor means with fused mix
    spmm_dev(g_idx2, g_len2, CAP_DD, g_dinv2, g_dinv2, g_curD, g_x2a, g_acc2, 0, 0.f, 0, 0, D_NUM);
    spmm_dev(g_idx3, g_len3, CAP_PP, g_dinv3, g_dinv3, g_cur3, g_x3a, g_acc3, 0, 0.f, 0, 0, P_NUM);
    spmm_dev(g_idx4, g_len4, CAP_DD, g_dinv4, g_dinv4, g_curD, g_x4a, g_acc4, 0, 0.f, 0, 0, D_NUM);
    spmm_dev(g_idxR, g_lenR, CAP_PP, g_cinvRd, 0, g_nei3, 0, 0, 0, 0.f, g_dru_str, g_one_all, D_NUM);
    spmm_dev(g_idxRT, g_curRT, CAP_DD, g_cinvRp, 0, g_nei2, 0, 0, 0, 0.f, g_pro_str, g_tmpp, P_NUM);
    gsync();

    // ---- P5: GCN layer 2 + two_all GEMM
    spmm_dev(g_idx2, g_len2, CAP_DD, g_dinv2, g_dinv2, g_x2a, g_x2b, g_acc2, 0, 0.f, 0, 0, D_NUM);
    spmm_dev(g_idx3, g_len3, CAP_PP, g_dinv3, g_dinv3, g_x3a, g_x3b, g_acc3, 0, 0.f, 0, 0, P_NUM);
    spmm_dev(g_idx4, g_len4, CAP_DD, g_dinv4, g_dinv4, g_x4a, g_x4b, g_acc4, 0, 0.f, 0, 0, D_NUM);
    gemm_dev(g_tmpp, P_NUM, 128, g_Wc, 0, g_two_all, 0, 0, sbuf);
    gsync();

    // ---- P6: GCN layer 3 (finalize towers) + bipartite step 1
    spmm_dev(g_idx2, g_len2, CAP_DD, g_dinv2, g_dinv2, g_x2b, 0, g_acc2, g_emb2, 0.25f, 0, 0, D_NUM);
    spmm_dev(g_idx3, g_len3, CAP_PP, g_dinv3, g_dinv3, g_x3b, 0, g_acc3, g_emb3, 0.25f, 0, 0, P_NUM);
    spmm_dev(g_idx4, g_len4, CAP_DD, g_dinv4, g_dinv4, g_x4b, 0, g_acc4, g_emb4, 0.25f, 0, 0, D_NUM);
    spmm_dev(g_idxR, g_lenR, CAP_PP, g_dinvRd, g_dinvRp, g_two_all, g_bd1, g_accd, 0, 0.f, 0, 0, D_NUM);
    spmm_dev(g_idxRT, g_curRT, CAP_DD, g_dinvRp, g_dinvRd, g_one_emb, g_bp1, 0, 0, 0.f, 0, 0, P_NUM);
    spmm_dev(g_idxRT, g_curRT, CAP_DD, g_dinvRp, g_dinvRd, g_one_all, g_bpx, g_accp, 0, 0.f, 0, 0, P_NUM);
    spmm_dev(g_idxR, g_lenR, CAP_PP, g_dinvRd, g_dinvRp, g_two_emb, g_bdx, 0, 0, 0.f, 0, 0, D_NUM);
    gsync();

    // ---- P7: bipartite step 2 + tower attention heads (overlap)
    spmm_dev(g_idxRT, g_curRT, CAP_DD, g_dinvRp, g_dinvRd, g_bd1, g_bp2, 0, 0, 0.f, 0, 0, P_NUM);
    spmm_dev(g_idxR, g_lenR, CAP_PP, g_dinvRd, g_dinvRp, g_bp1, 0, g_accd, 0, 0.f, 0, 0, D_NUM);
    spmm_dev(g_idxRT, g_curRT, CAP_DD, g_dinvRp, g_dinvRd, g_bdx, 0, g_accp, 0, 0.f, 0, 0, P_NUM);
    spmm_dev(g_idxR, g_lenR, CAP_PP, g_dinvRd, g_dinvRp, g_bpx, g_bdy, 0, 0, 0.f, 0, 0, D_NUM);
    att_dev(g_emb2, WB_drug, BB_drug, HB_drug, g_wdrel, D_NUM, sbuf);
    att_dev(g_emb3, WB_pro, BB_pro, HB_pro, g_wprel, P_NUM, sbuf);
    att_dev(g_emb4, WA_sim, BA_sim, HA_sim, g_wdsim, D_NUM, sbuf);
    gsync();

    // ---- P8: bipartite step 3
    spmm_dev(g_idxR, g_lenR, CAP_PP, g_dinvRd, g_dinvRp, g_bp2, 0, g_accd, g_dru_int, 0.25f, 0, 0, D_NUM);
    spmm_dev(g_idxRT, g_curRT, CAP_DD, g_dinvRp, g_dinvRd, g_bdy, 0, g_accp, g_pro_int, 0.25f, 0, 0, P_NUM);
    gsync();

    // ---- P9: remaining attention heads
    att_dev(g_dru_int, WA_drug, BA_drug, HA_drug, g_wdrug, D_NUM, sbuf);
    att_dev(g_pro_int, WA_pro, BA_pro, HA_pro, g_wpro, P_NUM, sbuf);
    gsync();

    // ---- P10: log-softmax (5 heads, 5 blocks)
    if (blockIdx.x < 5) {
        float* s; int n;
        switch (blockIdx.x) {
            case 0: s = g_wdrug; n = D_NUM; break;
            case 1: s = g_wpro;  n = P_NUM; break;
            case 2: s = g_wdrel; n = D_NUM; break;
            case 3: s = g_wprel; n = P_NUM; break;
            default:s = g_wdsim; n = D_NUM; break;
        }
        ls_dev(s, n, sbuf);
    }
    gsync();

    // ---- P11: fused weighted-combine + Gram matrices + column sums
    if (blockIdx.x < 128) {
        bool isD = blockIdx.x < 32;
        int n    = isD ? D_NUM : P_NUM;
        int brel = isD ? (int)blockIdx.x : (int)blockIdx.x - 32;
        int nblk = isD ? 32 : 96;
        float* gG  = isD ? g_gd : g_gp;
        float* gS  = isD ? g_sd : g_sp;
        float* fin = isD ? g_fin_d : g_fin_p;
        int ntiles = (n + 15) >> 4;
        int k0 = (threadIdx.x & 15) * 8, l0 = (threadIdx.x >> 4) * 8;
        float accG[8][8];
#pragma unroll
        for (int i = 0; i < 8; i++)
#pragma unroll
            for (int j = 0; j < 8; j++) accG[i][j] = 0.f;
        float cs = 0.f;
        for (int t = brel; t < ntiles; t += nblk) {
            int r0 = t << 4;
            __syncthreads();
            for (int i = threadIdx.x; i < 16 * 128; i += MEGA_THREADS) {
                int rr = i >> 7, kk = i & 127;
                int gr = r0 + rr;
                float val = 0.f;
                if (gr < n) {
                    size_t o = (size_t)gr * EMB + kk;
                    if (isD) {
                        float wa = g_wdrug[gr], wb = g_wdrel[gr], wc = g_wdsim[gr];
                        float a = wa / (wa + wb + wc);
                        float b = wb / (a + wb + wc);
                        float c = 1.0f - a - b;
                        val = a * g_dru_int[o] + b * g_emb2[o] + c * g_emb4[o];
                    } else {
                        float wa = g_wpro[gr], wb = g_wprel[gr];
                        float pa = wa / (wa + wb);
                        val = pa * g_pro_int[o] + (1.0f - pa) * g_emb3[o];
                    }
                    fin[o] = val;
                }
                sbuf[rr * 132 + kk] = val;
            }
            __syncthreads();
#pragma unroll 4
            for (int r = 0; r < 16; r++) {
                const float* row = &sbuf[r * 132];
                float4 a0 = *(const float4*)(row + k0);
                float4 a1 = *(const float4*)(row + k0 + 4);
                float4 b0 = *(const float4*)(row + l0);
                float4 b1 = *(const float4*)(row + l0 + 4);
                float av[8] = {a0.x, a0.y, a0.z, a0.w, a1.x, a1.y, a1.z, a1.w};
                float bv[8] = {b0.x, b0.y, b0.z, b0.w, b1.x, b1.y, b1.z, b1.w};
#pragma unroll
                for (int i = 0; i < 8; i++)
#pragma unroll
                    for (int j = 0; j < 8; j++) accG[i][j] += av[i] * bv[j];
            }
            if (threadIdx.x < 128) {
                float c = 0.f;
                for (int r = 0; r < 16; r++) c += sbuf[r * 132 + threadIdx.x];
                cs += c;
            }
        }
#pragma unroll
        for (int i = 0; i < 8; i++)
#pragma unroll
            for (int j = 0; j < 8; j++)
                atomicAdd(&gG[(k0 + i) * EMB + (l0 + j)], accG[i][j]);
        if (threadIdx.x < 128) atomicAdd(&gS[threadIdx.x], cs);
    }
    gsync();

    // ---- P12: reduce stats -> g_musig (block 0 only)
    if (blockIdx.x == 0) {
        double* sd = (double*)sbuf;
        double acc = 0.0;
        for (int i = threadIdx.x; i < EMB * EMB; i += MEGA_THREADS)
            acc += (double)g_gd[i] * (double)g_gp[i];
        sd[threadIdx.x] = acc; __syncthreads();
        for (int o = 128; o; o >>= 1) { if (threadIdx.x < o) sd[threadIdx.x] += sd[threadIdx.x + o]; __syncthreads(); }
        double sumsq = sd[0]; __syncthreads();
        double a2 = (threadIdx.x < EMB) ? (double)g_sd[threadIdx.x] * (double)g_sp[threadIdx.x] : 0.0;
        sd[threadIdx.x] = a2; __syncthreads();
        for (int o = 128; o; o >>= 1) { if (threadIdx.x < o) sd[threadIdx.x] += sd[threadIdx.x + o]; __syncthreads(); }
        if (threadIdx.x == 0) {
            double sumy = sd[0];
            const double nn = (double)D_NUM * (double)P_NUM;
            double mean = sumy / nn;
            double var = (sumsq - sumy * sumy / nn) / (nn - 1.0);
            g_musig = make_float2((float)mean, (float)(1.0 / sqrt(var)));
        }
    }
}

// ---------------- final GEMM with fused standardize+sigmoid ----------------
__global__ void __launch_bounds__(256) k_final_gemm(float* __restrict__ out) {
    __shared__ __align__(16) float sA[32 * 132];
    __shared__ __align__(16) float sB[32 * 132];
    float2 ms = g_musig;
    float mu = ms.x, istd = ms.y;
    int bi = blockIdx.y * 128, bj = blockIdx.x * 128;
    int t = threadIdx.x;
    int tx = t & 15, ty = t >> 4;
    int m0 = ty * 8, n0 = tx * 8;
    float acc[8][8];
#pragma unroll
    for (int i = 0; i < 8; i++)
#pragma unroll
        for (int j = 0; j < 8; j++) acc[i][j] = 0.0f;

    for (int k0 = 0; k0 < EMB; k0 += 32) {
#pragma unroll
        for (int it = 0; it < 4; it++) {
            int e = t + it * 256;
            int rr = e >> 3, kv = e & 7;
            int gi = bi + rr, gj = bj + rr;
            float4 va = (gi < D_NUM) ? *(const float4*)&g_fin_d[(size_t)gi * EMB + k0 + kv * 4]
                                     : make_float4(0.f, 0.f, 0.f, 0.f);
            float4 vb = (gj < P_NUM) ? *(const float4*)&g_fin_p[(size_t)gj * EMB + k0 + kv * 4]
                                     : make_float4(0.f, 0.f, 0.f, 0.f);
            sA[(kv * 4 + 0) * 132 + rr] = va.x;
            sA[(kv * 4 + 1) * 132 + rr] = va.y;
            sA[(kv * 4 + 2) * 132 + rr] = va.z;
            sA[(kv * 4 + 3) * 132 + rr] = va.w;
            sB[(kv * 4 + 0) * 132 + rr] = vb.x;
            sB[(kv * 4 + 1) * 132 + rr] = vb.y;
            sB[(kv * 4 + 2) * 132 + rr] = vb.z;
            sB[(kv * 4 + 3) * 132 + rr] = vb.w;
        }
        __syncthreads();
#pragma unroll
        for (int kk = 0; kk < 32; kk++) {
            const float* pa = &sA[kk * 132 + m0];
            const float* pb = &sB[kk * 132 + n0];
            float4 a0 = *(const float4*)pa;
            float4 a1 = *(const float4*)(pa + 4);
            float4 b0 = *(const float4*)pb;
            float4 b1 = *(const float4*)(pb + 4);
            float ra[8] = {a0.x, a0.y, a0.z, a0.w, a1.x, a1.y, a1.z, a1.w};
            float rb[8] = {b0.x, b0.y, b0.z, b0.w, b1.x, b1.y, b1.z, b1.w};
#pragma unroll
            for (int i = 0; i < 8; i++)
#pragma unroll
                for (int j = 0; j < 8; j++) acc[i][j] += ra[i] * rb[j];
        }
        __syncthreads();
    }
#pragma unroll
    for (int i = 0; i < 8; i++) {
        int gi = bi + m0 + i;
        if (gi < D_NUM) {
#pragma unroll
            for (int j = 0; j < 8; j++) {
                int gj = bj + n0 + j;
                if (gj < P_NUM) {
                    float z = (acc[i][j] - mu) * istd;
                    out[(size_t)gi * P_NUM + gj] = __fdividef(1.0f, 1.0f + __expf(-z));
                }
            }
        }
    }
}

// one nop so the graph is 4 nodes/iter and ncu (-s 5) lands on k_mega
__global__ void k_nop() { if (threadIdx.x == 0 && blockIdx.x == 0) g_nopsink = 1; }

// ---------------- host launcher ----------------
extern "C" void kernel_launch(void* const* d_in, const int* in_sizes, int n_in,
                              void* d_out, int out_size) {
    const float* A                 = (const float*)d_in[0];
    const float* drug_structure    = (const float*)d_in[1];
    const float* protein_structure = (const float*)d_in[2];
    const float* lin_drug_w = (const float*)d_in[3];
    const float* lin_drug_b = (const float*)d_in[4];
    const float* lin_pro_w  = (const float*)d_in[5];
    const float* lin_pro_b  = (const float*)d_in[6];
    const float* p_weight   = (const float*)d_in[7];
    const float* d_weight_i = (const float*)d_in[8];
    const float* pd_weight_p = (const float*)d_in[9];
    const float* pd_weight_d = (const float*)d_in[10];
    const float* dp_weight_p = (const float*)d_in[11];
    const float* WA_drug = (const float*)d_in[12];
    const float* BA_drug = (const float*)d_in[13];
    const float* HA_drug = (const float*)d_in[14];
    const float* WB_drug = (const float*)d_in[15];
    const float* BB_drug = (const float*)d_in[16];
    const float* HB_drug = (const float*)d_in[17];
    const float* WA_pro = (const float*)d_in[18];
    const float* BA_pro = (const float*)d_in[19];
    const float* HA_pro = (const float*)d_in[20];
    const float* WB_pro = (const float*)d_in[21];
    const float* BB_pro = (const float*)d_in[22];
    const float* HB_pro = (const float*)d_in[23];
    const float* WA_sim = (const float*)d_in[24];
    const float* BA_sim = (const float*)d_in[25];
    const float* HA_sim = (const float*)d_in[26];
    float* out = (float*)d_out;
    (void)in_sizes; (void)n_in; (void)out_size;

    k_ell_all<<<9000, 256>>>(A);

    k_mega<<<MEGA_BLKS, MEGA_THREADS>>>(
        drug_structure, protein_structure,
        lin_drug_w, lin_drug_b, lin_pro_w, lin_pro_b,
        p_weight, d_weight_i, pd_weight_p, pd_weight_d, dp_weight_p,
        WA_drug, BA_drug, HA_drug,
        WB_drug, BB_drug, HB_drug,
        WA_pro, BA_pro, HA_pro,
        WB_pro, BB_pro, HB_pro,
        WA_sim, BA_sim, HA_sim);

    dim3 fg((P_NUM + 127) / 128, (D_NUM + 127) / 128);
    k_final_gemm<<<fg, 256>>>(out);

    k_nop<<<1, 32>>>();
}

// round 10
// speedup vs baseline: 1.0320x; 1.0320x over previous
#include <cuda_runtime.h>
#include <math.h>
#include <stdint.h>

#define D_NUM 1500
#define P_NUM 4500
#define NTOT  6000
#define EMB   128
#define CAP_DD 64
#define CAP_PP 128
#define DB (D_NUM*EMB)
#define PB (P_NUM*EMB)
#define MEGA_BLKS 296
#define MEGA_THREADS 256

// ---------------- scratch (static __device__, no allocs) ----------------
__device__ __align__(128) int g_idx2[D_NUM*CAP_DD]; __device__ int g_len2[D_NUM];
__device__ __align__(128) int g_idx4[D_NUM*CAP_DD]; __device__ int g_len4[D_NUM];
__device__ __align__(128) int g_idx3[P_NUM*CAP_PP]; __device__ int g_len3[P_NUM];
__device__ __align__(128) int g_idxR[D_NUM*CAP_PP]; __device__ int g_lenR[D_NUM];
__device__ __align__(128) int g_idxRT[P_NUM*CAP_DD]; __device__ int g_curRT[P_NUM];

__device__ float g_dinv2[D_NUM], g_cinv2[D_NUM];
__device__ float g_dinv3[P_NUM], g_cinv3[P_NUM];
__device__ float g_dinv4[D_NUM];
__device__ float g_dinvRd[D_NUM], g_cinvRd[D_NUM];
__device__ float g_dinvRp[P_NUM], g_cinvRp[P_NUM];

__device__ __align__(128) float g_dru_str[DB], g_pro_str[PB];
__device__ __align__(128) float g_nei2[DB],    g_nei3[PB];
__device__ __align__(128) float g_emb2[DB],    g_emb3[PB],  g_emb4[DB];
__device__ __align__(128) float g_curD[DB],    g_cur3[PB];
__device__ __align__(128) float g_x2a[DB], g_x2b[DB], g_x4a[DB], g_x4b[DB];
__device__ __align__(128) float g_x3a[PB], g_x3b[PB];
__device__ __align__(128) float g_acc2[DB], g_acc3[PB], g_acc4[DB];
__device__ __align__(128) float g_one_emb[DB], g_two_all[PB], g_one_all[DB], g_two_emb[PB];
__device__ __align__(128) float g_bd1[DB],  g_bp1[PB], g_bp2[PB];
__device__ __align__(128) float g_bdx[DB],  g_bpx[PB], g_bdy[DB];
__device__ __align__(128) float g_accd[DB], g_accp[PB];
__device__ __align__(128) float g_dru_int[DB], g_pro_int[PB];
__device__ __align__(128) float g_tmpp[PB], g_Wc[EMB*EMB];
__device__ __align__(128) float g_fin_d[DB], g_fin_p[PB];
__device__ float g_wdrug[D_NUM], g_wdrel[D_NUM], g_wdsim[D_NUM];
__device__ float g_wpro[P_NUM],  g_wprel[P_NUM];
__device__ __align__(128) float g_gd[EMB*EMB], g_gp[EMB*EMB];
__device__ float g_sd[EMB], g_sp[EMB];
__device__ float2 g_musig;
__device__ unsigned g_barcnt;

// ---------------- ELL extraction (round-6 version, known 49us) -------------
__global__ void k_ell_all(const float* __restrict__ A) {
    const size_t NN = (size_t)NTOT * NTOT;
    int b = blockIdx.x;
    const float* base; int r, row0, col0, ncols, cap; int *idx, *len;
    if (b < 1500)      { base = A + 2*NN; r = b;        row0 = 0;     col0 = 0;     ncols = D_NUM; cap = CAP_DD; idx = g_idx2; len = g_len2; }
    else if (b < 6000) { base = A + 3*NN; r = b - 1500; row0 = D_NUM; col0 = D_NUM; ncols = P_NUM; cap = CAP_PP; idx = g_idx3; len = g_len3; }
    else if (b < 7500) { base = A + 4*NN; r = b - 6000; row0 = 0;     col0 = 0;     ncols = D_NUM; cap = CAP_DD; idx = g_idx4; len = g_len4; }
    else               { base = A;        r = b - 7500; row0 = 0;     col0 = D_NUM; ncols = P_NUM; cap = CAP_PP; idx = g_idxR; len = g_lenR; }

    const float4* row4 = (const float4*)(base + (size_t)(row0 + r) * NTOT + col0);
    int nv = ncols >> 2;
    __shared__ int cnt;
    __shared__ int buf[160];
    if (threadIdx.x == 0) cnt = 0;
    __syncthreads();

    float4 v[5];
#pragma unroll
    for (int u = 0; u < 5; u++) {
        int i = threadIdx.x + (u << 8);
        if (i < nv) v[u] = __ldg(&row4[i]);
    }
#pragma unroll
    for (int u = 0; u < 5; u++) {
        int i = threadIdx.x + (u << 8);
        if (i < nv) {
            int c = i << 2;
            if (v[u].x == 1.0f) { int p = atomicAdd(&cnt, 1); if (p < 160) buf[p] = c; }
            if (v[u].y == 1.0f) { int p = atomicAdd(&cnt, 1); if (p < 160) buf[p] = c + 1; }
            if (v[u].z == 1.0f) { int p = atomicAdd(&cnt, 1); if (p < 160) buf[p] = c + 2; }
            if (v[u].w == 1.0f) { int p = atomicAdd(&cnt, 1); if (p < 160) buf[p] = c + 3; }
        }
    }
    __syncthreads();
    int L = min(cnt, cap);
    if (threadIdx.x == 0) {
        len[r] = L;
        for (int i = 1; i < L; i++) {
            int t = buf[i]; int j = i - 1;
            while (j >= 0 && buf[j] > t) { buf[j + 1] = buf[j]; j--; }
            buf[j + 1] = t;
        }
    }
    __syncthreads();
    for (int i = threadIdx.x; i < L; i += blockDim.x)
        idx[(size_t)r * cap + i] = buf[i];
}

// ------------- grid barrier: round-6 monotonic counter (known-good) --------
__device__ __forceinline__ void gsync(unsigned& target) {
    __syncthreads();
    if (threadIdx.x == 0) {
        __threadfence();
        atomicAdd(&g_barcnt, 1u);
        target += gridDim.x;
        unsigned v;
        do {
            asm volatile("ld.acquire.gpu.global.u32 %0, [%1];"
                         : "=r"(v) : "l"(&g_barcnt) : "memory");
        } while (v < target);
    }
    __syncthreads();
}

// ---------------- register-tiled GEMM: C(n x 128) = A(n x k) @ W + bias ----
// 64-row x 128-col tile per block, 8x4 per thread, k-major smem, float4 LDS.
__device__ void gemm_dev(const float* A, int n, int k,
                         const float* W, const float* bias,
                         float* C, float* C2, float* C3, float* sbuf) {
    float* As = sbuf;            // [32][68] k-major
    float* Ws = sbuf + 32 * 68;  // [32][132]
    int ntiles = (n + 63) >> 6;
    int t = threadIdx.x;
    int tx = t & 31, ty = t >> 5;
    int m0 = ty << 3, n0 = tx << 2;
    for (int tile = blockIdx.x; tile < ntiles; tile += gridDim.x) {
        int r0 = tile << 6;
        float acc[8][4];
#pragma unroll
        for (int i = 0; i < 8; i++)
#pragma unroll
            for (int j = 0; j < 4; j++) acc[i][j] = 0.f;
        for (int k0 = 0; k0 < k; k0 += 32) {
            __syncthreads();
#pragma unroll
            for (int e = t; e < 512; e += 256) {       // A: 64 rows x 8 float4
                int rr = e >> 3, kv = e & 7;
                int gr = r0 + rr;
                float4 va = (gr < n) ? *(const float4*)&A[(size_t)gr * k + k0 + (kv << 2)]
                                     : make_float4(0.f, 0.f, 0.f, 0.f);
                As[(kv * 4 + 0) * 68 + rr] = va.x;
                As[(kv * 4 + 1) * 68 + rr] = va.y;
                As[(kv * 4 + 2) * 68 + rr] = va.z;
                As[(kv * 4 + 3) * 68 + rr] = va.w;
            }
#pragma unroll
            for (int e = t; e < 1024; e += 256) {      // W: 32 k x 32 float4
                int kk = e >> 5, cv = e & 31;
                *(float4*)&Ws[kk * 132 + (cv << 2)] =
                    *(const float4*)&W[(size_t)(k0 + kk) * EMB + (cv << 2)];
            }
            __syncthreads();
#pragma unroll
            for (int kk = 0; kk < 32; kk++) {
                float4 a0 = *(const float4*)&As[kk * 68 + m0];
                float4 a1 = *(const float4*)&As[kk * 68 + m0 + 4];
                float4 w  = *(const float4*)&Ws[kk * 132 + n0];
                float av[8] = {a0.x, a0.y, a0.z, a0.w, a1.x, a1.y, a1.z, a1.w};
#pragma unroll
                for (int i = 0; i < 8; i++) {
                    acc[i][0] += av[i] * w.x;
                    acc[i][1] += av[i] * w.y;
                    acc[i][2] += av[i] * w.z;
                    acc[i][3] += av[i] * w.w;
                }
            }
        }
        float4 bb = bias ? *(const float4*)&bias[n0] : make_float4(0.f, 0.f, 0.f, 0.f);
#pragma unroll
        for (int i = 0; i < 8; i++) {
            int gr = r0 + m0 + i;
            if (gr < n) {
                float4 vv = make_float4(acc[i][0] + bb.x, acc[i][1] + bb.y,
                                        acc[i][2] + bb.z, acc[i][3] + bb.w);
                *(float4*)&C[(size_t)gr * EMB + n0] = vv;
                if (C2) *(float4*)&C2[(size_t)gr * EMB + n0] = vv;
                if (C3) *(float4*)&C3[(size_t)gr * EMB + n0] = vv;
            }
        }
    }
}

// attention on the same tile: s[r] = sum_c relu(emb@W + B)[c]*H[c]
__device__ void att_dev(const float* emb, const float* W, const float* B,
                        const float* H, float* s, int n, float* sbuf) {
    float* As = sbuf;
    float* Ws = sbuf + 32 * 68;
    int ntiles = (n + 63) >> 6;
    int t = threadIdx.x;
    int tx = t & 31, ty = t >> 5;
    int m0 = ty << 3, n0 = tx << 2;
    for (int tile = blockIdx.x; tile < ntiles; tile += gridDim.x) {
        int r0 = tile << 6;
        float acc[8][4];
#pragma unroll
        for (int i = 0; i < 8; i++)
#pragma unroll
            for (int j = 0; j < 4; j++) acc[i][j] = 0.f;
        for (int k0 = 0; k0 < EMB; k0 += 32) {
            __syncthreads();
#pragma unroll
            for (int e = t; e < 512; e += 256) {
                int rr = e >> 3, kv = e & 7;
                int gr = r0 + rr;
                float4 va = (gr < n) ? *(const float4*)&emb[(size_t)gr * EMB + k0 + (kv << 2)]
                                     : make_float4(0.f, 0.f, 0.f, 0.f);
                As[(kv * 4 + 0) * 68 + rr] = va.x;
                As[(kv * 4 + 1) * 68 + rr] = va.y;
                As[(kv * 4 + 2) * 68 + rr] = va.z;
                As[(kv * 4 + 3) * 68 + rr] = va.w;
            }
#pragma unroll
            for (int e = t; e < 1024; e += 256) {
                int kk = e >> 5, cv = e & 31;
                *(float4*)&Ws[kk * 132 + (cv << 2)] =
                    *(const float4*)&W[(size_t)(k0 + kk) * EMB + (cv << 2)];
            }
            __syncthreads();
#pragma unroll
            for (int kk = 0; kk < 32; kk++) {
                float4 a0 = *(const float4*)&As[kk * 68 + m0];
                float4 a1 = *(const float4*)&As[kk * 68 + m0 + 4];
                float4 w  = *(const float4*)&Ws[kk * 132 + n0];
                float av[8] = {a0.x, a0.y, a0.z, a0.w, a1.x, a1.y, a1.z, a1.w};
#pragma unroll
                for (int i = 0; i < 8; i++) {
                    acc[i][0] += av[i] * w.x;
                    acc[i][1] += av[i] * w.y;
                    acc[i][2] += av[i] * w.z;
                    acc[i][3] += av[i] * w.w;
                }
            }
        }
        float4 bb = *(const float4*)&B[n0];
        float4 hh = *(const float4*)&H[n0];
#pragma unroll
        for (int i = 0; i < 8; i++) {
            float p = fmaxf(acc[i][0] + bb.x, 0.f) * hh.x
                    + fmaxf(acc[i][1] + bb.y, 0.f) * hh.y
                    + fmaxf(acc[i][2] + bb.z, 0.f) * hh.z
                    + fmaxf(acc[i][3] + bb.w, 0.f) * hh.w;
#pragma unroll
            for (int o = 16; o; o >>= 1) p += __shfl_down_sync(0xffffffffu, p, o);
            if (tx == 0) {
                int gr = r0 + m0 + i;
                if (gr < n) s[gr] = p;
            }
        }
    }
}

__device__ void spmm_dev(const int* idx, const int* len, int cap,
                         const float* rs, const float* cs, const float* x,
                         float* out, float* acc, float* fin, float fscale,
                         const float* mixb, float* mixo, int n) {
    int nw = (gridDim.x * blockDim.x) >> 5;
    int gw = (blockIdx.x * blockDim.x + threadIdx.x) >> 5;
    int lane = threadIdx.x & 31;
    const float4* x4 = (const float4*)x;
    for (int r = gw; r < n; r += nw) {
        int L = len[r];
        float4 s = make_float4(0.f, 0.f, 0.f, 0.f);
        for (int p0 = 0; p0 < L; p0 += 32) {
            int j = 0; float f = 0.f;
            if (p0 + lane < L) {
                j = idx[(size_t)r * cap + p0 + lane];
                f = cs ? cs[j] : 1.0f;
            }
            int m = min(32, L - p0);
            int q = 0;
            for (; q + 4 <= m; q += 4) {
                int j0 = __shfl_sync(0xffffffffu, j, q);
                int j1 = __shfl_sync(0xffffffffu, j, q + 1);
                int j2 = __shfl_sync(0xffffffffu, j, q + 2);
                int j3 = __shfl_sync(0xffffffffu, j, q + 3);
                float f0 = __shfl_sync(0xffffffffu, f, q);
                float f1 = __shfl_sync(0xffffffffu, f, q + 1);
                float f2 = __shfl_sync(0xffffffffu, f, q + 2);
                float f3 = __shfl_sync(0xffffffffu, f, q + 3);
                float4 v0 = x4[(size_t)j0 * 32 + lane];
                float4 v1 = x4[(size_t)j1 * 32 + lane];
                float4 v2 = x4[(size_t)j2 * 32 + lane];
                float4 v3 = x4[(size_t)j3 * 32 + lane];
                s.x += f0 * v0.x + f1 * v1.x + f2 * v2.x + f3 * v3.x;
                s.y += f0 * v0.y + f1 * v1.y + f2 * v2.y + f3 * v3.y;
                s.z += f0 * v0.z + f1 * v1.z + f2 * v2.z + f3 * v3.z;
                s.w += f0 * v0.w + f1 * v1.w + f2 * v2.w + f3 * v3.w;
            }
            for (; q < m; q++) {
                int j0 = __shfl_sync(0xffffffffu, j, q);
                float f0 = __shfl_sync(0xffffffffu, f, q);
                float4 v0 = x4[(size_t)j0 * 32 + lane];
                s.x += f0 * v0.x; s.y += f0 * v0.y;
                s.z += f0 * v0.z; s.w += f0 * v0.w;
            }
        }
        float rr = rs[r];
        s.x *= rr; s.y *= rr; s.z *= rr; s.w *= rr;
        size_t o = (size_t)r * 32 + lane;
        if (out) ((float4*)out)[o] = s;
        if (acc) {
            float4 a = ((const float4*)acc)[o];
            a.x += s.x; a.y += s.y; a.z += s.z; a.w += s.w;
            ((float4*)acc)[o] = a;
            if (fin) {
                float4 ff = make_float4(a.x * fscale, a.y * fscale, a.z * fscale, a.w * fscale);
                ((float4*)fin)[o] = ff;
            }
        }
        if (mixo) {
            float4 mb = ((const float4*)mixb)[o];
            float4 mo = make_float4(0.8f * mb.x + 0.2f * s.x, 0.8f * mb.y + 0.2f * s.y,
                                    0.8f * mb.z + 0.2f * s.z, 0.8f * mb.w + 0.2f * s.w);
            ((float4*)mixo)[o] = mo;
        }
    }
}

__device__ void ls_dev(float* s, int n, float* sh) {
    int t = threadIdx.x;
    float m = -1e30f;
    for (int i = t; i < n; i += MEGA_THREADS) m = fmaxf(m, s[i]);
    sh[t] = m; __syncthreads();
    for (int o = 128; o; o >>= 1) { if (t < o) sh[t] = fmaxf(sh[t], sh[t + o]); __syncthreads(); }
    float mall = sh[0]; __syncthreads();
    float sum = 0.0f;
    for (int i = t; i < n; i += MEGA_THREADS) sum += expf(s[i] - mall);
    sh[t] = sum; __syncthreads();
    for (int o = 128; o; o >>= 1) { if (t < o) sh[t] += sh[t + o]; __syncthreads(); }
    float lse = mall + logf(sh[0]);
    __syncthreads();
    for (int i = t; i < n; i += MEGA_THREADS) s[i] -= lse;
}

// ---------------- the megakernel (round-6 structure) ----------------
__global__ void __launch_bounds__(MEGA_THREADS, 2) k_mega(
    const float* __restrict__ drug_structure, const float* __restrict__ protein_structure,
    const float* __restrict__ lin_drug_w, const float* __restrict__ lin_drug_b,
    const float* __restrict__ lin_pro_w, const float* __restrict__ lin_pro_b,
    const float* __restrict__ p_weight, const float* __restrict__ d_weight_i,
    const float* __restrict__ pd_weight_p, const float* __restrict__ pd_weight_d,
    const float* __restrict__ dp_weight_p,
    const float* __restrict__ WA_drug, const float* __restrict__ BA_drug, const float* __restrict__ HA_drug,
    const float* __restrict__ WB_drug, const float* __restrict__ BB_drug, const float* __restrict__ HB_drug,
    const float* __restrict__ WA_pro, const float* __restrict__ BA_pro, const float* __restrict__ HA_pro,
    const float* __restrict__ WB_pro, const float* __restrict__ BB_pro, const float* __restrict__ HB_pro,
    const float* __restrict__ WA_sim, const float* __restrict__ BA_sim, const float* __restrict__ HA_sim) {
    __shared__ __align__(16) float sbuf[16 * 512];
    unsigned target = 0;

    // ---- P1: build R^T + zero Gram/colsum accumulators
    {
        int nw = (gridDim.x * blockDim.x) >> 5;
        int gw = (blockIdx.x * blockDim.x + threadIdx.x) >> 5;
        int lane = threadIdx.x & 31;
        for (int r = gw; r < D_NUM; r += nw) {
            int L = g_lenR[r];
            for (int p = lane; p < L; p += 32) {
                int c = g_idxR[r * CAP_PP + p];
                int pos = atomicAdd(&g_curRT[c], 1);
                if (pos < CAP_DD) g_idxRT[c * CAP_DD + pos] = r;
            }
        }
        int stride = gridDim.x * blockDim.x;
        int gid = blockIdx.x * blockDim.x + threadIdx.x;
        for (int i = gid; i < EMB * EMB; i += stride) { g_gd[i] = 0.f; g_gp[i] = 0.f; }
        if (gid < EMB) { g_sd[gid] = 0.f; g_sp[gid] = 0.f; }
    }
    gsync(target);

    // ---- P2: sort R^T + degree scales + feature lifts + Wc (independent)
    {
        int i = blockIdx.x * blockDim.x + threadIdx.x;
        if (i < D_NUM) {
            int d;
            d = g_len2[i]; g_dinv2[i] = d > 0 ? rsqrtf((float)d) : 0.0f;
                           g_cinv2[i] = d > 0 ? 1.0f / (float)d : 0.0f;
            d = g_len4[i]; g_dinv4[i] = d > 0 ? rsqrtf((float)d) : 0.0f;
            d = g_lenR[i]; g_dinvRd[i] = d > 0 ? rsqrtf((float)d) : 0.0f;
                           g_cinvRd[i] = d > 0 ? 1.0f / (float)d : 0.0f;
        }
        if (i < P_NUM) {
            int d = g_len3[i];
            g_dinv3[i] = d > 0 ? rsqrtf((float)d) : 0.0f;
            g_cinv3[i] = d > 0 ? 1.0f / (float)d : 0.0f;
            int L = min(g_curRT[i], CAP_DD);
            g_curRT[i] = L;
            int* a = &g_idxRT[i * CAP_DD];
            for (int q = 1; q < L; q++) {
                int v = a[q]; int jj = q - 1;
                while (jj >= 0 && a[jj] > v) { a[jj + 1] = a[jj]; jj--; }
                a[jj + 1] = v;
            }
            g_dinvRp[i] = L > 0 ? rsqrtf((float)L) : 0.0f;
            g_cinvRp[i] = L > 0 ? 1.0f / (float)L : 0.0f;
        }
    }
    gemm_dev(drug_structure, D_NUM, 160, lin_drug_w, lin_drug_b, g_dru_str, 0, 0, sbuf);
    gemm_dev(protein_structure, P_NUM, 512, lin_pro_w, lin_pro_b, g_pro_str, 0, 0, sbuf);
    gemm_dev(dp_weight_p, 128, 128, pd_weight_d, 0, g_Wc, 0, 0, sbuf);
    gsync(target);

    // ---- P4: tower-input GEMMs (+acc inits) and neighbor means
    gemm_dev(g_dru_str, D_NUM, 128, d_weight_i, 0, g_curD, g_acc2, g_acc4, sbuf);
    gemm_dev(g_pro_str, P_NUM, 128, p_weight, 0, g_cur3, g_acc3, 0, sbuf);
    gemm_dev(g_dru_str, D_NUM, 128, pd_weight_d, 0, g_one_emb, g_accd, 0, sbuf);
    gemm_dev(g_pro_str, P_NUM, 128, pd_weight_p, 0, g_two_emb, g_accp, 0, sbuf);
    spmm_dev(g_idx2, g_len2, CAP_DD, g_cinv2, 0, g_dru_str, g_nei2, 0, 0, 0.f, 0, 0, D_NUM);
    spmm_dev(g_idx3, g_len3, CAP_PP, g_cinv3, 0, g_pro_str, g_nei3, 0, 0, 0.f, 0, 0, P_NUM);
    gsync(target);

    // ---- P5: GCN layer 1 + cross-domain neighbor means with fused mix
    spmm_dev(g_idx2, g_len2, CAP_DD, g_dinv2, g_dinv2, g_curD, g_x2a, g_acc2, 0, 0.f, 0, 0, D_NUM);
    spmm_dev(g_idx3, g_len3, CAP_PP, g_dinv3, g_dinv3, g_cur3, g_x3a, g_acc3, 0, 0.f, 0, 0, P_NUM);
    spmm_dev(g_idx4, g_len4, CAP_DD, g_dinv4, g_dinv4, g_curD, g_x4a, g_acc4, 0, 0.f, 0, 0, D_NUM);
    spmm_dev(g_idxR, g_lenR, CAP_PP, g_cinvRd, 0, g_nei3, 0, 0, 0, 0.f, g_dru_str, g_one_all, D_NUM);
    spmm_dev(g_idxRT, g_curRT, CAP_DD, g_cinvRp, 0, g_nei2, 0, 0, 0, 0.f, g_pro_str, g_tmpp, P_NUM);
    gsync(target);

    // ---- P6: GCN layer 2 + two_all GEMM
    spmm_dev(g_idx2, g_len2, CAP_DD, g_dinv2, g_dinv2, g_x2a, g_x2b, g_acc2, 0, 0.f, 0, 0, D_NUM);
    spmm_dev(g_idx3, g_len3, CAP_PP, g_dinv3, g_dinv3, g_x3a, g_x3b, g_acc3, 0, 0.f, 0, 0, P_NUM);
    spmm_dev(g_idx4, g_len4, CAP_DD, g_dinv4, g_dinv4, g_x4a, g_x4b, g_acc4, 0, 0.f, 0, 0, D_NUM);
    gemm_dev(g_tmpp, P_NUM, 128, g_Wc, 0, g_two_all, 0, 0, sbuf);
    gsync(target);

    // ---- P7: GCN layer 3 (finalize towers) + bipartite step 1
    spmm_dev(g_idx2, g_len2, CAP_DD, g_dinv2, g_dinv2, g_x2b, 0, g_acc2, g_emb2, 0.25f, 0, 0, D_NUM);
    spmm_dev(g_idx3, g_len3, CAP_PP, g_dinv3, g_dinv3, g_x3b, 0, g_acc3, g_emb3, 0.25f, 0, 0, P_NUM);
    spmm_dev(g_idx4, g_len4, CAP_DD, g_dinv4, g_dinv4, g_x4b, 0, g_acc4, g_emb4, 0.25f, 0, 0, D_NUM);
    spmm_dev(g_idxR, g_lenR, CAP_PP, g_dinvRd, g_dinvRp, g_two_all, g_bd1, g_accd, 0, 0.f, 0, 0, D_NUM);
    spmm_dev(g_idxRT, g_curRT, CAP_DD, g_dinvRp, g_dinvRd, g_one_emb, g_bp1, 0, 0, 0.f, 0, 0, P_NUM);
    spmm_dev(g_idxRT, g_curRT, CAP_DD, g_dinvRp, g_dinvRd, g_one_all, g_bpx, g_accp, 0, 0.f, 0, 0, P_NUM);
    spmm_dev(g_idxR, g_lenR, CAP_PP, g_dinvRd, g_dinvRp, g_two_emb, g_bdx, 0, 0, 0.f, 0, 0, D_NUM);
    gsync(target);

    // ---- P8: bipartite step 2 + tower attention heads (overlap)
    spmm_dev(g_idxRT, g_curRT, CAP_DD, g_dinvRp, g_dinvRd, g_bd1, g_bp2, 0, 0, 0.f, 0, 0, P_NUM);
    spmm_dev(g_idxR, g_lenR, CAP_PP, g_dinvRd, g_dinvRp, g_bp1, 0, g_accd, 0, 0.f, 0, 0, D_NUM);
    spmm_dev(g_idxRT, g_curRT, CAP_DD, g_dinvRp, g_dinvRd, g_bdx, 0, g_accp, 0, 0.f, 0, 0, P_NUM);
    spmm_dev(g_idxR, g_lenR, CAP_PP, g_dinvRd, g_dinvRp, g_bpx, g_bdy, 0, 0, 0.f, 0, 0, D_NUM);
    att_dev(g_emb2, WB_drug, BB_drug, HB_drug, g_wdrel, D_NUM, sbuf);
    att_dev(g_emb3, WB_pro, BB_pro, HB_pro, g_wprel, P_NUM, sbuf);
    att_dev(g_emb4, WA_sim, BA_sim, HA_sim, g_wdsim, D_NUM, sbuf);
    gsync(target);

    // ---- P9: bipartite step 3
    spmm_dev(g_idxR, g_lenR, CAP_PP, g_dinvRd, g_dinvRp, g_bp2, 0, g_accd, g_dru_int, 0.25f, 0, 0, D_NUM);
    spmm_dev(g_idxRT, g_curRT, CAP_DD, g_dinvRp, g_dinvRd, g_bdy, 0, g_accp, g_pro_int, 0.25f, 0, 0, P_NUM);
    gsync(target);

    // ---- P10: remaining attention heads
    att_dev(g_dru_int, WA_drug, BA_drug, HA_drug, g_wdrug, D_NUM, sbuf);
    att_dev(g_pro_int, WA_pro, BA_pro, HA_pro, g_wpro, P_NUM, sbuf);
    gsync(target);

    // ---- P11: log-softmax
    if (blockIdx.x < 5) {
        float* s; int n;
        switch (blockIdx.x) {
            case 0: s = g_wdrug; n = D_NUM; break;
            case 1: s = g_wpro;  n = P_NUM; break;
            case 2: s = g_wdrel; n = D_NUM; break;
            case 3: s = g_wprel; n = P_NUM; break;
            default:s = g_wdsim; n = D_NUM; break;
        }
        ls_dev(s, n, sbuf);
    }
    gsync(target);

    // ---- P12: weighted combine
    {
        int stride = gridDim.x * blockDim.x;
        for (int i = blockIdx.x * blockDim.x + threadIdx.x; i < DB + PB; i += stride) {
            if (i < DB) {
                int r = i >> 7;
                float wa = g_wdrug[r], wb = g_wdrel[r], wc = g_wdsim[r];
                float a = wa / (wa + wb + wc);
                float b = wb / (a + wb + wc);
                float c = 1.0f - a - b;
                g_fin_d[i] = a * g_dru_int[i] + b * g_emb2[i] + c * g_emb4[i];
            } else {
                int j = i - DB;
                int r = j >> 7;
                float wa = g_wpro[r], wb = g_wprel[r];
                float pa = wa / (wa + wb);
                g_fin_p[j] = pa * g_pro_int[j] + (1.0f - pa) * g_emb3[j];
            }
        }
    }
    gsync(target);

    // ---- P13: Gram matrices + column sums (blocks 0..127)
    if (blockIdx.x < 128) {
        const float* X; int n, brel, nblk;
        float* gG; float* gS;
        if (blockIdx.x < 32) { X = g_fin_d; n = D_NUM; brel = blockIdx.x;      nblk = 32; gG = g_gd; gS = g_sd; }
        else                 { X = g_fin_p; n = P_NUM; brel = blockIdx.x - 32; nblk = 96; gG = g_gp; gS = g_sp; }
        int ntiles = (n + 15) >> 4;
        int k0 = (threadIdx.x & 15) * 8, l0 = (threadIdx.x >> 4) * 8;
        float accG[8][8];
#pragma unroll
        for (int i = 0; i < 8; i++)
#pragma unroll
            for (int j = 0; j < 8; j++) accG[i][j] = 0.f;
        float cs = 0.f;
        for (int t = brel; t < ntiles; t += nblk) {
            int r0 = t << 4;
            __syncthreads();
            for (int i = threadIdx.x; i < 16 * 128; i += MEGA_THREADS) {
                int rr = i >> 7, kk = i & 127;
                int gr = r0 + rr;
                sbuf[rr * 132 + kk] = (gr < n) ? X[(size_t)gr * EMB + kk] : 0.f;
            }
            __syncthreads();
#pragma unroll 4
            for (int r = 0; r < 16; r++) {
                const float* row = &sbuf[r * 132];
                float4 a0 = *(const float4*)(row + k0);
                float4 a1 = *(const float4*)(row + k0 + 4);
                float4 b0 = *(const float4*)(row + l0);
                float4 b1 = *(const float4*)(row + l0 + 4);
                float av[8] = {a0.x, a0.y, a0.z, a0.w, a1.x, a1.y, a1.z, a1.w};
                float bv[8] = {b0.x, b0.y, b0.z, b0.w, b1.x, b1.y, b1.z, b1.w};
#pragma unroll
                for (int i = 0; i < 8; i++)
#pragma unroll
                    for (int j = 0; j < 8; j++) accG[i][j] += av[i] * bv[j];
            }
            if (threadIdx.x < 128) {
                float c = 0.f;
                for (int r = 0; r < 16; r++) c += sbuf[r * 132 + threadIdx.x];
                cs += c;
            }
        }
#pragma unroll
        for (int i = 0; i < 8; i++)
#pragma unroll
            for (int j = 0; j < 8; j++)
                atomicAdd(&gG[(k0 + i) * EMB + (l0 + j)], accG[i][j]);
        if (threadIdx.x < 128) atomicAdd(&gS[threadIdx.x], cs);
    }
    gsync(target);

    // ---- P14: reduce stats -> g_musig (block 0 only)
    if (blockIdx.x == 0) {
        double* sd = (double*)sbuf;
        double acc = 0.0;
        for (int i = threadIdx.x; i < EMB * EMB; i += MEGA_THREADS)
            acc += (double)g_gd[i] * (double)g_gp[i];
        sd[threadIdx.x] = acc; __syncthreads();
        for (int o = 128; o; o >>= 1) { if (threadIdx.x < o) sd[threadIdx.x] += sd[threadIdx.x + o]; __syncthreads(); }
        double sumsq = sd[0]; __syncthreads();
        double a2 = (threadIdx.x < EMB) ? (double)g_sd[threadIdx.x] * (double)g_sp[threadIdx.x] : 0.0;
        sd[threadIdx.x] = a2; __syncthreads();
        for (int o = 128; o; o >>= 1) { if (threadIdx.x < o) sd[threadIdx.x] += sd[threadIdx.x + o]; __syncthreads(); }
        if (threadIdx.x == 0) {
            double sumy = sd[0];
            const double nn = (double)D_NUM * (double)P_NUM;
            double mean = sumy / nn;
            double var = (sumsq - sumy * sumy / nn) / (nn - 1.0);
            g_musig = make_float2((float)mean, (float)(1.0 / sqrt(var)));
        }
    }
}

// ---------------- final GEMM with fused standardize+sigmoid ----------------
__global__ void __launch_bounds__(256) k_final_gemm(float* __restrict__ out) {
    __shared__ __align__(16) float sA[32 * 132];
    __shared__ __align__(16) float sB[32 * 132];
    float2 ms = g_musig;
    float mu = ms.x, istd = ms.y;
    int bi = blockIdx.y * 128, bj = blockIdx.x * 128;
    int t = threadIdx.x;
    int tx = t & 15, ty = t >> 4;
    int m0 = ty * 8, n0 = tx * 8;
    float acc[8][8];
#pragma unroll
    for (int i = 0; i < 8; i++)
#pragma unroll
        for (int j = 0; j < 8; j++) acc[i][j] = 0.0f;

    for (int k0 = 0; k0 < EMB; k0 += 32) {
#pragma unroll
        for (int it = 0; it < 4; it++) {
            int e = t + it * 256;
            int rr = e >> 3, kv = e & 7;
            int gi = bi + rr, gj = bj + rr;
            float4 va = (gi < D_NUM) ? *(const float4*)&g_fin_d[(size_t)gi * EMB + k0 + kv * 4]
                                     : make_float4(0.f, 0.f, 0.f, 0.f);
            float4 vb = (gj < P_NUM) ? *(const float4*)&g_fin_p[(size_t)gj * EMB + k0 + kv * 4]
                                     : make_float4(0.f, 0.f, 0.f, 0.f);
            sA[(kv * 4 + 0) * 132 + rr] = va.x;
            sA[(kv * 4 + 1) * 132 + rr] = va.y;
            sA[(kv * 4 + 2) * 132 + rr] = va.z;
            sA[(kv * 4 + 3) * 132 + rr] = va.w;
            sB[(kv * 4 + 0) * 132 + rr] = vb.x;
            sB[(kv * 4 + 1) * 132 + rr] = vb.y;
            sB[(kv * 4 + 2) * 132 + rr] = vb.z;
            sB[(kv * 4 + 3) * 132 + rr] = vb.w;
        }
        __syncthreads();
#pragma unroll
        for (int kk = 0; kk < 32; kk++) {
            const float* pa = &sA[kk * 132 + m0];
            const float* pb = &sB[kk * 132 + n0];
            float4 a0 = *(const float4*)pa;
            float4 a1 = *(const float4*)(pa + 4);
            float4 b0 = *(const float4*)pb;
            float4 b1 = *(const float4*)(pb + 4);
            float ra[8] = {a0.x, a0.y, a0.z, a0.w, a1.x, a1.y, a1.z, a1.w};
            float rb[8] = {b0.x, b0.y, b0.z, b0.w, b1.x, b1.y, b1.z, b1.w};
#pragma unroll
            for (int i = 0; i < 8; i++)
#pragma unroll
                for (int j = 0; j < 8; j++) acc[i][j] += ra[i] * rb[j];
        }
        __syncthreads();
    }
#pragma unroll
    for (int i = 0; i < 8; i++) {
        int gi = bi + m0 + i;
        if (gi < D_NUM) {
#pragma unroll
            for (int j = 0; j < 8; j++) {
                int gj = bj + n0 + j;
                if (gj < P_NUM) {
                    float z = (acc[i][j] - mu) * istd;
                    out[(size_t)gi * P_NUM + gj] = __fdividef(1.0f, 1.0f + __expf(-z));
                }
            }
        }
    }
}

// ---------------- host launcher ----------------
extern "C" void kernel_launch(void* const* d_in, const int* in_sizes, int n_in,
                              void* d_out, int out_size) {
    const float* A                 = (const float*)d_in[0];
    const float* drug_structure    = (const float*)d_in[1];
    const float* protein_structure = (const float*)d_in[2];
    const float* lin_drug_w = (const float*)d_in[3];
    const float* lin_drug_b = (const float*)d_in[4];
    const float* lin_pro_w  = (const float*)d_in[5];
    const float* lin_pro_b  = (const float*)d_in[6];
    const float* p_weight   = (const float*)d_in[7];
    const float* d_weight_i = (const float*)d_in[8];
    const float* pd_weight_p = (const float*)d_in[9];
    const float* pd_weight_d = (const float*)d_in[10];
    const float* dp_weight_p = (const float*)d_in[11];
    const float* WA_drug = (const float*)d_in[12];
    const float* BA_drug = (const float*)d_in[13];
    const float* HA_drug = (const float*)d_in[14];
    const float* WB_drug = (const float*)d_in[15];
    const float* BB_drug = (const float*)d_in[16];
    const float* HB_drug = (const float*)d_in[17];
    const float* WA_pro = (const float*)d_in[18];
    const float* BA_pro = (const float*)d_in[19];
    const float* HA_pro = (const float*)d_in[20];
    const float* WB_pro = (const float*)d_in[21];
    const float* BB_pro = (const float*)d_in[22];
    const float* HB_pro = (const float*)d_in[23];
    const float* WA_sim = (const float*)d_in[24];
    const float* BA_sim = (const float*)d_in[25];
    const float* HA_sim = (const float*)d_in[26];
    float* out = (float*)d_out;
    (void)in_sizes; (void)n_in; (void)out_size;

    void* tp;
    cudaGetSymbolAddress(&tp, g_curRT);  void* p_curRT  = tp;
    cudaGetSymbolAddress(&tp, g_barcnt); void* p_barcnt = tp;

    cudaMemsetAsync(p_curRT, 0, P_NUM * sizeof(int), 0);
    cudaMemsetAsync(p_barcnt, 0, sizeof(unsigned), 0);

    k_ell_all<<<9000, 256>>>(A);

    k_mega<<<MEGA_BLKS, MEGA_THREADS>>>(
        drug_structure, protein_structure,
        lin_drug_w, lin_drug_b, lin_pro_w, lin_pro_b,
        p_weight, d_weight_i, pd_weight_p, pd_weight_d, dp_weight_p,
        WA_drug, BA_drug, HA_drug,
        WB_drug, BB_drug, HB_drug,
        WA_pro, BA_pro, HA_pro,
        WB_pro, BB_pro, HB_pro,
        WA_sim, BA_sim, HA_sim);

    dim3 fg((P_NUM + 127) / 128, (D_NUM + 127) / 128);
    k_final_gemm<<<fg, 256>>>(out);
}

// round 12
// speedup vs baseline: 1.4061x; 1.3624x over previous
#include <cuda_runtime.h>
#include <cuda_bf16.h>
#include <math.h>
#include <stdint.h>

#define D_NUM 1500
#define P_NUM 4500
#define NTOT  6000
#define EMB   128
#define CAP_DD 64
#define CAP_PP 128
#define DB (D_NUM*EMB)
#define PB (P_NUM*EMB)
#define MEGA_BLKS 296
#define MEGA_THREADS 256

// ---------------- scratch (static __device__, no allocs) ----------------
__device__ __align__(128) int g_idx2[D_NUM*CAP_DD]; __device__ int g_len2[D_NUM];
__device__ __align__(128) int g_idx4[D_NUM*CAP_DD]; __device__ int g_len4[D_NUM];
__device__ __align__(128) int g_idx3[P_NUM*CAP_PP]; __device__ int g_len3[P_NUM];
__device__ __align__(128) int g_idxR[D_NUM*CAP_PP]; __device__ int g_lenR[D_NUM];
__device__ __align__(128) int g_idxRT[P_NUM*CAP_DD]; __device__ int g_curRT[P_NUM];

__device__ float g_dinv2[D_NUM], g_cinv2[D_NUM];
__device__ float g_dinv3[P_NUM], g_cinv3[P_NUM];
__device__ float g_dinv4[D_NUM];
__device__ float g_dinvRd[D_NUM], g_cinvRd[D_NUM];
__device__ float g_dinvRp[P_NUM], g_cinvRp[P_NUM];

__device__ __align__(128) float g_dru_str[DB], g_pro_str[PB];
__device__ __align__(128) float g_nei2[DB],    g_nei3[PB];
__device__ __align__(128) float g_emb2[DB],    g_emb3[PB],  g_emb4[DB];
__device__ __align__(128) float g_curD[DB],    g_cur3[PB];
__device__ __align__(128) float g_x2a[DB], g_x2b[DB], g_x4a[DB], g_x4b[DB];
__device__ __align__(128) float g_x3a[PB], g_x3b[PB];
__device__ __align__(128) float g_acc2[DB], g_acc3[PB], g_acc4[DB];
__device__ __align__(128) float g_one_emb[DB], g_two_all[PB], g_one_all[DB], g_two_emb[PB];
__device__ __align__(128) float g_bd1[DB],  g_bp1[PB], g_bp2[PB];
__device__ __align__(128) float g_bdx[DB],  g_bpx[PB], g_bdy[DB];
__device__ __align__(128) float g_accd[DB], g_accp[PB];
__device__ __align__(128) float g_dru_int[DB], g_pro_int[PB];
__device__ __align__(128) float g_tmpp[PB], g_Wc[EMB*EMB];
__device__ __align__(128) float g_fin_d[DB], g_fin_p[PB];
__device__ float g_wdrug[D_NUM], g_wdrel[D_NUM], g_wdsim[D_NUM];
__device__ float g_wpro[P_NUM],  g_wprel[P_NUM];
__device__ __align__(128) float g_gd[EMB*EMB], g_gp[EMB*EMB];
__device__ float g_sd[EMB], g_sp[EMB];
__device__ float2 g_musig;
__device__ unsigned g_barcnt;

// ---------------- ELL extraction (round-6 version) ----------------
__global__ void k_ell_all(const float* __restrict__ A) {
    const size_t NN = (size_t)NTOT * NTOT;
    int b = blockIdx.x;
    const float* base; int r, row0, col0, ncols, cap; int *idx, *len;
    if (b < 1500)      { base = A + 2*NN; r = b;        row0 = 0;     col0 = 0;     ncols = D_NUM; cap = CAP_DD; idx = g_idx2; len = g_len2; }
    else if (b < 6000) { base = A + 3*NN; r = b - 1500; row0 = D_NUM; col0 = D_NUM; ncols = P_NUM; cap = CAP_PP; idx = g_idx3; len = g_len3; }
    else if (b < 7500) { base = A + 4*NN; r = b - 6000; row0 = 0;     col0 = 0;     ncols = D_NUM; cap = CAP_DD; idx = g_idx4; len = g_len4; }
    else               { base = A;        r = b - 7500; row0 = 0;     col0 = D_NUM; ncols = P_NUM; cap = CAP_PP; idx = g_idxR; len = g_lenR; }

    const float4* row4 = (const float4*)(base + (size_t)(row0 + r) * NTOT + col0);
    int nv = ncols >> 2;
    __shared__ int cnt;
    __shared__ int buf[160];
    if (threadIdx.x == 0) cnt = 0;
    __syncthreads();

    float4 v[5];
#pragma unroll
    for (int u = 0; u < 5; u++) {
        int i = threadIdx.x + (u << 8);
        if (i < nv) v[u] = __ldg(&row4[i]);
    }
#pragma unroll
    for (int u = 0; u < 5; u++) {
        int i = threadIdx.x + (u << 8);
        if (i < nv) {
            int c = i << 2;
            if (v[u].x == 1.0f) { int p = atomicAdd(&cnt, 1); if (p < 160) buf[p] = c; }
            if (v[u].y == 1.0f) { int p = atomicAdd(&cnt, 1); if (p < 160) buf[p] = c + 1; }
            if (v[u].z == 1.0f) { int p = atomicAdd(&cnt, 1); if (p < 160) buf[p] = c + 2; }
            if (v[u].w == 1.0f) { int p = atomicAdd(&cnt, 1); if (p < 160) buf[p] = c + 3; }
        }
    }
    __syncthreads();
    int L = min(cnt, cap);
    if (threadIdx.x == 0) {
        len[r] = L;
        for (int i = 1; i < L; i++) {
            int t = buf[i]; int j = i - 1;
            while (j >= 0 && buf[j] > t) { buf[j + 1] = buf[j]; j--; }
            buf[j + 1] = t;
        }
    }
    __syncthreads();
    for (int i = threadIdx.x; i < L; i += blockDim.x)
        idx[(size_t)r * cap + i] = buf[i];
}

// ------------- grid barrier (round-6 monotonic, known-good) ----------------
__device__ __forceinline__ void gsync(unsigned& target) {
    __syncthreads();
    if (threadIdx.x == 0) {
        __threadfence();
        atomicAdd(&g_barcnt, 1u);
        target += gridDim.x;
        unsigned v;
        do {
            asm volatile("ld.acquire.gpu.global.u32 %0, [%1];"
                         : "=r"(v) : "l"(&g_barcnt) : "memory");
        } while (v < target);
    }
    __syncthreads();
}

// ---------------- round-6 device helpers (unchanged) ----------------
__device__ void gemm_dev(const float* A, int n, int k,
                         const float* W, bool wext, const float* bias,
                         float* C, float* C2, float* C3, float* sA) {
    int ntiles = (n + 15) >> 4;
    int col = threadIdx.x & 127;
    int half = threadIdx.x >> 7;
    for (int t = blockIdx.x; t < ntiles; t += gridDim.x) {
        int r0 = t << 4;
        __syncthreads();
        for (int i = threadIdx.x; i < (k << 4); i += MEGA_THREADS) {
            int rr = i / k, kk = i - rr * k;
            int gr = r0 + rr;
            sA[rr * k + kk] = (gr < n) ? A[(size_t)gr * k + kk] : 0.0f;
        }
        __syncthreads();
        float acc[8];
#pragma unroll
        for (int rr = 0; rr < 8; rr++) acc[rr] = 0.0f;
        const float* sAr = sA + (half << 3) * k;
        for (int kk = 0; kk < k; kk++) {
            float w = wext ? __ldg(&W[(size_t)kk * EMB + col]) : W[(size_t)kk * EMB + col];
#pragma unroll
            for (int rr = 0; rr < 8; rr++) acc[rr] += sAr[rr * k + kk] * w;
        }
        float b = bias ? __ldg(bias + col) : 0.0f;
#pragma unroll
        for (int rr = 0; rr < 8; rr++) {
            int gr = r0 + (half << 3) + rr;
            if (gr < n) {
                float v = acc[rr] + b;
                size_t o = (size_t)gr * EMB + col;
                C[o] = v;
                if (C2) C2[o] = v;
                if (C3) C3[o] = v;
            }
        }
    }
}

__device__ void spmm_dev(const int* idx, const int* len, int cap,
                         const float* rs, const float* cs, const float* x,
                         float* out, float* acc, float* fin, float fscale,
                         const float* mixb, float* mixo, int n) {
    int nw = (gridDim.x * blockDim.x) >> 5;
    int gw = (blockIdx.x * blockDim.x + threadIdx.x) >> 5;
    int lane = threadIdx.x & 31;
    const float4* x4 = (const float4*)x;
    for (int r = gw; r < n; r += nw) {
        int L = len[r];
        float4 s = make_float4(0.f, 0.f, 0.f, 0.f);
        for (int p0 = 0; p0 < L; p0 += 32) {
            int j = 0; float f = 0.f;
            if (p0 + lane < L) {
                j = idx[(size_t)r * cap + p0 + lane];
                f = cs ? cs[j] : 1.0f;
            }
            int m = min(32, L - p0);
            int q = 0;
            for (; q + 4 <= m; q += 4) {
                int j0 = __shfl_sync(0xffffffffu, j, q);
                int j1 = __shfl_sync(0xffffffffu, j, q + 1);
                int j2 = __shfl_sync(0xffffffffu, j, q + 2);
                int j3 = __shfl_sync(0xffffffffu, j, q + 3);
                float f0 = __shfl_sync(0xffffffffu, f, q);
                float f1 = __shfl_sync(0xffffffffu, f, q + 1);
                float f2 = __shfl_sync(0xffffffffu, f, q + 2);
                float f3 = __shfl_sync(0xffffffffu, f, q + 3);
                float4 v0 = x4[(size_t)j0 * 32 + lane];
                float4 v1 = x4[(size_t)j1 * 32 + lane];
                float4 v2 = x4[(size_t)j2 * 32 + lane];
                float4 v3 = x4[(size_t)j3 * 32 + lane];
                s.x += f0 * v0.x + f1 * v1.x + f2 * v2.x + f3 * v3.x;
                s.y += f0 * v0.y + f1 * v1.y + f2 * v2.y + f3 * v3.y;
                s.z += f0 * v0.z + f1 * v1.z + f2 * v2.z + f3 * v3.z;
                s.w += f0 * v0.w + f1 * v1.w + f2 * v2.w + f3 * v3.w;
            }
            for (; q < m; q++) {
                int j0 = __shfl_sync(0xffffffffu, j, q);
                float f0 = __shfl_sync(0xffffffffu, f, q);
                float4 v0 = x4[(size_t)j0 * 32 + lane];
                s.x += f0 * v0.x; s.y += f0 * v0.y;
                s.z += f0 * v0.z; s.w += f0 * v0.w;
            }
        }
        float rr = rs[r];
        s.x *= rr; s.y *= rr; s.z *= rr; s.w *= rr;
        size_t o = (size_t)r * 32 + lane;
        if (out) ((float4*)out)[o] = s;
        if (acc) {
            float4 a = ((const float4*)acc)[o];
            a.x += s.x; a.y += s.y; a.z += s.z; a.w += s.w;
            ((float4*)acc)[o] = a;
            if (fin) {
                float4 ff = make_float4(a.x * fscale, a.y * fscale, a.z * fscale, a.w * fscale);
                ((float4*)fin)[o] = ff;
            }
        }
        if (mixo) {
            float4 mb = ((const float4*)mixb)[o];
            float4 mo = make_float4(0.8f * mb.x + 0.2f * s.x, 0.8f * mb.y + 0.2f * s.y,
                                    0.8f * mb.z + 0.2f * s.z, 0.8f * mb.w + 0.2f * s.w);
            ((float4*)mixo)[o] = mo;
        }
    }
}

__device__ void att_dev(const float* emb, const float* W, const float* B,
                        const float* H, float* s, int n, float* sE) {
    int ntiles = (n + 15) >> 4;
    int col = threadIdx.x & 127;
    int half = threadIdx.x >> 7;
    for (int t = blockIdx.x; t < ntiles; t += gridDim.x) {
        int r0 = t << 4;
        __syncthreads();
        for (int i = threadIdx.x; i < 16 * 128; i += MEGA_THREADS) {
            int rr = i >> 7, kk = i & 127;
            int gr = r0 + rr;
            sE[i] = (gr < n) ? emb[(size_t)gr * EMB + kk] : 0.0f;
        }
        __syncthreads();
        float acc[8];
#pragma unroll
        for (int rr = 0; rr < 8; rr++) acc[rr] = 0.0f;
        const float* sEr = sE + (half << 3) * 128;
#pragma unroll 4
        for (int kk = 0; kk < 128; kk++) {
            float w = __ldg(&W[kk * EMB + col]);
#pragma unroll
            for (int rr = 0; rr < 8; rr++) acc[rr] += sEr[rr * 128 + kk] * w;
        }
        float bb = __ldg(B + col), hh = __ldg(H + col);
        __syncthreads();
#pragma unroll
        for (int rr = 0; rr < 8; rr++)
            sE[((half << 3) + rr) * 128 + col] = fmaxf(acc[rr] + bb, 0.0f) * hh;
        __syncthreads();
        int wid = threadIdx.x >> 5, lane = threadIdx.x & 31;
#pragma unroll
        for (int i = 0; i < 2; i++) {
            int row = wid * 2 + i;
            float v = sE[row * 128 + lane] + sE[row * 128 + lane + 32]
                    + sE[row * 128 + lane + 64] + sE[row * 128 + lane + 96];
            for (int off = 16; off; off >>= 1) v += __shfl_down_sync(0xffffffffu, v, off);
            if (lane == 0 && r0 + row < n) s[r0 + row] = v;
        }
    }
}

__device__ void ls_dev(float* s, int n, float* sh) {
    int t = threadIdx.x;
    float m = -1e30f;
    for (int i = t; i < n; i += MEGA_THREADS) m = fmaxf(m, s[i]);
    sh[t] = m; __syncthreads();
    for (int o = 128; o; o >>= 1) { if (t < o) sh[t] = fmaxf(sh[t], sh[t + o]); __syncthreads(); }
    float mall = sh[0]; __syncthreads();
    float sum = 0.0f;
    for (int i = t; i < n; i += MEGA_THREADS) sum += expf(s[i] - mall);
    sh[t] = sum; __syncthreads();
    for (int o = 128; o; o >>= 1) { if (t < o) sh[t] += sh[t + o]; __syncthreads(); }
    float lse = mall + logf(sh[0]);
    __syncthreads();
    for (int i = t; i < n; i += MEGA_THREADS) s[i] -= lse;
}

// ---------------- the megakernel (round-6 structure, unchanged) ------------
__global__ void __launch_bounds__(MEGA_THREADS, 2) k_mega(
    const float* __restrict__ drug_structure, const float* __restrict__ protein_structure,
    const float* __restrict__ lin_drug_w, const float* __restrict__ lin_drug_b,
    const float* __restrict__ lin_pro_w, const float* __restrict__ lin_pro_b,
    const float* __restrict__ p_weight, const float* __restrict__ d_weight_i,
    const float* __restrict__ pd_weight_p, const float* __restrict__ pd_weight_d,
    const float* __restrict__ dp_weight_p,
    const float* __restrict__ WA_drug, const float* __restrict__ BA_drug, const float* __restrict__ HA_drug,
    const float* __restrict__ WB_drug, const float* __restrict__ BB_drug, const float* __restrict__ HB_drug,
    const float* __restrict__ WA_pro, const float* __restrict__ BA_pro, const float* __restrict__ HA_pro,
    const float* __restrict__ WB_pro, const float* __restrict__ BB_pro, const float* __restrict__ HB_pro,
    const float* __restrict__ WA_sim, const float* __restrict__ BA_sim, const float* __restrict__ HA_sim) {
    __shared__ __align__(16) float sbuf[16 * 512];
    unsigned target = 0;

    // ---- P1: build R^T + zero Gram/colsum accumulators
    {
        int nw = (gridDim.x * blockDim.x) >> 5;
        int gw = (blockIdx.x * blockDim.x + threadIdx.x) >> 5;
        int lane = threadIdx.x & 31;
        for (int r = gw; r < D_NUM; r += nw) {
            int L = g_lenR[r];
            for (int p = lane; p < L; p += 32) {
                int c = g_idxR[r * CAP_PP + p];
                int pos = atomicAdd(&g_curRT[c], 1);
                if (pos < CAP_DD) g_idxRT[c * CAP_DD + pos] = r;
            }
        }
        int stride = gridDim.x * blockDim.x;
        int gid = blockIdx.x * blockDim.x + threadIdx.x;
        for (int i = gid; i < EMB * EMB; i += stride) { g_gd[i] = 0.f; g_gp[i] = 0.f; }
        if (gid < EMB) { g_sd[gid] = 0.f; g_sp[gid] = 0.f; }
    }
    gsync(target);

    // ---- P2: sort R^T + degree scales + feature lifts + Wc (independent)
    {
        int i = blockIdx.x * blockDim.x + threadIdx.x;
        if (i < D_NUM) {
            int d;
            d = g_len2[i]; g_dinv2[i] = d > 0 ? rsqrtf((float)d) : 0.0f;
                           g_cinv2[i] = d > 0 ? 1.0f / (float)d : 0.0f;
            d = g_len4[i]; g_dinv4[i] = d > 0 ? rsqrtf((float)d) : 0.0f;
            d = g_lenR[i]; g_dinvRd[i] = d > 0 ? rsqrtf((float)d) : 0.0f;
                           g_cinvRd[i] = d > 0 ? 1.0f / (float)d : 0.0f;
        }
        if (i < P_NUM) {
            int d = g_len3[i];
            g_dinv3[i] = d > 0 ? rsqrtf((float)d) : 0.0f;
            g_cinv3[i] = d > 0 ? 1.0f / (float)d : 0.0f;
            int L = min(g_curRT[i], CAP_DD);
            g_curRT[i] = L;
            int* a = &g_idxRT[i * CAP_DD];
            for (int q = 1; q < L; q++) {
                int v = a[q]; int jj = q - 1;
                while (jj >= 0 && a[jj] > v) { a[jj + 1] = a[jj]; jj--; }
                a[jj + 1] = v;
            }
            g_dinvRp[i] = L > 0 ? rsqrtf((float)L) : 0.0f;
            g_cinvRp[i] = L > 0 ? 1.0f / (float)L : 0.0f;
        }
    }
    gemm_dev(drug_structure, D_NUM, 160, lin_drug_w, true, lin_drug_b, g_dru_str, 0, 0, sbuf);
    gemm_dev(protein_structure, P_NUM, 512, lin_pro_w, true, lin_pro_b, g_pro_str, 0, 0, sbuf);
    gemm_dev(dp_weight_p, 128, 128, pd_weight_d, true, 0, g_Wc, 0, 0, sbuf);
    gsync(target);

    // ---- P4: tower-input GEMMs (+acc inits) and neighbor means
    gemm_dev(g_dru_str, D_NUM, 128, d_weight_i, true, 0, g_curD, g_acc2, g_acc4, sbuf);
    gemm_dev(g_pro_str, P_NUM, 128, p_weight, true, 0, g_cur3, g_acc3, 0, sbuf);
    gemm_dev(g_dru_str, D_NUM, 128, pd_weight_d, true, 0, g_one_emb, g_accd, 0, sbuf);
    gemm_dev(g_pro_str, P_NUM, 128, pd_weight_p, true, 0, g_two_emb, g_accp, 0, sbuf);
    spmm_dev(g_idx2, g_len2, CAP_DD, g_cinv2, 0, g_dru_str, g_nei2, 0, 0, 0.f, 0, 0, D_NUM);
    spmm_dev(g_idx3, g_len3, CAP_PP, g_cinv3, 0, g_pro_str, g_nei3, 0, 0, 0.f, 0, 0, P_NUM);
    gsync(target);

    // ---- P5: GCN layer 1 + cross-domain neighbor means with fused mix
    spmm_dev(g_idx2, g_len2, CAP_DD, g_dinv2, g_dinv2, g_curD, g_x2a, g_acc2, 0, 0.f, 0, 0, D_NUM);
    spmm_dev(g_idx3, g_len3, CAP_PP, g_dinv3, g_dinv3, g_cur3, g_x3a, g_acc3, 0, 0.f, 0, 0, P_NUM);
    spmm_dev(g_idx4, g_len4, CAP_DD, g_dinv4, g_dinv4, g_curD, g_x4a, g_acc4, 0, 0.f, 0, 0, D_NUM);
    spmm_dev(g_idxR, g_lenR, CAP_PP, g_cinvRd, 0, g_nei3, 0, 0, 0, 0.f, g_dru_str, g_one_all, D_NUM);
    spmm_dev(g_idxRT, g_curRT, CAP_DD, g_cinvRp, 0, g_nei2, 0, 0, 0, 0.f, g_pro_str, g_tmpp, P_NUM);
    gsync(target);

    // ---- P6: GCN layer 2 + two_all GEMM
    spmm_dev(g_idx2, g_len2, CAP_DD, g_dinv2, g_dinv2, g_x2a, g_x2b, g_acc2, 0, 0.f, 0, 0, D_NUM);
    spmm_dev(g_idx3, g_len3, CAP_PP, g_dinv3, g_dinv3, g_x3a, g_x3b, g_acc3, 0, 0.f, 0, 0, P_NUM);
    spmm_dev(g_idx4, g_len4, CAP_DD, g_dinv4, g_dinv4, g_x4a, g_x4b, g_acc4, 0, 0.f, 0, 0, D_NUM);
    gemm_dev(g_tmpp, P_NUM, 128, g_Wc, false, 0, g_two_all, 0, 0, sbuf);
    gsync(target);

    // ---- P7: GCN layer 3 (finalize towers) + bipartite step 1
    spmm_dev(g_idx2, g_len2, CAP_DD, g_dinv2, g_dinv2, g_x2b, 0, g_acc2, g_emb2, 0.25f, 0, 0, D_NUM);
    spmm_dev(g_idx3, g_len3, CAP_PP, g_dinv3, g_dinv3, g_x3b, 0, g_acc3, g_emb3, 0.25f, 0, 0, P_NUM);
    spmm_dev(g_idx4, g_len4, CAP_DD, g_dinv4, g_dinv4, g_x4b, 0, g_acc4, g_emb4, 0.25f, 0, 0, D_NUM);
    spmm_dev(g_idxR, g_lenR, CAP_PP, g_dinvRd, g_dinvRp, g_two_all, g_bd1, g_accd, 0, 0.f, 0, 0, D_NUM);
    spmm_dev(g_idxRT, g_curRT, CAP_DD, g_dinvRp, g_dinvRd, g_one_emb, g_bp1, 0, 0, 0.f, 0, 0, P_NUM);
    spmm_dev(g_idxRT, g_curRT, CAP_DD, g_dinvRp, g_dinvRd, g_one_all, g_bpx, g_accp, 0, 0.f, 0, 0, P_NUM);
    spmm_dev(g_idxR, g_lenR, CAP_PP, g_dinvRd, g_dinvRp, g_two_emb, g_bdx, 0, 0, 0.f, 0, 0, D_NUM);
    gsync(target);

    // ---- P8: bipartite step 2 + tower attention heads (overlap)
    spmm_dev(g_idxRT, g_curRT, CAP_DD, g_dinvRp, g_dinvRd, g_bd1, g_bp2, 0, 0, 0.f, 0, 0, P_NUM);
    spmm_dev(g_idxR, g_lenR, CAP_PP, g_dinvRd, g_dinvRp, g_bp1, 0, g_accd, 0, 0.f, 0, 0, D_NUM);
    spmm_dev(g_idxRT, g_curRT, CAP_DD, g_dinvRp, g_dinvRd, g_bdx, 0, g_accp, 0, 0.f, 0, 0, P_NUM);
    spmm_dev(g_idxR, g_lenR, CAP_PP, g_dinvRd, g_dinvRp, g_bpx, g_bdy, 0, 0, 0.f, 0, 0, D_NUM);
    att_dev(g_emb2, WB_drug, BB_drug, HB_drug, g_wdrel, D_NUM, sbuf);
    att_dev(g_emb3, WB_pro, BB_pro, HB_pro, g_wprel, P_NUM, sbuf);
    att_dev(g_emb4, WA_sim, BA_sim, HA_sim, g_wdsim, D_NUM, sbuf);
    gsync(target);

    // ---- P9: bipartite step 3
    spmm_dev(g_idxR, g_lenR, CAP_PP, g_dinvRd, g_dinvRp, g_bp2, 0, g_accd, g_dru_int, 0.25f, 0, 0, D_NUM);
    spmm_dev(g_idxRT, g_curRT, CAP_DD, g_dinvRp, g_dinvRd, g_bdy, 0, g_accp, g_pro_int, 0.25f, 0, 0, P_NUM);
    gsync(target);

    // ---- P10: remaining attention heads
    att_dev(g_dru_int, WA_drug, BA_drug, HA_drug, g_wdrug, D_NUM, sbuf);
    att_dev(g_pro_int, WA_pro, BA_pro, HA_pro, g_wpro, P_NUM, sbuf);
    gsync(target);

    // ---- P11: log-softmax
    if (blockIdx.x < 5) {
        float* s; int n;
        switch (blockIdx.x) {
            case 0: s = g_wdrug; n = D_NUM; break;
            case 1: s = g_wpro;  n = P_NUM; break;
            case 2: s = g_wdrel; n = D_NUM; break;
            case 3: s = g_wprel; n = P_NUM; break;
            default:s = g_wdsim; n = D_NUM; break;
        }
        ls_dev(s, n, sbuf);
    }
    gsync(target);

    // ---- P12: weighted combine
    {
        int stride = gridDim.x * blockDim.x;
        for (int i = blockIdx.x * blockDim.x + threadIdx.x; i < DB + PB; i += stride) {
            if (i < DB) {
                int r = i >> 7;
                float wa = g_wdrug[r], wb = g_wdrel[r], wc = g_wdsim[r];
                float a = wa / (wa + wb + wc);
                float b = wb / (a + wb + wc);
                float c = 1.0f - a - b;
                g_fin_d[i] = a * g_dru_int[i] + b * g_emb2[i] + c * g_emb4[i];
            } else {
                int j = i - DB;
                int r = j >> 7;
                float wa = g_wpro[r], wb = g_wprel[r];
                float pa = wa / (wa + wb);
                g_fin_p[j] = pa * g_pro_int[j] + (1.0f - pa) * g_emb3[j];
            }
        }
    }
    gsync(target);

    // ---- P13: Gram matrices + column sums (blocks 0..127)
    if (blockIdx.x < 128) {
        const float* X; int n, brel, nblk;
        float* gG; float* gS;
        if (blockIdx.x < 32) { X = g_fin_d; n = D_NUM; brel = blockIdx.x;      nblk = 32; gG = g_gd; gS = g_sd; }
        else                 { X = g_fin_p; n = P_NUM; brel = blockIdx.x - 32; nblk = 96; gG = g_gp; gS = g_sp; }
        int ntiles = (n + 15) >> 4;
        int k0 = (threadIdx.x & 15) * 8, l0 = (threadIdx.x >> 4) * 8;
        float accG[8][8];
#pragma unroll
        for (int i = 0; i < 8; i++)
#pragma unroll
            for (int j = 0; j < 8; j++) accG[i][j] = 0.f;
        float cs = 0.f;
        for (int t = brel; t < ntiles; t += nblk) {
            int r0 = t << 4;
            __syncthreads();
            for (int i = threadIdx.x; i < 16 * 128; i += MEGA_THREADS) {
                int rr = i >> 7, kk = i & 127;
                int gr = r0 + rr;
                sbuf[rr * 132 + kk] = (gr < n) ? X[(size_t)gr * EMB + kk] : 0.f;
            }
            __syncthreads();
#pragma unroll 4
            for (int r = 0; r < 16; r++) {
                const float* row = &sbuf[r * 132];
                float4 a0 = *(const float4*)(row + k0);
                float4 a1 = *(const float4*)(row + k0 + 4);
                float4 b0 = *(const float4*)(row + l0);
                float4 b1 = *(const float4*)(row + l0 + 4);
                float av[8] = {a0.x, a0.y, a0.z, a0.w, a1.x, a1.y, a1.z, a1.w};
                float bv[8] = {b0.x, b0.y, b0.z, b0.w, b1.x, b1.y, b1.z, b1.w};
#pragma unroll
                for (int i = 0; i < 8; i++)
#pragma unroll
                    for (int j = 0; j < 8; j++) accG[i][j] += av[i] * bv[j];
            }
            if (threadIdx.x < 128) {
                float c = 0.f;
                for (int r = 0; r < 16; r++) c += sbuf[r * 132 + threadIdx.x];
                cs += c;
            }
        }
#pragma unroll
        for (int i = 0; i < 8; i++)
#pragma unroll
            for (int j = 0; j < 8; j++)
                atomicAdd(&gG[(k0 + i) * EMB + (l0 + j)], accG[i][j]);
        if (threadIdx.x < 128) atomicAdd(&gS[threadIdx.x], cs);
    }
    gsync(target);

    // ---- P14: reduce stats -> g_musig (block 0 only)
    if (blockIdx.x == 0) {
        double* sd = (double*)sbuf;
        double acc = 0.0;
        for (int i = threadIdx.x; i < EMB * EMB; i += MEGA_THREADS)
            acc += (double)g_gd[i] * (double)g_gp[i];
        sd[threadIdx.x] = acc; __syncthreads();
        for (int o = 128; o; o >>= 1) { if (threadIdx.x < o) sd[threadIdx.x] += sd[threadIdx.x + o]; __syncthreads(); }
        double sumsq = sd[0]; __syncthreads();
        double a2 = (threadIdx.x < EMB) ? (double)g_sd[threadIdx.x] * (double)g_sp[threadIdx.x] : 0.0;
        sd[threadIdx.x] = a2; __syncthreads();
        for (int o = 128; o; o >>= 1) { if (threadIdx.x < o) sd[threadIdx.x] += sd[threadIdx.x + o]; __syncthreads(); }
        if (threadIdx.x == 0) {
            double sumy = sd[0];
            const double nn = (double)D_NUM * (double)P_NUM;
            double mean = sumy / nn;
            double var = (sumsq - sumy * sumy / nn) / (nn - 1.0);
            g_musig = make_float2((float)mean, (float)(1.0 / sqrt(var)));
        }
    }
}

// ====== final GEMM: warp-level bf16 mma.sync (sm_80 path, compute_103 OK) ====
// D = AhBh + AhBl + AlBh (fp32 accum), fused standardize+sigmoid epilogue.
// Block 128x128, 8 warps (4m x 2n), warp tile 32x64, mma m16n8k16.
#define FS 136                    // bf16 row stride (128 + 8 pad)
#define SM_AH_OFF 0
#define SM_AL_OFF (128*FS*2)
#define SM_BH_OFF (2*128*FS*2)
#define SM_BL_OFF (3*128*FS*2)
#define SMEM_MMA  (4*128*FS*2)    // 139,264 bytes

__device__ __forceinline__ void mma_bf16(
    float& c0, float& c1, float& c2, float& c3,
    uint32_t a0, uint32_t a1, uint32_t a2, uint32_t a3,
    uint32_t b0, uint32_t b1) {
    asm volatile(
        "mma.sync.aligned.m16n8k16.row.col.f32.bf16.bf16.f32 "
        "{%0,%1,%2,%3}, {%4,%5,%6,%7}, {%8,%9}, {%0,%1,%2,%3};"
        : "+f"(c0), "+f"(c1), "+f"(c2), "+f"(c3)
        : "r"(a0), "r"(a1), "r"(a2), "r"(a3), "r"(b0), "r"(b1));
}

__global__ void __launch_bounds__(256) k_final_mma(float* __restrict__ out) {
    extern __shared__ __align__(16) char smem[];
    __nv_bfloat16* Ah = (__nv_bfloat16*)(smem + SM_AH_OFF);
    __nv_bfloat16* Al = (__nv_bfloat16*)(smem + SM_AL_OFF);
    __nv_bfloat16* Bh = (__nv_bfloat16*)(smem + SM_BH_OFF);
    __nv_bfloat16* Bl = (__nv_bfloat16*)(smem + SM_BL_OFF);

    int t = threadIdx.x;
    int bi = blockIdx.y * 128, bj = blockIdx.x * 128;
    float2 ms = g_musig;
    float mu = ms.x, istd = ms.y;

    // ---- stage: convert fin_d / fin_p rows to bf16 hi/lo in smem
    {
        int row = t >> 1;
        int c0 = (t & 1) * 64;
        int gi = bi + row, gj = bj + row;
        const float4* sa = (gi < D_NUM) ? (const float4*)&g_fin_d[(size_t)gi * EMB + c0] : 0;
        const float4* sb = (gj < P_NUM) ? (const float4*)&g_fin_p[(size_t)gj * EMB + c0] : 0;
#pragma unroll 4
        for (int q = 0; q < 16; q++) {
            int c = c0 + q * 4;
            float4 va = sa ? __ldg(&sa[q]) : make_float4(0.f, 0.f, 0.f, 0.f);
            float4 vb = sb ? __ldg(&sb[q]) : make_float4(0.f, 0.f, 0.f, 0.f);
            __nv_bfloat162 ah01 = __floats2bfloat162_rn(va.x, va.y);
            __nv_bfloat162 ah23 = __floats2bfloat162_rn(va.z, va.w);
            __nv_bfloat162 al01 = __floats2bfloat162_rn(
                va.x - __bfloat162float(__low2bfloat16(ah01)),
                va.y - __bfloat162float(__high2bfloat16(ah01)));
            __nv_bfloat162 al23 = __floats2bfloat162_rn(
                va.z - __bfloat162float(__low2bfloat16(ah23)),
                va.w - __bfloat162float(__high2bfloat16(ah23)));
            __nv_bfloat162 bh01 = __floats2bfloat162_rn(vb.x, vb.y);
            __nv_bfloat162 bh23 = __floats2bfloat162_rn(vb.z, vb.w);
            __nv_bfloat162 bl01 = __floats2bfloat162_rn(
                vb.x - __bfloat162float(__low2bfloat16(bh01)),
                vb.y - __bfloat162float(__high2bfloat16(bh01)));
            __nv_bfloat162 bl23 = __floats2bfloat162_rn(
                vb.z - __bfloat162float(__low2bfloat16(bh23)),
                vb.w - __bfloat162float(__high2bfloat16(bh23)));
            int o = row * FS + c;
            *(__nv_bfloat162*)&Ah[o]     = ah01;
            *(__nv_bfloat162*)&Ah[o + 2] = ah23;
            *(__nv_bfloat162*)&Al[o]     = al01;
            *(__nv_bfloat162*)&Al[o + 2] = al23;
            *(__nv_bfloat162*)&Bh[o]     = bh01;
            *(__nv_bfloat162*)&Bh[o + 2] = bh23;
            *(__nv_bfloat162*)&Bl[o]     = bl01;
            *(__nv_bfloat162*)&Bl[o + 2] = bl23;
        }
    }
    __syncthreads();

    // ---- warp tiling
    int wid = t >> 5, lane = t & 31;
    int wm = wid & 3, wn = wid >> 2;            // warp at (wm*32, wn*64)
    int g = lane >> 2, ctid = lane & 3;         // mma lane mapping
    int m_base = wm * 32, n_base = wn * 64;

    float acc[2][8][4];
#pragma unroll
    for (int mt = 0; mt < 2; mt++)
#pragma unroll
        for (int nt = 0; nt < 8; nt++)
#pragma unroll
            for (int e = 0; e < 4; e++) acc[mt][nt][e] = 0.f;

#pragma unroll
    for (int pass = 0; pass < 3; pass++) {
        const __nv_bfloat16* Asel = (pass == 2) ? Al : Ah;
        const __nv_bfloat16* Bsel = (pass == 1) ? Bl : Bh;
#pragma unroll
        for (int ks = 0; ks < 8; ks++) {
            int k0 = ks * 16;
            uint32_t af[2][4];
#pragma unroll
            for (int mt = 0; mt < 2; mt++) {
                int r = m_base + mt * 16;
                const __nv_bfloat16* ap = Asel + (size_t)(r + g) * FS + k0 + ctid * 2;
                af[mt][0] = *(const uint32_t*)ap;
                af[mt][1] = *(const uint32_t*)(ap + 8 * FS);
                af[mt][2] = *(const uint32_t*)(ap + 8);
                af[mt][3] = *(const uint32_t*)(ap + 8 * FS + 8);
            }
            uint32_t bf[8][2];
#pragma unroll
            for (int nt = 0; nt < 8; nt++) {
                int nn = n_base + nt * 8 + g;
                const __nv_bfloat16* bp = Bsel + (size_t)nn * FS + k0 + ctid * 2;
                bf[nt][0] = *(const uint32_t*)bp;
                bf[nt][1] = *(const uint32_t*)(bp + 8);
            }
#pragma unroll
            for (int mt = 0; mt < 2; mt++)
#pragma unroll
                for (int nt = 0; nt < 8; nt++)
                    mma_bf16(acc[mt][nt][0], acc[mt][nt][1], acc[mt][nt][2], acc[mt][nt][3],
                             af[mt][0], af[mt][1], af[mt][2], af[mt][3],
                             bf[nt][0], bf[nt][1]);
        }
    }

    // ---- epilogue: standardize + sigmoid, bounds-checked stores
#pragma unroll
    for (int mt = 0; mt < 2; mt++) {
#pragma unroll
        for (int nt = 0; nt < 8; nt++) {
            int gj0 = bj + n_base + nt * 8 + ctid * 2;
#pragma unroll
            for (int half = 0; half < 2; half++) {
                int gi = bi + m_base + mt * 16 + g + half * 8;
                if (gi < D_NUM) {
                    float v0 = acc[mt][nt][half * 2 + 0];
                    float v1 = acc[mt][nt][half * 2 + 1];
                    float z0 = (v0 - mu) * istd;
                    float z1 = (v1 - mu) * istd;
                    float s0 = __fdividef(1.0f, 1.0f + __expf(-z0));
                    float s1 = __fdividef(1.0f, 1.0f + __expf(-z1));
                    if (gj0 + 1 < P_NUM) {
                        *(float2*)&out[(size_t)gi * P_NUM + gj0] = make_float2(s0, s1);
                    } else if (gj0 < P_NUM) {
                        out[(size_t)gi * P_NUM + gj0] = s0;
                    }
                }
            }
        }
    }
}

// ---------------- host launcher ----------------
extern "C" void kernel_launch(void* const* d_in, const int* in_sizes, int n_in,
                              void* d_out, int out_size) {
    const float* A                 = (const float*)d_in[0];
    const float* drug_structure    = (const float*)d_in[1];
    const float* protein_structure = (const float*)d_in[2];
    const float* lin_drug_w = (const float*)d_in[3];
    const float* lin_drug_b = (const float*)d_in[4];
    const float* lin_pro_w  = (const float*)d_in[5];
    const float* lin_pro_b  = (const float*)d_in[6];
    const float* p_weight   = (const float*)d_in[7];
    const float* d_weight_i = (const float*)d_in[8];
    const float* pd_weight_p = (const float*)d_in[9];
    const float* pd_weight_d = (const float*)d_in[10];
    const float* dp_weight_p = (const float*)d_in[11];
    const float* WA_drug = (const float*)d_in[12];
    const float* BA_drug = (const float*)d_in[13];
    const float* HA_drug = (const float*)d_in[14];
    const float* WB_drug = (const float*)d_in[15];
    const float* BB_drug = (const float*)d_in[16];
    const float* HB_drug = (const float*)d_in[17];
    const float* WA_pro = (const float*)d_in[18];
    const float* BA_pro = (const float*)d_in[19];
    const float* HA_pro = (const float*)d_in[20];
    const float* WB_pro = (const float*)d_in[21];
    const float* BB_pro = (const float*)d_in[22];
    const float* HB_pro = (const float*)d_in[23];
    const float* WA_sim = (const float*)d_in[24];
    const float* BA_sim = (const float*)d_in[25];
    const float* HA_sim = (const float*)d_in[26];
    float* out = (float*)d_out;
    (void)in_sizes; (void)n_in; (void)out_size;

    void* tp;
    cudaGetSymbolAddress(&tp, g_curRT);  void* p_curRT  = tp;
    cudaGetSymbolAddress(&tp, g_barcnt); void* p_barcnt = tp;

    cudaMemsetAsync(p_curRT, 0, P_NUM * sizeof(int), 0);
    cudaMemsetAsync(p_barcnt, 0, sizeof(unsigned), 0);

    k_ell_all<<<9000, 256>>>(A);

    k_mega<<<MEGA_BLKS, MEGA_THREADS>>>(
        drug_structure, protein_structure,
        lin_drug_w, lin_drug_b, lin_pro_w, lin_pro_b,
        p_weight, d_weight_i, pd_weight_p, pd_weight_d, dp_weight_p,
        WA_drug, BA_drug, HA_drug,
        WB_drug, BB_drug, HB_drug,
        WA_pro, BA_pro, HA_pro,
        WB_pro, BB_pro, HB_pro,
        WA_sim, BA_sim, HA_sim);

    static bool attr_done = false;
    if (!attr_done) {
        cudaFuncSetAttribute(k_final_mma, cudaFuncAttributeMaxDynamicSharedMemorySize, SMEM_MMA);
        attr_done = true;
    }
    dim3 fg((P_NUM + 127) / 128, (D_NUM + 127) / 128);
    k_final_mma<<<fg, 256, SMEM_MMA>>>(out);
}

// round 13
// speedup vs baseline: 1.6951x; 1.2056x over previous
#include <cuda_runtime.h>
#include <cuda_bf16.h>
#include <math.h>
#include <stdint.h>

#define D_NUM 1500
#define P_NUM 4500
#define NTOT  6000
#define EMB   128
#define CAP_DD 64
#define CAP_PP 128
#define DB (D_NUM*EMB)
#define PB (P_NUM*EMB)
#define MEGA_BLKS 296
#define MEGA_THREADS 256

// ---------------- scratch (static __device__, no allocs) ----------------
__device__ __align__(128) int g_idx2[D_NUM*CAP_DD]; __device__ int g_len2[D_NUM];
__device__ __align__(128) int g_idx4[D_NUM*CAP_DD]; __device__ int g_len4[D_NUM];
__device__ __align__(128) int g_idx3[P_NUM*CAP_PP]; __device__ int g_len3[P_NUM];
__device__ __align__(128) int g_idxR[D_NUM*CAP_PP]; __device__ int g_lenR[D_NUM];
__device__ __align__(128) int g_idxRT[P_NUM*CAP_DD]; __device__ int g_curRT[P_NUM];

__device__ float g_dinv2[D_NUM], g_cinv2[D_NUM];
__device__ float g_dinv3[P_NUM], g_cinv3[P_NUM];
__device__ float g_dinv4[D_NUM];
__device__ float g_dinvRd[D_NUM], g_cinvRd[D_NUM];
__device__ float g_dinvRp[P_NUM], g_cinvRp[P_NUM];

__device__ __align__(128) float g_dru_str[DB], g_pro_str[PB];
__device__ __align__(128) float g_nei2[DB],    g_nei3[PB];
__device__ __align__(128) float g_emb2[DB],    g_emb3[PB],  g_emb4[DB];
__device__ __align__(128) float g_curD[DB],    g_cur3[PB];
__device__ __align__(128) float g_x2a[DB], g_x2b[DB], g_x4a[DB], g_x4b[DB];
__device__ __align__(128) float g_x3a[PB], g_x3b[PB];
__device__ __align__(128) float g_acc2[DB], g_acc3[PB], g_acc4[DB];
__device__ __align__(128) float g_one_emb[DB], g_two_all[PB], g_one_all[DB], g_two_emb[PB];
__device__ __align__(128) float g_bd1[DB],  g_bp1[PB], g_bp2[PB];
__device__ __align__(128) float g_bdx[DB],  g_bpx[PB], g_bdy[DB];
__device__ __align__(128) float g_accd[DB], g_accp[PB];
__device__ __align__(128) float g_dru_int[DB], g_pro_int[PB];
__device__ __align__(128) float g_tmpp[PB], g_Wc[EMB*EMB];
__device__ float g_wdrug[D_NUM], g_wdrel[D_NUM], g_wdsim[D_NUM];
__device__ float g_wpro[P_NUM],  g_wprel[P_NUM];
__device__ __align__(128) float g_gd[EMB*EMB], g_gp[EMB*EMB];
__device__ float g_sd[EMB], g_sp[EMB];
__device__ __align__(128) __nv_bfloat16 g_fdh[DB], g_fdl[DB];
__device__ __align__(128) __nv_bfloat16 g_fph[PB], g_fpl[PB];
__device__ float2 g_musig;
__device__ unsigned g_barcnt;
__device__ unsigned g_done;

// ---------------- ELL extraction (round-6 version, validated) --------------
__global__ void k_ell_all(const float* __restrict__ A) {
    const size_t NN = (size_t)NTOT * NTOT;
    int b = blockIdx.x;
    const float* base; int r, row0, col0, ncols, cap; int *idx, *len;
    if (b < 1500)      { base = A + 2*NN; r = b;        row0 = 0;     col0 = 0;     ncols = D_NUM; cap = CAP_DD; idx = g_idx2; len = g_len2; }
    else if (b < 6000) { base = A + 3*NN; r = b - 1500; row0 = D_NUM; col0 = D_NUM; ncols = P_NUM; cap = CAP_PP; idx = g_idx3; len = g_len3; }
    else if (b < 7500) { base = A + 4*NN; r = b - 6000; row0 = 0;     col0 = 0;     ncols = D_NUM; cap = CAP_DD; idx = g_idx4; len = g_len4; }
    else               { base = A;        r = b - 7500; row0 = 0;     col0 = D_NUM; ncols = P_NUM; cap = CAP_PP; idx = g_idxR; len = g_lenR; }

    const float4* row4 = (const float4*)(base + (size_t)(row0 + r) * NTOT + col0);
    int nv = ncols >> 2;
    __shared__ int cnt;
    __shared__ int buf[160];
    if (threadIdx.x == 0) cnt = 0;
    __syncthreads();

    float4 v[5];
#pragma unroll
    for (int u = 0; u < 5; u++) {
        int i = threadIdx.x + (u << 8);
        if (i < nv) v[u] = __ldg(&row4[i]);
    }
#pragma unroll
    for (int u = 0; u < 5; u++) {
        int i = threadIdx.x + (u << 8);
        if (i < nv) {
            int c = i << 2;
            if (v[u].x == 1.0f) { int p = atomicAdd(&cnt, 1); if (p < 160) buf[p] = c; }
            if (v[u].y == 1.0f) { int p = atomicAdd(&cnt, 1); if (p < 160) buf[p] = c + 1; }
            if (v[u].z == 1.0f) { int p = atomicAdd(&cnt, 1); if (p < 160) buf[p] = c + 2; }
            if (v[u].w == 1.0f) { int p = atomicAdd(&cnt, 1); if (p < 160) buf[p] = c + 3; }
        }
    }
    __syncthreads();
    int L = min(cnt, cap);
    if (threadIdx.x == 0) {
        len[r] = L;
        for (int i = 1; i < L; i++) {
            int t = buf[i]; int j = i - 1;
            while (j >= 0 && buf[j] > t) { buf[j + 1] = buf[j]; j--; }
            buf[j + 1] = t;
        }
    }
    __syncthreads();
    for (int i = threadIdx.x; i < L; i += blockDim.x)
        idx[(size_t)r * cap + i] = buf[i];
}

// ------------- standalone register-tiled GEMM tile (64 rows x 128 cols) ----
__device__ __forceinline__ void gemm64(const float* A, int n, int k,
    const float* W, const float* bias, float* C, float* C2, float* C3,
    int r0, float* As, float* Ws) {
    int t = threadIdx.x;
    int tx = t & 31, ty = t >> 5;
    int m0 = ty << 3, n0 = tx << 2;
    float acc[8][4];
#pragma unroll
    for (int i = 0; i < 8; i++)
#pragma unroll
        for (int j = 0; j < 4; j++) acc[i][j] = 0.f;
    for (int k0 = 0; k0 < k; k0 += 32) {
        __syncthreads();
#pragma unroll
        for (int e = t; e < 512; e += 256) {
            int rr = e >> 3, kv = e & 7;
            int gr = r0 + rr;
            float4 va = (gr < n) ? *(const float4*)&A[(size_t)gr * k + k0 + (kv << 2)]
                                 : make_float4(0.f, 0.f, 0.f, 0.f);
            As[(kv * 4 + 0) * 68 + rr] = va.x;
            As[(kv * 4 + 1) * 68 + rr] = va.y;
            As[(kv * 4 + 2) * 68 + rr] = va.z;
            As[(kv * 4 + 3) * 68 + rr] = va.w;
        }
#pragma unroll
        for (int e = t; e < 1024; e += 256) {
            int kk = e >> 5, cv = e & 31;
            *(float4*)&Ws[kk * 132 + (cv << 2)] =
                *(const float4*)&W[(size_t)(k0 + kk) * EMB + (cv << 2)];
        }
        __syncthreads();
#pragma unroll
        for (int kk = 0; kk < 32; kk++) {
            float4 a0 = *(const float4*)&As[kk * 68 + m0];
            float4 a1 = *(const float4*)&As[kk * 68 + m0 + 4];
            float4 w  = *(const float4*)&Ws[kk * 132 + n0];
            float av[8] = {a0.x, a0.y, a0.z, a0.w, a1.x, a1.y, a1.z, a1.w};
#pragma unroll
            for (int i = 0; i < 8; i++) {
                acc[i][0] += av[i] * w.x;
                acc[i][1] += av[i] * w.y;
                acc[i][2] += av[i] * w.z;
                acc[i][3] += av[i] * w.w;
            }
        }
    }
    float4 bb = bias ? *(const float4*)&bias[n0] : make_float4(0.f, 0.f, 0.f, 0.f);
#pragma unroll
    for (int i = 0; i < 8; i++) {
        int gr = r0 + m0 + i;
        if (gr < n) {
            float4 vv = make_float4(acc[i][0] + bb.x, acc[i][1] + bb.y,
                                    acc[i][2] + bb.z, acc[i][3] + bb.w);
            *(float4*)&C[(size_t)gr * EMB + n0] = vv;
            if (C2) *(float4*)&C2[(size_t)gr * EMB + n0] = vv;
            if (C3) *(float4*)&C3[(size_t)gr * EMB + n0] = vv;
        }
    }
}

// pre-mega kernel 1: feature lifts + Wc
__global__ void __launch_bounds__(256) k_lift(
    const float* __restrict__ drug_structure, const float* __restrict__ protein_structure,
    const float* __restrict__ lin_drug_w, const float* __restrict__ lin_drug_b,
    const float* __restrict__ lin_pro_w, const float* __restrict__ lin_pro_b,
    const float* __restrict__ dp_weight_p, const float* __restrict__ pd_weight_d) {
    __shared__ __align__(16) float As[32 * 68];
    __shared__ __align__(16) float Ws[32 * 132];
    int b = blockIdx.x;
    if (b < 24)       gemm64(drug_structure, D_NUM, 160, lin_drug_w, lin_drug_b, g_dru_str, 0, 0, b * 64, As, Ws);
    else if (b < 95)  gemm64(protein_structure, P_NUM, 512, lin_pro_w, lin_pro_b, g_pro_str, 0, 0, (b - 24) * 64, As, Ws);
    else              gemm64(dp_weight_p, 128, 128, pd_weight_d, 0, g_Wc, 0, 0, (b - 95) * 64, As, Ws);
}

// pre-mega kernel 2: tower-input GEMMs (+acc inits)
__global__ void __launch_bounds__(256) k_gemm2(
    const float* __restrict__ d_weight_i, const float* __restrict__ p_weight,
    const float* __restrict__ pd_weight_d, const float* __restrict__ pd_weight_p) {
    __shared__ __align__(16) float As[32 * 68];
    __shared__ __align__(16) float Ws[32 * 132];
    int b = blockIdx.x;
    if (b < 24)        gemm64(g_dru_str, D_NUM, 128, d_weight_i, 0, g_curD, g_acc2, g_acc4, b * 64, As, Ws);
    else if (b < 95)   gemm64(g_pro_str, P_NUM, 128, p_weight, 0, g_cur3, g_acc3, 0, (b - 24) * 64, As, Ws);
    else if (b < 119)  gemm64(g_dru_str, D_NUM, 128, pd_weight_d, 0, g_one_emb, g_accd, 0, (b - 95) * 64, As, Ws);
    else               gemm64(g_pro_str, P_NUM, 128, pd_weight_p, 0, g_two_emb, g_accp, 0, (b - 119) * 64, As, Ws);
}

// post-mega: 5 attention heads, register-tiled; also resets g_done
__global__ void __launch_bounds__(256) k_att(
    const float* __restrict__ WA_drug, const float* __restrict__ BA_drug, const float* __restrict__ HA_drug,
    const float* __restrict__ WA_pro,  const float* __restrict__ BA_pro,  const float* __restrict__ HA_pro,
    const float* __restrict__ WB_drug, const float* __restrict__ BB_drug, const float* __restrict__ HB_drug,
    const float* __restrict__ WB_pro,  const float* __restrict__ BB_pro,  const float* __restrict__ HB_pro,
    const float* __restrict__ WA_sim,  const float* __restrict__ BA_sim,  const float* __restrict__ HA_sim) {
    __shared__ __align__(16) float As[32 * 68];
    __shared__ __align__(16) float Ws[32 * 132];
    int b = blockIdx.x;
    if (b == 0 && threadIdx.x == 0) g_done = 0;
    const float *emb, *W, *B, *H; float* s; int n, r0;
    if (b < 24)        { emb = g_dru_int; W = WA_drug; B = BA_drug; H = HA_drug; s = g_wdrug; n = D_NUM; r0 = b * 64; }
    else if (b < 95)   { emb = g_pro_int; W = WA_pro;  B = BA_pro;  H = HA_pro;  s = g_wpro;  n = P_NUM; r0 = (b - 24) * 64; }
    else if (b < 119)  { emb = g_emb2;    W = WB_drug; B = BB_drug; H = HB_drug; s = g_wdrel; n = D_NUM; r0 = (b - 95) * 64; }
    else if (b < 190)  { emb = g_emb3;    W = WB_pro;  B = BB_pro;  H = HB_pro;  s = g_wprel; n = P_NUM; r0 = (b - 119) * 64; }
    else               { emb = g_emb4;    W = WA_sim;  B = BA_sim;  H = HA_sim;  s = g_wdsim; n = D_NUM; r0 = (b - 190) * 64; }

    int t = threadIdx.x;
    int tx = t & 31, ty = t >> 5;
    int m0 = ty << 3, n0 = tx << 2;
    float acc[8][4];
#pragma unroll
    for (int i = 0; i < 8; i++)
#pragma unroll
        for (int j = 0; j < 4; j++) acc[i][j] = 0.f;
    for (int k0 = 0; k0 < EMB; k0 += 32) {
        __syncthreads();
#pragma unroll
        for (int e = t; e < 512; e += 256) {
            int rr = e >> 3, kv = e & 7;
            int gr = r0 + rr;
            float4 va = (gr < n) ? *(const float4*)&emb[(size_t)gr * EMB + k0 + (kv << 2)]
                                 : make_float4(0.f, 0.f, 0.f, 0.f);
            As[(kv * 4 + 0) * 68 + rr] = va.x;
            As[(kv * 4 + 1) * 68 + rr] = va.y;
            As[(kv * 4 + 2) * 68 + rr] = va.z;
            As[(kv * 4 + 3) * 68 + rr] = va.w;
        }
#pragma unroll
        for (int e = t; e < 1024; e += 256) {
            int kk = e >> 5, cv = e & 31;
            *(float4*)&Ws[kk * 132 + (cv << 2)] =
                *(const float4*)&W[(size_t)(k0 + kk) * EMB + (cv << 2)];
        }
        __syncthreads();
#pragma unroll
        for (int kk = 0; kk < 32; kk++) {
            float4 a0 = *(const float4*)&As[kk * 68 + m0];
            float4 a1 = *(const float4*)&As[kk * 68 + m0 + 4];
            float4 w  = *(const float4*)&Ws[kk * 132 + n0];
            float av[8] = {a0.x, a0.y, a0.z, a0.w, a1.x, a1.y, a1.z, a1.w};
#pragma unroll
            for (int i = 0; i < 8; i++) {
                acc[i][0] += av[i] * w.x;
                acc[i][1] += av[i] * w.y;
                acc[i][2] += av[i] * w.z;
                acc[i][3] += av[i] * w.w;
            }
        }
    }
    float4 bb = *(const float4*)&B[n0];
    float4 hh = *(const float4*)&H[n0];
#pragma unroll
    for (int i = 0; i < 8; i++) {
        float p = fmaxf(acc[i][0] + bb.x, 0.f) * hh.x
                + fmaxf(acc[i][1] + bb.y, 0.f) * hh.y
                + fmaxf(acc[i][2] + bb.z, 0.f) * hh.z
                + fmaxf(acc[i][3] + bb.w, 0.f) * hh.w;
#pragma unroll
        for (int o = 16; o; o >>= 1) p += __shfl_down_sync(0xffffffffu, p, o);
        if (tx == 0) {
            int gr = r0 + m0 + i;
            if (gr < n) s[gr] = p;
        }
    }
}

// post-mega: log-softmax (5 heads)
__global__ void __launch_bounds__(1024) k_ls() {
    int head = blockIdx.x;
    float* s; int n;
    switch (head) {
        case 0: s = g_wdrug; n = D_NUM; break;
        case 1: s = g_wpro;  n = P_NUM; break;
        case 2: s = g_wdrel; n = D_NUM; break;
        case 3: s = g_wprel; n = P_NUM; break;
        default:s = g_wdsim; n = D_NUM; break;
    }
    __shared__ float sh[1024];
    int t = threadIdx.x;
    float m = -1e30f;
    for (int i = t; i < n; i += 1024) m = fmaxf(m, s[i]);
    sh[t] = m; __syncthreads();
    for (int o = 512; o; o >>= 1) { if (t < o) sh[t] = fmaxf(sh[t], sh[t + o]); __syncthreads(); }
    float mall = sh[0]; __syncthreads();
    float sum = 0.0f;
    for (int i = t; i < n; i += 1024) sum += expf(s[i] - mall);
    sh[t] = sum; __syncthreads();
    for (int o = 512; o; o >>= 1) { if (t < o) sh[t] += sh[t + o]; __syncthreads(); }
    float lse = mall + logf(sh[0]);
    for (int i = t; i < n; i += 1024) s[i] -= lse;
}

// post-mega: fused combine + bf16 hi/lo write + Gram + colsum + stats
__global__ void __launch_bounds__(256) k_comb_gram() {
    __shared__ __align__(16) float sbuf[16 * 132];
    bool isD = blockIdx.x < 32;
    int n    = isD ? D_NUM : P_NUM;
    int brel = isD ? (int)blockIdx.x : (int)blockIdx.x - 32;
    int nblk = isD ? 32 : 96;
    float* gG  = isD ? g_gd : g_gp;
    float* gS  = isD ? g_sd : g_sp;
    __nv_bfloat16* fh = isD ? g_fdh : g_fph;
    __nv_bfloat16* fl = isD ? g_fdl : g_fpl;
    int ntiles = (n + 15) >> 4;
    int tid = threadIdx.x;
    int k0 = (tid & 15) * 8, l0 = (tid >> 4) * 8;
    float accG[8][8];
#pragma unroll
    for (int i = 0; i < 8; i++)
#pragma unroll
        for (int j = 0; j < 8; j++) accG[i][j] = 0.f;
    float cs = 0.f;
    for (int t = brel; t < ntiles; t += nblk) {
        int r0 = t << 4;
        __syncthreads();
        for (int i = tid; i < 16 * 128; i += 256) {
            int rr = i >> 7, kk = i & 127;
            int gr = r0 + rr;
            float val = 0.f;
            if (gr < n) {
                size_t o = (size_t)gr * EMB + kk;
                if (isD) {
                    float wa = g_wdrug[gr], wb = g_wdrel[gr], wc = g_wdsim[gr];
                    float a = wa / (wa + wb + wc);
                    float bq = wb / (a + wb + wc);
                    float c = 1.0f - a - bq;
                    val = a * g_dru_int[o] + bq * g_emb2[o] + c * g_emb4[o];
                } else {
                    float wa = g_wpro[gr], wb = g_wprel[gr];
                    float pa = wa / (wa + wb);
                    val = pa * g_pro_int[o] + (1.0f - pa) * g_emb3[o];
                }
                __nv_bfloat16 h = __float2bfloat16(val);
                float hf = __bfloat162float(h);
                __nv_bfloat16 l = __float2bfloat16(val - hf);
                fh[o] = h;
                fl[o] = l;
                val = hf + __bfloat162float(l);   // exact value final GEMM sees
            }
            sbuf[rr * 132 + kk] = val;
        }
        __syncthreads();
#pragma unroll 4
        for (int r = 0; r < 16; r++) {
            const float* row = &sbuf[r * 132];
            float4 a0 = *(const float4*)(row + k0);
            float4 a1 = *(const float4*)(row + k0 + 4);
            float4 b0 = *(const float4*)(row + l0);
            float4 b1 = *(const float4*)(row + l0 + 4);
            float av[8] = {a0.x, a0.y, a0.z, a0.w, a1.x, a1.y, a1.z, a1.w};
            float bv[8] = {b0.x, b0.y, b0.z, b0.w, b1.x, b1.y, b1.z, b1.w};
#pragma unroll
            for (int i = 0; i < 8; i++)
#pragma unroll
                for (int j = 0; j < 8; j++) accG[i][j] += av[i] * bv[j];
        }
        if (tid < 128) {
            float c = 0.f;
            for (int r = 0; r < 16; r++) c += sbuf[r * 132 + tid];
            cs += c;
        }
    }
#pragma unroll
    for (int i = 0; i < 8; i++)
#pragma unroll
        for (int j = 0; j < 8; j++)
            atomicAdd(&gG[(k0 + i) * EMB + (l0 + j)], accG[i][j]);
    if (tid < 128) atomicAdd(&gS[tid], cs);

    // last-block stats reduction -> g_musig
    __threadfence();
    __syncthreads();
    __shared__ int slast;
    if (tid == 0) slast = (atomicAdd(&g_done, 1u) == 127u) ? 1 : 0;
    __syncthreads();
    if (slast) {
        double* sd = (double*)sbuf;
        double acc = 0.0;
        for (int i = tid; i < EMB * EMB; i += 256)
            acc += (double)g_gd[i] * (double)g_gp[i];
        sd[tid] = acc; __syncthreads();
        for (int o = 128; o; o >>= 1) { if (tid < o) sd[tid] += sd[tid + o]; __syncthreads(); }
        double sumsq = sd[0]; __syncthreads();
        double a2 = (tid < EMB) ? (double)g_sd[tid] * (double)g_sp[tid] : 0.0;
        sd[tid] = a2; __syncthreads();
        for (int o = 128; o; o >>= 1) { if (tid < o) sd[tid] += sd[tid + o]; __syncthreads(); }
        if (tid == 0) {
            double sumy = sd[0];
            const double nn = (double)D_NUM * (double)P_NUM;
            double mean = sumy / nn;
            double var = (sumsq - sumy * sumy / nn) / (nn - 1.0);
            g_musig = make_float2((float)mean, (float)(1.0 / sqrt(var)));
        }
    }
}

// ------------- grid barrier (round-6 monotonic, known-good) ----------------
__device__ __forceinline__ void gsync(unsigned& target) {
    __syncthreads();
    if (threadIdx.x == 0) {
        __threadfence();
        atomicAdd(&g_barcnt, 1u);
        target += gridDim.x;
        unsigned v;
        do {
            asm volatile("ld.acquire.gpu.global.u32 %0, [%1];"
                         : "=r"(v) : "l"(&g_barcnt) : "memory");
        } while (v < target);
    }
    __syncthreads();
}

// ---------------- mega helpers (round-6, unchanged) ----------------
__device__ void gemm_dev(const float* A, int n, int k,
                         const float* W, bool wext, const float* bias,
                         float* C, float* C2, float* C3, float* sA) {
    int ntiles = (n + 15) >> 4;
    int col = threadIdx.x & 127;
    int half = threadIdx.x >> 7;
    for (int t = blockIdx.x; t < ntiles; t += gridDim.x) {
        int r0 = t << 4;
        __syncthreads();
        for (int i = threadIdx.x; i < (k << 4); i += MEGA_THREADS) {
            int rr = i / k, kk = i - rr * k;
            int gr = r0 + rr;
            sA[rr * k + kk] = (gr < n) ? A[(size_t)gr * k + kk] : 0.0f;
        }
        __syncthreads();
        float acc[8];
#pragma unroll
        for (int rr = 0; rr < 8; rr++) acc[rr] = 0.0f;
        const float* sAr = sA + (half << 3) * k;
        for (int kk = 0; kk < k; kk++) {
            float w = wext ? __ldg(&W[(size_t)kk * EMB + col]) : W[(size_t)kk * EMB + col];
#pragma unroll
            for (int rr = 0; rr < 8; rr++) acc[rr] += sAr[rr * k + kk] * w;
        }
        float b = bias ? __ldg(bias + col) : 0.0f;
#pragma unroll
        for (int rr = 0; rr < 8; rr++) {
            int gr = r0 + (half << 3) + rr;
            if (gr < n) {
                float v = acc[rr] + b;
                size_t o = (size_t)gr * EMB + col;
                C[o] = v;
                if (C2) C2[o] = v;
                if (C3) C3[o] = v;
            }
        }
    }
}

__device__ void spmm_dev(const int* idx, const int* len, int cap,
                         const float* rs, const float* cs, const float* x,
                         float* out, float* acc, float* fin, float fscale,
                         const float* mixb, float* mixo, int n) {
    int nw = (gridDim.x * blockDim.x) >> 5;
    int gw = (blockIdx.x * blockDim.x + threadIdx.x) >> 5;
    int lane = threadIdx.x & 31;
    const float4* x4 = (const float4*)x;
    for (int r = gw; r < n; r += nw) {
        int L = len[r];
        float4 s = make_float4(0.f, 0.f, 0.f, 0.f);
        for (int p0 = 0; p0 < L; p0 += 32) {
            int j = 0; float f = 0.f;
            if (p0 + lane < L) {
                j = idx[(size_t)r * cap + p0 + lane];
                f = cs ? cs[j] : 1.0f;
            }
            int m = min(32, L - p0);
            int q = 0;
            for (; q + 4 <= m; q += 4) {
                int j0 = __shfl_sync(0xffffffffu, j, q);
                int j1 = __shfl_sync(0xffffffffu, j, q + 1);
                int j2 = __shfl_sync(0xffffffffu, j, q + 2);
                int j3 = __shfl_sync(0xffffffffu, j, q + 3);
                float f0 = __shfl_sync(0xffffffffu, f, q);
                float f1 = __shfl_sync(0xffffffffu, f, q + 1);
                float f2 = __shfl_sync(0xffffffffu, f, q + 2);
                float f3 = __shfl_sync(0xffffffffu, f, q + 3);
                float4 v0 = x4[(size_t)j0 * 32 + lane];
                float4 v1 = x4[(size_t)j1 * 32 + lane];
                float4 v2 = x4[(size_t)j2 * 32 + lane];
                float4 v3 = x4[(size_t)j3 * 32 + lane];
                s.x += f0 * v0.x + f1 * v1.x + f2 * v2.x + f3 * v3.x;
                s.y += f0 * v0.y + f1 * v1.y + f2 * v2.y + f3 * v3.y;
                s.z += f0 * v0.z + f1 * v1.z + f2 * v2.z + f3 * v3.z;
                s.w += f0 * v0.w + f1 * v1.w + f2 * v2.w + f3 * v3.w;
            }
            for (; q < m; q++) {
                int j0 = __shfl_sync(0xffffffffu, j, q);
                float f0 = __shfl_sync(0xffffffffu, f, q);
                float4 v0 = x4[(size_t)j0 * 32 + lane];
                s.x += f0 * v0.x; s.y += f0 * v0.y;
                s.z += f0 * v0.z; s.w += f0 * v0.w;
            }
        }
        float rr = rs[r];
        s.x *= rr; s.y *= rr; s.z *= rr; s.w *= rr;
        size_t o = (size_t)r * 32 + lane;
        if (out) ((float4*)out)[o] = s;
        if (acc) {
            float4 a = ((const float4*)acc)[o];
            a.x += s.x; a.y += s.y; a.z += s.z; a.w += s.w;
            ((float4*)acc)[o] = a;
            if (fin) {
                float4 ff = make_float4(a.x * fscale, a.y * fscale, a.z * fscale, a.w * fscale);
                ((float4*)fin)[o] = ff;
            }
        }
        if (mixo) {
            float4 mb = ((const float4*)mixb)[o];
            float4 mo = make_float4(0.8f * mb.x + 0.2f * s.x, 0.8f * mb.y + 0.2f * s.y,
                                    0.8f * mb.z + 0.2f * s.z, 0.8f * mb.w + 0.2f * s.w);
            ((float4*)mixo)[o] = mo;
        }
    }
}

// ---------------- the megakernel: SpMM core only (6 barriers) --------------
__global__ void __launch_bounds__(MEGA_THREADS, 2) k_mega() {
    __shared__ __align__(16) float sbuf[16 * 512];
    unsigned target = 0;

    // ---- M1: build R^T + len-based scales + zero gram accums
    {
        int nw = (gridDim.x * blockDim.x) >> 5;
        int gw = (blockIdx.x * blockDim.x + threadIdx.x) >> 5;
        int lane = threadIdx.x & 31;
        for (int r = gw; r < D_NUM; r += nw) {
            int L = g_lenR[r];
            for (int p = lane; p < L; p += 32) {
                int c = g_idxR[r * CAP_PP + p];
                int pos = atomicAdd(&g_curRT[c], 1);
                if (pos < CAP_DD) g_idxRT[c * CAP_DD + pos] = r;
            }
        }
        int i = blockIdx.x * blockDim.x + threadIdx.x;
        if (i < D_NUM) {
            int d;
            d = g_len2[i]; g_dinv2[i] = d > 0 ? rsqrtf((float)d) : 0.0f;
                           g_cinv2[i] = d > 0 ? 1.0f / (float)d : 0.0f;
            d = g_len4[i]; g_dinv4[i] = d > 0 ? rsqrtf((float)d) : 0.0f;
            d = g_lenR[i]; g_dinvRd[i] = d > 0 ? rsqrtf((float)d) : 0.0f;
                           g_cinvRd[i] = d > 0 ? 1.0f / (float)d : 0.0f;
        }
        if (i < P_NUM) {
            int d = g_len3[i];
            g_dinv3[i] = d > 0 ? rsqrtf((float)d) : 0.0f;
            g_cinv3[i] = d > 0 ? 1.0f / (float)d : 0.0f;
        }
        int stride = gridDim.x * blockDim.x;
        for (int q = i; q < EMB * EMB; q += stride) { g_gd[q] = 0.f; g_gp[q] = 0.f; }
        if (i < EMB) { g_sd[i] = 0.f; g_sp[i] = 0.f; }
    }
    gsync(target);

    // ---- M2: sort R^T + Rp scales; nei spmms; GCN layer 1
    {
        int i = blockIdx.x * blockDim.x + threadIdx.x;
        if (i < P_NUM) {
            int L = min(g_curRT[i], CAP_DD);
            g_curRT[i] = L;
            int* a = &g_idxRT[i * CAP_DD];
            for (int q = 1; q < L; q++) {
                int v = a[q]; int jj = q - 1;
                while (jj >= 0 && a[jj] > v) { a[jj + 1] = a[jj]; jj--; }
                a[jj + 1] = v;
            }
            g_dinvRp[i] = L > 0 ? rsqrtf((float)L) : 0.0f;
            g_cinvRp[i] = L > 0 ? 1.0f / (float)L : 0.0f;
        }
    }
    spmm_dev(g_idx2, g_len2, CAP_DD, g_cinv2, 0, g_dru_str, g_nei2, 0, 0, 0.f, 0, 0, D_NUM);
    spmm_dev(g_idx3, g_len3, CAP_PP, g_cinv3, 0, g_pro_str, g_nei3, 0, 0, 0.f, 0, 0, P_NUM);
    spmm_dev(g_idx2, g_len2, CAP_DD, g_dinv2, g_dinv2, g_curD, g_x2a, g_acc2, 0, 0.f, 0, 0, D_NUM);
    spmm_dev(g_idx3, g_len3, CAP_PP, g_dinv3, g_dinv3, g_cur3, g_x3a, g_acc3, 0, 0.f, 0, 0, P_NUM);
    spmm_dev(g_idx4, g_len4, CAP_DD, g_dinv4, g_dinv4, g_curD, g_x4a, g_acc4, 0, 0.f, 0, 0, D_NUM);
    gsync(target);

    // ---- M3: GCN layer 2; cross-domain mixes; bp1; bdx
    spmm_dev(g_idx2, g_len2, CAP_DD, g_dinv2, g_dinv2, g_x2a, g_x2b, g_acc2, 0, 0.f, 0, 0, D_NUM);
    spmm_dev(g_idx3, g_len3, CAP_PP, g_dinv3, g_dinv3, g_x3a, g_x3b, g_acc3, 0, 0.f, 0, 0, P_NUM);
    spmm_dev(g_idx4, g_len4, CAP_DD, g_dinv4, g_dinv4, g_x4a, g_x4b, g_acc4, 0, 0.f, 0, 0, D_NUM);
    spmm_dev(g_idxR, g_lenR, CAP_PP, g_cinvRd, 0, g_nei3, 0, 0, 0, 0.f, g_dru_str, g_one_all, D_NUM);
    spmm_dev(g_idxRT, g_curRT, CAP_DD, g_cinvRp, 0, g_nei2, 0, 0, 0, 0.f, g_pro_str, g_tmpp, P_NUM);
    spmm_dev(g_idxRT, g_curRT, CAP_DD, g_dinvRp, g_dinvRd, g_one_emb, g_bp1, 0, 0, 0.f, 0, 0, P_NUM);
    spmm_dev(g_idxR, g_lenR, CAP_PP, g_dinvRd, g_dinvRp, g_two_emb, g_bdx, 0, 0, 0.f, 0, 0, D_NUM);
    gsync(target);

    // ---- M4: GCN layer 3 finalize; two_all GEMM; bpx(+accp); accp+=S^T bdx; accd+=S bp1
    spmm_dev(g_idx2, g_len2, CAP_DD, g_dinv2, g_dinv2, g_x2b, 0, g_acc2, g_emb2, 0.25f, 0, 0, D_NUM);
    spmm_dev(g_idx3, g_len3, CAP_PP, g_dinv3, g_dinv3, g_x3b, 0, g_acc3, g_emb3, 0.25f, 0, 0, P_NUM);
    spmm_dev(g_idx4, g_len4, CAP_DD, g_dinv4, g_dinv4, g_x4b, 0, g_acc4, g_emb4, 0.25f, 0, 0, D_NUM);
    gemm_dev(g_tmpp, P_NUM, 128, g_Wc, false, 0, g_two_all, 0, 0, sbuf);
    spmm_dev(g_idxRT, g_curRT, CAP_DD, g_dinvRp, g_dinvRd, g_one_all, g_bpx, g_accp, 0, 0.f, 0, 0, P_NUM);
    spmm_dev(g_idxRT, g_curRT, CAP_DD, g_dinvRp, g_dinvRd, g_bdx, 0, g_accp, 0, 0.f, 0, 0, P_NUM);
    spmm_dev(g_idxR, g_lenR, CAP_PP, g_dinvRd, g_dinvRp, g_bp1, 0, g_accd, 0, 0.f, 0, 0, D_NUM);
    gsync(target);

    // ---- M5: bd1 = S two_all (+accd); bdy = S bpx
    spmm_dev(g_idxR, g_lenR, CAP_PP, g_dinvRd, g_dinvRp, g_two_all, g_bd1, g_accd, 0, 0.f, 0, 0, D_NUM);
    spmm_dev(g_idxR, g_lenR, CAP_PP, g_dinvRd, g_dinvRp, g_bpx, g_bdy, 0, 0, 0.f, 0, 0, D_NUM);
    gsync(target);

    // ---- M6: bp2 = S^T bd1; pro_int finalize (accp += S^T bdy, *0.25)
    spmm_dev(g_idxRT, g_curRT, CAP_DD, g_dinvRp, g_dinvRd, g_bd1, g_bp2, 0, 0, 0.f, 0, 0, P_NUM);
    spmm_dev(g_idxRT, g_curRT, CAP_DD, g_dinvRp, g_dinvRd, g_bdy, 0, g_accp, g_pro_int, 0.25f, 0, 0, P_NUM);
    gsync(target);

    // ---- M7: dru_int finalize (accd += S bp2, *0.25)
    spmm_dev(g_idxR, g_lenR, CAP_PP, g_dinvRd, g_dinvRp, g_bp2, 0, g_accd, g_dru_int, 0.25f, 0, 0, D_NUM);
}

// ====== final GEMM: warp-level bf16 mma.sync, loads precomputed hi/lo ======
#define FS 136
#define SM_AH_OFF 0
#define SM_AL_OFF (128*FS*2)
#define SM_BH_OFF (2*128*FS*2)
#define SM_BL_OFF (3*128*FS*2)
#define SMEM_MMA  (4*128*FS*2)

__device__ __forceinline__ void mma_bf16(
    float& c0, float& c1, float& c2, float& c3,
    uint32_t a0, uint32_t a1, uint32_t a2, uint32_t a3,
    uint32_t b0, uint32_t b1) {
    asm volatile(
        "mma.sync.aligned.m16n8k16.row.col.f32.bf16.bf16.f32 "
        "{%0,%1,%2,%3}, {%4,%5,%6,%7}, {%8,%9}, {%0,%1,%2,%3};"
        : "+f"(c0), "+f"(c1), "+f"(c2), "+f"(c3)
        : "r"(a0), "r"(a1), "r"(a2), "r"(a3), "r"(b0), "r"(b1));
}

__global__ void __launch_bounds__(256) k_final_mma(float* __restrict__ out) {
    extern __shared__ __align__(16) char smem[];
    __nv_bfloat16* Ah = (__nv_bfloat16*)(smem + SM_AH_OFF);
    __nv_bfloat16* Al = (__nv_bfloat16*)(smem + SM_AL_OFF);
    __nv_bfloat16* Bh = (__nv_bfloat16*)(smem + SM_BH_OFF);
    __nv_bfloat16* Bl = (__nv_bfloat16*)(smem + SM_BL_OFF);

    int t = threadIdx.x;
    int bi = blockIdx.y * 128, bj = blockIdx.x * 128;
    float2 ms = g_musig;
    float mu = ms.x, istd = ms.y;

    // ---- stage: copy precomputed bf16 hi/lo rows into smem
    {
        int row = t >> 1;
        int c0 = (t & 1) * 64;
        int gi = bi + row, gj = bj + row;
        const uint4 z = make_uint4(0u, 0u, 0u, 0u);
        const uint4* sah = (gi < D_NUM) ? (const uint4*)&g_fdh[(size_t)gi * EMB + c0] : 0;
        const uint4* sal = (gi < D_NUM) ? (const uint4*)&g_fdl[(size_t)gi * EMB + c0] : 0;
        const uint4* sbh = (gj < P_NUM) ? (const uint4*)&g_fph[(size_t)gj * EMB + c0] : 0;
        const uint4* sbl = (gj < P_NUM) ? (const uint4*)&g_fpl[(size_t)gj * EMB + c0] : 0;
        int o = row * FS + c0;
#pragma unroll
        for (int q = 0; q < 8; q++) {
            *(uint4*)&Ah[o + q * 8] = sah ? __ldg(&sah[q]) : z;
            *(uint4*)&Al[o + q * 8] = sal ? __ldg(&sal[q]) : z;
            *(uint4*)&Bh[o + q * 8] = sbh ? __ldg(&sbh[q]) : z;
            *(uint4*)&Bl[o + q * 8] = sbl ? __ldg(&sbl[q]) : z;
        }
    }
    __syncthreads();

    // ---- warp tiling
    int wid = t >> 5, lane = t & 31;
    int wm = wid & 3, wn = wid >> 2;
    int g = lane >> 2, ctid = lane & 3;
    int m_base = wm * 32, n_base = wn * 64;

    float acc[2][8][4];
#pragma unroll
    for (int mt = 0; mt < 2; mt++)
#pragma unroll
        for (int nt = 0; nt < 8; nt++)
#pragma unroll
            for (int e = 0; e < 4; e++) acc[mt][nt][e] = 0.f;

#pragma unroll
    for (int pass = 0; pass < 3; pass++) {
        const __nv_bfloat16* Asel = (pass == 2) ? Al : Ah;
        const __nv_bfloat16* Bsel = (pass == 1) ? Bl : Bh;
#pragma unroll
        for (int ks = 0; ks < 8; ks++) {
            int k0 = ks * 16;
            uint32_t af[2][4];
#pragma unroll
            for (int mt = 0; mt < 2; mt++) {
                int r = m_base + mt * 16;
                const __nv_bfloat16* ap = Asel + (size_t)(r + g) * FS + k0 + ctid * 2;
                af[mt][0] = *(const uint32_t*)ap;
                af[mt][1] = *(const uint32_t*)(ap + 8 * FS);
                af[mt][2] = *(const uint32_t*)(ap + 8);
                af[mt][3] = *(const uint32_t*)(ap + 8 * FS + 8);
            }
            uint32_t bf[8][2];
#pragma unroll
            for (int nt = 0; nt < 8; nt++) {
                int nn = n_base + nt * 8 + g;
                const __nv_bfloat16* bp = Bsel + (size_t)nn * FS + k0 + ctid * 2;
                bf[nt][0] = *(const uint32_t*)bp;
                bf[nt][1] = *(const uint32_t*)(bp + 8);
            }
#pragma unroll
            for (int mt = 0; mt < 2; mt++)
#pragma unroll
                for (int nt = 0; nt < 8; nt++)
                    mma_bf16(acc[mt][nt][0], acc[mt][nt][1], acc[mt][nt][2], acc[mt][nt][3],
                             af[mt][0], af[mt][1], af[mt][2], af[mt][3],
                             bf[nt][0], bf[nt][1]);
        }
    }

    // ---- epilogue: standardize + sigmoid
#pragma unroll
    for (int mt = 0; mt < 2; mt++) {
#pragma unroll
        for (int nt = 0; nt < 8; nt++) {
            int gj0 = bj + n_base + nt * 8 + ctid * 2;
#pragma unroll
            for (int half = 0; half < 2; half++) {
                int gi = bi + m_base + mt * 16 + g + half * 8;
                if (gi < D_NUM) {
                    float v0 = acc[mt][nt][half * 2 + 0];
                    float v1 = acc[mt][nt][half * 2 + 1];
                    float z0 = (v0 - mu) * istd;
                    float z1 = (v1 - mu) * istd;
                    float s0 = __fdividef(1.0f, 1.0f + __expf(-z0));
                    float s1 = __fdividef(1.0f, 1.0f + __expf(-z1));
                    if (gj0 + 1 < P_NUM) {
                        *(float2*)&out[(size_t)gi * P_NUM + gj0] = make_float2(s0, s1);
                    } else if (gj0 < P_NUM) {
                        out[(size_t)gi * P_NUM + gj0] = s0;
                    }
                }
            }
        }
    }
}

// ---------------- host launcher ----------------
extern "C" void kernel_launch(void* const* d_in, const int* in_sizes, int n_in,
                              void* d_out, int out_size) {
    const float* A                 = (const float*)d_in[0];
    const float* drug_structure    = (const float*)d_in[1];
    const float* protein_structure = (const float*)d_in[2];
    const float* lin_drug_w = (const float*)d_in[3];
    const float* lin_drug_b = (const float*)d_in[4];
    const float* lin_pro_w  = (const float*)d_in[5];
    const float* lin_pro_b  = (const float*)d_in[6];
    const float* p_weight   = (const float*)d_in[7];
    const float* d_weight_i = (const float*)d_in[8];
    const float* pd_weight_p = (const float*)d_in[9];
    const float* pd_weight_d = (const float*)d_in[10];
    const float* dp_weight_p = (const float*)d_in[11];
    const float* WA_drug = (const float*)d_in[12];
    const float* BA_drug = (const float*)d_in[13];
    const float* HA_drug = (const float*)d_in[14];
    const float* WB_drug = (const float*)d_in[15];
    const float* BB_drug = (const float*)d_in[16];
    const float* HB_drug = (const float*)d_in[17];
    const float* WA_pro = (const float*)d_in[18];
    const float* BA_pro = (const float*)d_in[19];
    const float* HA_pro = (const float*)d_in[20];
    const float* WB_pro = (const float*)d_in[21];
    const float* BB_pro = (const float*)d_in[22];
    const float* HB_pro = (const float*)d_in[23];
    const float* WA_sim = (const float*)d_in[24];
    const float* BA_sim = (const float*)d_in[25];
    const float* HA_sim = (const float*)d_in[26];
    float* out = (float*)d_out;
    (void)in_sizes; (void)n_in; (void)out_size;

    void* tp;
    cudaGetSymbolAddress(&tp, g_curRT);  void* p_curRT  = tp;
    cudaGetSymbolAddress(&tp, g_barcnt); void* p_barcnt = tp;

    cudaMemsetAsync(p_curRT, 0, P_NUM * sizeof(int), 0);
    cudaMemsetAsync(p_barcnt, 0, sizeof(unsigned), 0);

    k_ell_all<<<9000, 256>>>(A);
    k_lift<<<97, 256>>>(drug_structure, protein_structure,
                        lin_drug_w, lin_drug_b, lin_pro_w, lin_pro_b,
                        dp_weight_p, pd_weight_d);
    k_gemm2<<<190, 256>>>(d_weight_i, p_weight, pd_weight_d, pd_weight_p);
    k_mega<<<MEGA_BLKS, MEGA_THREADS>>>();
    k_att<<<214, 256>>>(WA_drug, BA_drug, HA_drug, WA_pro, BA_pro, HA_pro,
                        WB_drug, BB_drug, HB_drug, WB_pro, BB_pro, HB_pro,
                        WA_sim, BA_sim, HA_sim);
    k_ls<<<5, 1024>>>();
    k_comb_gram<<<128, 256>>>();

    static bool attr_done = false;
    if (!attr_done) {
        cudaFuncSetAttribute(k_final_mma, cudaFuncAttributeMaxDynamicSharedMemorySize, SMEM_MMA);
        attr_done = true;
    }
    dim3 fg((P_NUM + 127) / 128, (D_NUM + 127) / 128);
    k_final_mma<<<fg, 256, SMEM_MMA>>>(out);
}

// round 16
// speedup vs baseline: 1.8588x; 1.0966x over previous
#include <cuda_runtime.h>
#include <cuda_bf16.h>
#include <math.h>
#include <stdint.h>

#define D_NUM 1500
#define P_NUM 4500
#define NTOT  6000
#define EMB   128
#define CAP_DD 64
#define CAP_PP 128
#define DB (D_NUM*EMB)
#define PB (P_NUM*EMB)
#define DBK 188   // ceil(D_NUM/8)
#define PBK 563   // ceil(P_NUM/8)

// ---------------- scratch (static __device__, no allocs) ----------------
__device__ __align__(128) int g_idx2[D_NUM*CAP_DD]; __device__ int g_len2[D_NUM];
__device__ __align__(128) int g_idx4[D_NUM*CAP_DD]; __device__ int g_len4[D_NUM];
__device__ __align__(128) int g_idx3[P_NUM*CAP_PP]; __device__ int g_len3[P_NUM];
__device__ __align__(128) int g_idxR[D_NUM*CAP_PP]; __device__ int g_lenR[D_NUM];
__device__ __align__(128) int g_idxRT[P_NUM*CAP_DD]; __device__ int g_curRT[P_NUM];

__device__ float g_dinv2[D_NUM], g_cinv2[D_NUM];
__device__ float g_dinv3[P_NUM], g_cinv3[P_NUM];
__device__ float g_dinv4[D_NUM];
__device__ float g_dinvRd[D_NUM], g_cinvRd[D_NUM];
__device__ float g_dinvRp[P_NUM], g_cinvRp[P_NUM];

__device__ __align__(128) float g_dru_str[DB], g_pro_str[PB];
__device__ __align__(128) float g_nei2[DB],    g_nei3[PB];
__device__ __align__(128) float g_emb2[DB],    g_emb3[PB],  g_emb4[DB];
__device__ __align__(128) float g_curD[DB],    g_cur3[PB];
__device__ __align__(128) float g_x2a[DB], g_x2b[DB], g_x4a[DB], g_x4b[DB];
__device__ __align__(128) float g_x3a[PB], g_x3b[PB];
__device__ __align__(128) float g_acc2[DB], g_acc3[PB], g_acc4[DB];
__device__ __align__(128) float g_one_emb[DB], g_two_all[PB], g_one_all[DB], g_two_emb[PB];
__device__ __align__(128) float g_bd1[DB],  g_bp1[PB], g_bp2[PB];
__device__ __align__(128) float g_bdx[DB],  g_bpx[PB], g_bdy[DB];
__device__ __align__(128) float g_accd[DB], g_accp[PB];
__device__ __align__(128) float g_dru_int[DB], g_pro_int[PB];
__device__ __align__(128) float g_tmpp[PB], g_Wc[EMB*EMB];
__device__ float g_wdrug[D_NUM], g_wdrel[D_NUM], g_wdsim[D_NUM];
__device__ float g_wpro[P_NUM],  g_wprel[P_NUM];
__device__ __align__(128) float g_gd[EMB*EMB], g_gp[EMB*EMB];
__device__ float g_sd[EMB], g_sp[EMB];
__device__ __align__(128) __nv_bfloat16 g_fdh[DB], g_fdl[DB];
__device__ __align__(128) __nv_bfloat16 g_fph[PB], g_fpl[PB];
__device__ float2 g_musig;
__device__ unsigned g_done;

// ---------------- ELL extraction (validated round-6 version) ---------------
__global__ void k_ell_all(const float* __restrict__ A) {
    const size_t NN = (size_t)NTOT * NTOT;
    int b = blockIdx.x;
    const float* base; int r, row0, col0, ncols, cap; int *idx, *len;
    if (b < 1500)      { base = A + 2*NN; r = b;        row0 = 0;     col0 = 0;     ncols = D_NUM; cap = CAP_DD; idx = g_idx2; len = g_len2; }
    else if (b < 6000) { base = A + 3*NN; r = b - 1500; row0 = D_NUM; col0 = D_NUM; ncols = P_NUM; cap = CAP_PP; idx = g_idx3; len = g_len3; }
    else if (b < 7500) { base = A + 4*NN; r = b - 6000; row0 = 0;     col0 = 0;     ncols = D_NUM; cap = CAP_DD; idx = g_idx4; len = g_len4; }
    else               { base = A;        r = b - 7500; row0 = 0;     col0 = D_NUM; ncols = P_NUM; cap = CAP_PP; idx = g_idxR; len = g_lenR; }

    const float4* row4 = (const float4*)(base + (size_t)(row0 + r) * NTOT + col0);
    int nv = ncols >> 2;
    __shared__ int cnt;
    __shared__ int buf[160];
    if (threadIdx.x == 0) cnt = 0;
    __syncthreads();

    float4 v[5];
#pragma unroll
    for (int u = 0; u < 5; u++) {
        int i = threadIdx.x + (u << 8);
        if (i < nv) v[u] = __ldg(&row4[i]);
    }
#pragma unroll
    for (int u = 0; u < 5; u++) {
        int i = threadIdx.x + (u << 8);
        if (i < nv) {
            int c = i << 2;
            if (v[u].x == 1.0f) { int p = atomicAdd(&cnt, 1); if (p < 160) buf[p] = c; }
            if (v[u].y == 1.0f) { int p = atomicAdd(&cnt, 1); if (p < 160) buf[p] = c + 1; }
            if (v[u].z == 1.0f) { int p = atomicAdd(&cnt, 1); if (p < 160) buf[p] = c + 2; }
            if (v[u].w == 1.0f) { int p = atomicAdd(&cnt, 1); if (p < 160) buf[p] = c + 3; }
        }
    }
    __syncthreads();
    int L = min(cnt, cap);
    if (threadIdx.x == 0) {
        len[r] = L;
        for (int i = 1; i < L; i++) {
            int t = buf[i]; int j = i - 1;
            while (j >= 0 && buf[j] > t) { buf[j + 1] = buf[j]; j--; }
            buf[j + 1] = t;
        }
    }
    __syncthreads();
    for (int i = threadIdx.x; i < L; i += blockDim.x)
        idx[(size_t)r * cap + i] = buf[i];
}

// ------------- register-tiled GEMM tile (64 rows x 128 cols) ---------------
__device__ __forceinline__ void gemm64(const float* A, int n, int k,
    const float* W, const float* bias, float* C, float* C2, float* C3,
    int r0, float* As, float* Ws) {
    int t = threadIdx.x;
    int tx = t & 31, ty = t >> 5;
    int m0 = ty << 3, n0 = tx << 2;
    float acc[8][4];
#pragma unroll
    for (int i = 0; i < 8; i++)
#pragma unroll
        for (int j = 0; j < 4; j++) acc[i][j] = 0.f;
    for (int k0 = 0; k0 < k; k0 += 32) {
        __syncthreads();
#pragma unroll
        for (int e = t; e < 512; e += 256) {
            int rr = e >> 3, kv = e & 7;
            int gr = r0 + rr;
            float4 va = (gr < n) ? *(const float4*)&A[(size_t)gr * k + k0 + (kv << 2)]
                                 : make_float4(0.f, 0.f, 0.f, 0.f);
            As[(kv * 4 + 0) * 68 + rr] = va.x;
            As[(kv * 4 + 1) * 68 + rr] = va.y;
            As[(kv * 4 + 2) * 68 + rr] = va.z;
            As[(kv * 4 + 3) * 68 + rr] = va.w;
        }
#pragma unroll
        for (int e = t; e < 1024; e += 256) {
            int kk = e >> 5, cv = e & 31;
            *(float4*)&Ws[kk * 132 + (cv << 2)] =
                *(const float4*)&W[(size_t)(k0 + kk) * EMB + (cv << 2)];
        }
        __syncthreads();
#pragma unroll
        for (int kk = 0; kk < 32; kk++) {
            float4 a0 = *(const float4*)&As[kk * 68 + m0];
            float4 a1 = *(const float4*)&As[kk * 68 + m0 + 4];
            float4 w  = *(const float4*)&Ws[kk * 132 + n0];
            float av[8] = {a0.x, a0.y, a0.z, a0.w, a1.x, a1.y, a1.z, a1.w};
#pragma unroll
            for (int i = 0; i < 8; i++) {
                acc[i][0] += av[i] * w.x;
                acc[i][1] += av[i] * w.y;
                acc[i][2] += av[i] * w.z;
                acc[i][3] += av[i] * w.w;
            }
        }
    }
    float4 bb = bias ? *(const float4*)&bias[n0] : make_float4(0.f, 0.f, 0.f, 0.f);
#pragma unroll
    for (int i = 0; i < 8; i++) {
        int gr = r0 + m0 + i;
        if (gr < n) {
            float4 vv = make_float4(acc[i][0] + bb.x, acc[i][1] + bb.y,
                                    acc[i][2] + bb.z, acc[i][3] + bb.w);
            *(float4*)&C[(size_t)gr * EMB + n0] = vv;
            if (C2) *(float4*)&C2[(size_t)gr * EMB + n0] = vv;
            if (C3) *(float4*)&C3[(size_t)gr * EMB + n0] = vv;
        }
    }
}

__global__ void __launch_bounds__(256) k_lift(
    const float* __restrict__ drug_structure, const float* __restrict__ protein_structure,
    const float* __restrict__ lin_drug_w, const float* __restrict__ lin_drug_b,
    const float* __restrict__ lin_pro_w, const float* __restrict__ lin_pro_b,
    const float* __restrict__ dp_weight_p, const float* __restrict__ pd_weight_d) {
    __shared__ __align__(16) float As[32 * 68];
    __shared__ __align__(16) float Ws[32 * 132];
    int b = blockIdx.x;
    if (b < 24)       gemm64(drug_structure, D_NUM, 160, lin_drug_w, lin_drug_b, g_dru_str, 0, 0, b * 64, As, Ws);
    else if (b < 95)  gemm64(protein_structure, P_NUM, 512, lin_pro_w, lin_pro_b, g_pro_str, 0, 0, (b - 24) * 64, As, Ws);
    else              gemm64(dp_weight_p, 128, 128, pd_weight_d, 0, g_Wc, 0, 0, (b - 95) * 64, As, Ws);
}

__global__ void __launch_bounds__(256) k_gemm2(
    const float* __restrict__ d_weight_i, const float* __restrict__ p_weight,
    const float* __restrict__ pd_weight_d, const float* __restrict__ pd_weight_p) {
    __shared__ __align__(16) float As[32 * 68];
    __shared__ __align__(16) float Ws[32 * 132];
    int b = blockIdx.x;
    if (b < 24)        gemm64(g_dru_str, D_NUM, 128, d_weight_i, 0, g_curD, g_acc2, g_acc4, b * 64, As, Ws);
    else if (b < 95)   gemm64(g_pro_str, P_NUM, 128, p_weight, 0, g_cur3, g_acc3, 0, (b - 24) * 64, As, Ws);
    else if (b < 119)  gemm64(g_dru_str, D_NUM, 128, pd_weight_d, 0, g_one_emb, g_accd, 0, (b - 95) * 64, As, Ws);
    else               gemm64(g_pro_str, P_NUM, 128, pd_weight_p, 0, g_two_emb, g_accp, 0, (b - 119) * 64, As, Ws);
}

// ---------------- warp-per-row SpMM body ----------------
__device__ __forceinline__ void spmm_row(
    const int* __restrict__ idx, const int* __restrict__ len, int cap,
    const float* __restrict__ rs, const float* __restrict__ cs,
    const float* __restrict__ x, float* out, float* acc, float* fin,
    float fscale, const float* mixb, float* mixo, int n, int r) {
    if (r >= n) return;
    int lane = threadIdx.x & 31;
    const float4* x4 = (const float4*)x;
    int L = len[r];
    float4 s = make_float4(0.f, 0.f, 0.f, 0.f);
    for (int p0 = 0; p0 < L; p0 += 32) {
        int j = 0; float f = 0.f;
        if (p0 + lane < L) {
            j = idx[(size_t)r * cap + p0 + lane];
            f = cs ? cs[j] : 1.0f;
        }
        int m = min(32, L - p0);
        int q = 0;
        for (; q + 4 <= m; q += 4) {
            int j0 = __shfl_sync(0xffffffffu, j, q);
            int j1 = __shfl_sync(0xffffffffu, j, q + 1);
            int j2 = __shfl_sync(0xffffffffu, j, q + 2);
            int j3 = __shfl_sync(0xffffffffu, j, q + 3);
            float f0 = __shfl_sync(0xffffffffu, f, q);
            float f1 = __shfl_sync(0xffffffffu, f, q + 1);
            float f2 = __shfl_sync(0xffffffffu, f, q + 2);
            float f3 = __shfl_sync(0xffffffffu, f, q + 3);
            float4 v0 = x4[(size_t)j0 * 32 + lane];
            float4 v1 = x4[(size_t)j1 * 32 + lane];
            float4 v2 = x4[(size_t)j2 * 32 + lane];
            float4 v3 = x4[(size_t)j3 * 32 + lane];
            s.x += f0 * v0.x + f1 * v1.x + f2 * v2.x + f3 * v3.x;
            s.y += f0 * v0.y + f1 * v1.y + f2 * v2.y + f3 * v3.y;
            s.z += f0 * v0.z + f1 * v1.z + f2 * v2.z + f3 * v3.z;
            s.w += f0 * v0.w + f1 * v1.w + f2 * v2.w + f3 * v3.w;
        }
        for (; q < m; q++) {
            int j0 = __shfl_sync(0xffffffffu, j, q);
            float f0 = __shfl_sync(0xffffffffu, f, q);
            float4 v0 = x4[(size_t)j0 * 32 + lane];
            s.x += f0 * v0.x; s.y += f0 * v0.y;
            s.z += f0 * v0.z; s.w += f0 * v0.w;
        }
    }
    float rr = rs[r];
    s.x *= rr; s.y *= rr; s.z *= rr; s.w *= rr;
    size_t o = (size_t)r * 32 + lane;
    if (out) ((float4*)out)[o] = s;
    if (acc) {
        float4 a = ((const float4*)acc)[o];
        a.x += s.x; a.y += s.y; a.z += s.z; a.w += s.w;
        ((float4*)acc)[o] = a;
        if (fin) {
            ((float4*)fin)[o] = make_float4(a.x * fscale, a.y * fscale,
                                            a.z * fscale, a.w * fscale);
        }
    }
    if (mixo) {
        float4 mb = ((const float4*)mixb)[o];
        ((float4*)mixo)[o] = make_float4(
            0.8f * mb.x + 0.2f * s.x, 0.8f * mb.y + 0.2f * s.y,
            0.8f * mb.z + 0.2f * s.z, 0.8f * mb.w + 0.2f * s.w);
    }
}

// Fused two-input SpMM over the same sparsity: out1 = S x1; acc += S x1 + S x2.
__device__ __forceinline__ void spmm_row2(
    const int* __restrict__ idx, const int* __restrict__ len, int cap,
    const float* __restrict__ rs, const float* __restrict__ cs,
    const float* __restrict__ x1, const float* __restrict__ x2,
    float* out1, float* acc, int n, int r) {
    if (r >= n) return;
    int lane = threadIdx.x & 31;
    const float4* x14 = (const float4*)x1;
    const float4* x24 = (const float4*)x2;
    int L = len[r];
    float4 s1 = make_float4(0.f, 0.f, 0.f, 0.f);
    float4 s2 = make_float4(0.f, 0.f, 0.f, 0.f);
    for (int p0 = 0; p0 < L; p0 += 32) {
        int j = 0; float f = 0.f;
        if (p0 + lane < L) {
            j = idx[(size_t)r * cap + p0 + lane];
            f = cs[j];
        }
        int m = min(32, L - p0);
        for (int q = 0; q < m; q++) {
            int j0 = __shfl_sync(0xffffffffu, j, q);
            float f0 = __shfl_sync(0xffffffffu, f, q);
            float4 a = x14[(size_t)j0 * 32 + lane];
            float4 b = x24[(size_t)j0 * 32 + lane];
            s1.x += f0 * a.x; s1.y += f0 * a.y; s1.z += f0 * a.z; s1.w += f0 * a.w;
            s2.x += f0 * b.x; s2.y += f0 * b.y; s2.z += f0 * b.z; s2.w += f0 * b.w;
        }
    }
    float rr = rs[r];
    s1.x *= rr; s1.y *= rr; s1.z *= rr; s1.w *= rr;
    s2.x *= rr; s2.y *= rr; s2.z *= rr; s2.w *= rr;
    size_t o = (size_t)r * 32 + lane;
    ((float4*)out1)[o] = s1;
    float4 a = ((const float4*)acc)[o];
    a.x += s1.x + s2.x; a.y += s1.y + s2.y;
    a.z += s1.z + s2.z; a.w += s1.w + s2.w;
    ((float4*)acc)[o] = a;
}

// ---- M1: R^T fill (warp/row) + len-based scales + zero gram ----
__global__ void __launch_bounds__(256) k_m1() {
    int b = blockIdx.x;
    if (b < DBK) {
        int wid = threadIdx.x >> 5, lane = threadIdx.x & 31;
        int r = b * 8 + wid;
        if (r < D_NUM) {
            int L = g_lenR[r];
            for (int p = lane; p < L; p += 32) {
                int c = g_idxR[r * CAP_PP + p];
                int pos = atomicAdd(&g_curRT[c], 1);
                if (pos < CAP_DD) g_idxRT[c * CAP_DD + pos] = r;
            }
        }
    } else {
        int i = (b - DBK) * 256 + threadIdx.x;
        if (i < D_NUM) {
            int d;
            d = g_len2[i]; g_dinv2[i] = d > 0 ? rsqrtf((float)d) : 0.0f;
                           g_cinv2[i] = d > 0 ? 1.0f / (float)d : 0.0f;
            d = g_len4[i]; g_dinv4[i] = d > 0 ? rsqrtf((float)d) : 0.0f;
            d = g_lenR[i]; g_dinvRd[i] = d > 0 ? rsqrtf((float)d) : 0.0f;
                           g_cinvRd[i] = d > 0 ? 1.0f / (float)d : 0.0f;
        }
        if (i < P_NUM) {
            int d = g_len3[i];
            g_dinv3[i] = d > 0 ? rsqrtf((float)d) : 0.0f;
            g_cinv3[i] = d > 0 ? 1.0f / (float)d : 0.0f;
        }
        for (int q = i; q < EMB * EMB; q += 18 * 256) { g_gd[q] = 0.f; g_gp[q] = 0.f; }
        if (i < EMB) { g_sd[i] = 0.f; g_sp[i] = 0.f; }
    }
}

// ---- M2: sort R^T + Rp scales; nei2/nei3; GCN layer 1 ----
__global__ void __launch_bounds__(256) k_m2() {
    int b = blockIdx.x;
    int wid = threadIdx.x >> 5;
    if (b < DBK) {
        spmm_row(g_idx2, g_len2, CAP_DD, g_cinv2, 0, g_dru_str, g_nei2, 0, 0, 0.f, 0, 0, D_NUM, b * 8 + wid);
    } else if (b < DBK + PBK) {
        spmm_row(g_idx3, g_len3, CAP_PP, g_cinv3, 0, g_pro_str, g_nei3, 0, 0, 0.f, 0, 0, P_NUM, (b - DBK) * 8 + wid);
    } else if (b < 2 * DBK + PBK) {
        spmm_row(g_idx2, g_len2, CAP_DD, g_dinv2, g_dinv2, g_curD, g_x2a, g_acc2, 0, 0.f, 0, 0, D_NUM, (b - DBK - PBK) * 8 + wid);
    } else if (b < 2 * DBK + 2 * PBK) {
        spmm_row(g_idx3, g_len3, CAP_PP, g_dinv3, g_dinv3, g_cur3, g_x3a, g_acc3, 0, 0.f, 0, 0, P_NUM, (b - 2 * DBK - PBK) * 8 + wid);
    } else if (b < 3 * DBK + 2 * PBK) {
        spmm_row(g_idx4, g_len4, CAP_DD, g_dinv4, g_dinv4, g_curD, g_x4a, g_acc4, 0, 0.f, 0, 0, D_NUM, (b - 2 * DBK - 2 * PBK) * 8 + wid);
    } else {
        int i = (b - 3 * DBK - 2 * PBK) * 256 + threadIdx.x;
        if (i < P_NUM) {
            int L = min(g_curRT[i], CAP_DD);
            g_curRT[i] = L;
            int* a = &g_idxRT[i * CAP_DD];
            for (int q = 1; q < L; q++) {
                int v = a[q]; int jj = q - 1;
                while (jj >= 0 && a[jj] > v) { a[jj + 1] = a[jj]; jj--; }
                a[jj + 1] = v;
            }
            g_dinvRp[i] = L > 0 ? rsqrtf((float)L) : 0.0f;
            g_cinvRp[i] = L > 0 ? 1.0f / (float)L : 0.0f;
        }
    }
}

// ---- M3: GCN layer 2; cross-domain mixes; bp1; bdx  (4 D-ops + 3 P-ops) ----
__global__ void __launch_bounds__(256) k_m3() {
    int b = blockIdx.x;
    int wid = threadIdx.x >> 5;
    if (b < DBK) {
        spmm_row(g_idx2, g_len2, CAP_DD, g_dinv2, g_dinv2, g_x2a, g_x2b, g_acc2, 0, 0.f, 0, 0, D_NUM, b * 8 + wid);
    } else if (b < DBK + PBK) {
        spmm_row(g_idx3, g_len3, CAP_PP, g_dinv3, g_dinv3, g_x3a, g_x3b, g_acc3, 0, 0.f, 0, 0, P_NUM, (b - DBK) * 8 + wid);
    } else if (b < 2 * DBK + PBK) {
        spmm_row(g_idx4, g_len4, CAP_DD, g_dinv4, g_dinv4, g_x4a, g_x4b, g_acc4, 0, 0.f, 0, 0, D_NUM, (b - DBK - PBK) * 8 + wid);
    } else if (b < 3 * DBK + PBK) {
        spmm_row(g_idxR, g_lenR, CAP_PP, g_cinvRd, 0, g_nei3, 0, 0, 0, 0.f, g_dru_str, g_one_all, D_NUM, (b - 2 * DBK - PBK) * 8 + wid);
    } else if (b < 3 * DBK + 2 * PBK) {
        spmm_row(g_idxRT, g_curRT, CAP_DD, g_cinvRp, 0, g_nei2, 0, 0, 0, 0.f, g_pro_str, g_tmpp, P_NUM, (b - 3 * DBK - PBK) * 8 + wid);
    } else if (b < 3 * DBK + 3 * PBK) {
        spmm_row(g_idxRT, g_curRT, CAP_DD, g_dinvRp, g_dinvRd, g_one_emb, g_bp1, 0, 0, 0.f, 0, 0, P_NUM, (b - 3 * DBK - 2 * PBK) * 8 + wid);
    } else {
        spmm_row(g_idxR, g_lenR, CAP_PP, g_dinvRd, g_dinvRp, g_two_emb, g_bdx, 0, 0, 0.f, 0, 0, D_NUM, (b - 3 * DBK - 3 * PBK) * 8 + wid);
    }
}

// ---- M4: GCN layer 3 finalize; two_all GEMM; fused bpx+accp; accd+=S bp1 ---
__global__ void __launch_bounds__(256) k_m4() {
    __shared__ __align__(16) float As[32 * 68];
    __shared__ __align__(16) float Ws[32 * 132];
    int b = blockIdx.x;
    int wid = threadIdx.x >> 5;
    if (b < 71) {
        gemm64(g_tmpp, P_NUM, 128, g_Wc, 0, g_two_all, 0, 0, b * 64, As, Ws);
        return;
    }
    b -= 71;
    if (b < DBK) {
        spmm_row(g_idx2, g_len2, CAP_DD, g_dinv2, g_dinv2, g_x2b, 0, g_acc2, g_emb2, 0.25f, 0, 0, D_NUM, b * 8 + wid);
    } else if (b < DBK + PBK) {
        spmm_row(g_idx3, g_len3, CAP_PP, g_dinv3, g_dinv3, g_x3b, 0, g_acc3, g_emb3, 0.25f, 0, 0, P_NUM, (b - DBK) * 8 + wid);
    } else if (b < 2 * DBK + PBK) {
        spmm_row(g_idx4, g_len4, CAP_DD, g_dinv4, g_dinv4, g_x4b, 0, g_acc4, g_emb4, 0.25f, 0, 0, D_NUM, (b - DBK - PBK) * 8 + wid);
    } else if (b < 2 * DBK + 2 * PBK) {
        // fused: bpx = S^T one_all; accp += S^T one_all + S^T bdx (one gather)
        spmm_row2(g_idxRT, g_curRT, CAP_DD, g_dinvRp, g_dinvRd,
                  g_one_all, g_bdx, g_bpx, g_accp, P_NUM, (b - 2 * DBK - PBK) * 8 + wid);
    } else {
        spmm_row(g_idxR, g_lenR, CAP_PP, g_dinvRd, g_dinvRp, g_bp1, 0, g_accd, 0, 0.f, 0, 0, D_NUM, (b - 2 * DBK - 2 * PBK) * 8 + wid);
    }
}

// ---- M5: bd1 = S two_all (+accd); bdy = S bpx ----
__global__ void __launch_bounds__(256) k_m5() {
    int b = blockIdx.x;
    int wid = threadIdx.x >> 5;
    if (b < DBK)
        spmm_row(g_idxR, g_lenR, CAP_PP, g_dinvRd, g_dinvRp, g_two_all, g_bd1, g_accd, 0, 0.f, 0, 0, D_NUM, b * 8 + wid);
    else
        spmm_row(g_idxR, g_lenR, CAP_PP, g_dinvRd, g_dinvRp, g_bpx, g_bdy, 0, 0, 0.f, 0, 0, D_NUM, (b - DBK) * 8 + wid);
}

// ---- M6: bp2 = S^T bd1; pro_int finalize ----
__global__ void __launch_bounds__(256) k_m6() {
    int b = blockIdx.x;
    int wid = threadIdx.x >> 5;
    if (b < PBK)
        spmm_row(g_idxRT, g_curRT, CAP_DD, g_dinvRp, g_dinvRd, g_bd1, g_bp2, 0, 0, 0.f, 0, 0, P_NUM, b * 8 + wid);
    else
        spmm_row(g_idxRT, g_curRT, CAP_DD, g_dinvRp, g_dinvRd, g_bdy, 0, g_accp, g_pro_int, 0.25f, 0, 0, P_NUM, (b - PBK) * 8 + wid);
}

// ---- M7: dru_int finalize ----
__global__ void __launch_bounds__(256) k_m7() {
    int wid = threadIdx.x >> 5;
    spmm_row(g_idxR, g_lenR, CAP_PP, g_dinvRd, g_dinvRp, g_bp2, 0, g_accd, g_dru_int, 0.25f, 0, 0, D_NUM, blockIdx.x * 8 + wid);
}

// ---- attention heads (register-tiled); resets g_done ----
__global__ void __launch_bounds__(256) k_att(
    const float* __restrict__ WA_drug, const float* __restrict__ BA_drug, const float* __restrict__ HA_drug,
    const float* __restrict__ WA_pro,  const float* __restrict__ BA_pro,  const float* __restrict__ HA_pro,
    const float* __restrict__ WB_drug, const float* __restrict__ BB_drug, const float* __restrict__ HB_drug,
    const float* __restrict__ WB_pro,  const float* __restrict__ BB_pro,  const float* __restrict__ HB_pro,
    const float* __restrict__ WA_sim,  const float* __restrict__ BA_sim,  const float* __restrict__ HA_sim) {
    __shared__ __align__(16) float As[32 * 68];
    __shared__ __align__(16) float Ws[32 * 132];
    int b = blockIdx.x;
    if (b == 0 && threadIdx.x == 0) g_done = 0;
    const float *emb, *W, *B, *H; float* s; int n, r0;
    if (b < 24)        { emb = g_dru_int; W = WA_drug; B = BA_drug; H = HA_drug; s = g_wdrug; n = D_NUM; r0 = b * 64; }
    else if (b < 95)   { emb = g_pro_int; W = WA_pro;  B = BA_pro;  H = HA_pro;  s = g_wpro;  n = P_NUM; r0 = (b - 24) * 64; }
    else if (b < 119)  { emb = g_emb2;    W = WB_drug; B = BB_drug; H = HB_drug; s = g_wdrel; n = D_NUM; r0 = (b - 95) * 64; }
    else if (b < 190)  { emb = g_emb3;    W = WB_pro;  B = BB_pro;  H = HB_pro;  s = g_wprel; n = P_NUM; r0 = (b - 119) * 64; }
    else               { emb = g_emb4;    W = WA_sim;  B = BA_sim;  H = HA_sim;  s = g_wdsim; n = D_NUM; r0 = (b - 190) * 64; }

    int t = threadIdx.x;
    int tx = t & 31, ty = t >> 5;
    int m0 = ty << 3, n0 = tx << 2;
    float acc[8][4];
#pragma unroll
    for (int i = 0; i < 8; i++)
#pragma unroll
        for (int j = 0; j < 4; j++) acc[i][j] = 0.f;
    for (int k0 = 0; k0 < EMB; k0 += 32) {
        __syncthreads();
#pragma unroll
        for (int e = t; e < 512; e += 256) {
            int rr = e >> 3, kv = e & 7;
            int gr = r0 + rr;
            float4 va = (gr < n) ? *(const float4*)&emb[(size_t)gr * EMB + k0 + (kv << 2)]
                                 : make_float4(0.f, 0.f, 0.f, 0.f);
            As[(kv * 4 + 0) * 68 + rr] = va.x;
            As[(kv * 4 + 1) * 68 + rr] = va.y;
            As[(kv * 4 + 2) * 68 + rr] = va.z;
            As[(kv * 4 + 3) * 68 + rr] = va.w;
        }
#pragma unroll
        for (int e = t; e < 1024; e += 256) {
            int kk = e >> 5, cv = e & 31;
            *(float4*)&Ws[kk * 132 + (cv << 2)] =
                *(const float4*)&W[(size_t)(k0 + kk) * EMB + (cv << 2)];
        }
        __syncthreads();
#pragma unroll
        for (int kk = 0; kk < 32; kk++) {
            float4 a0 = *(const float4*)&As[kk * 68 + m0];
            float4 a1 = *(const float4*)&As[kk * 68 + m0 + 4];
            float4 w  = *(const float4*)&Ws[kk * 132 + n0];
            float av[8] = {a0.x, a0.y, a0.z, a0.w, a1.x, a1.y, a1.z, a1.w};
#pragma unroll
            for (int i = 0; i < 8; i++) {
                acc[i][0] += av[i] * w.x;
                acc[i][1] += av[i] * w.y;
                acc[i][2] += av[i] * w.z;
                acc[i][3] += av[i] * w.w;
            }
        }
    }
    float4 bb = *(const float4*)&B[n0];
    float4 hh = *(const float4*)&H[n0];
#pragma unroll
    for (int i = 0; i < 8; i++) {
        float p = fmaxf(acc[i][0] + bb.x, 0.f) * hh.x
                + fmaxf(acc[i][1] + bb.y, 0.f) * hh.y
                + fmaxf(acc[i][2] + bb.z, 0.f) * hh.z
                + fmaxf(acc[i][3] + bb.w, 0.f) * hh.w;
#pragma unroll
        for (int o = 16; o; o >>= 1) p += __shfl_down_sync(0xffffffffu, p, o);
        if (tx == 0) {
            int gr = r0 + m0 + i;
            if (gr < n) s[gr] = p;
        }
    }
}

__global__ void __launch_bounds__(1024) k_ls() {
    int head = blockIdx.x;
    float* s; int n;
    switch (head) {
        case 0: s = g_wdrug; n = D_NUM; break;
        case 1: s = g_wpro;  n = P_NUM; break;
        case 2: s = g_wdrel; n = D_NUM; break;
        case 3: s = g_wprel; n = P_NUM; break;
        default:s = g_wdsim; n = D_NUM; break;
    }
    __shared__ float sh[1024];
    int t = threadIdx.x;
    float m = -1e30f;
    for (int i = t; i < n; i += 1024) m = fmaxf(m, s[i]);
    sh[t] = m; __syncthreads();
    for (int o = 512; o; o >>= 1) { if (t < o) sh[t] = fmaxf(sh[t], sh[t + o]); __syncthreads(); }
    float mall = sh[0]; __syncthreads();
    float sum = 0.0f;
    for (int i = t; i < n; i += 1024) sum += expf(s[i] - mall);
    sh[t] = sum; __syncthreads();
    for (int o = 512; o; o >>= 1) { if (t < o) sh[t] += sh[t + o]; __syncthreads(); }
    float lse = mall + logf(sh[0]);
    for (int i = t; i < n; i += 1024) s[i] -= lse;
}

// ---- fused combine + bf16 hi/lo write + Gram + colsum + stats ----
__global__ void __launch_bounds__(256) k_comb_gram() {
    __shared__ __align__(16) float sbuf[16 * 132];
    bool isD = blockIdx.x < 32;
    int n    = isD ? D_NUM : P_NUM;
    int brel = isD ? (int)blockIdx.x : (int)blockIdx.x - 32;
    int nblk = isD ? 32 : 96;
    float* gG  = isD ? g_gd : g_gp;
    float* gS  = isD ? g_sd : g_sp;
    __nv_bfloat16* fh = isD ? g_fdh : g_fph;
    __nv_bfloat16* fl = isD ? g_fdl : g_fpl;
    int ntiles = (n + 15) >> 4;
    int tid = threadIdx.x;
    int k0 = (tid & 15) * 8, l0 = (tid >> 4) * 8;
    float accG[8][8];
#pragma unroll
    for (int i = 0; i < 8; i++)
#pragma unroll
        for (int j = 0; j < 8; j++) accG[i][j] = 0.f;
    float cs = 0.f;
    for (int t = brel; t < ntiles; t += nblk) {
        int r0 = t << 4;
        __syncthreads();
        for (int i = tid; i < 16 * 128; i += 256) {
            int rr = i >> 7, kk = i & 127;
            int gr = r0 + rr;
            float val = 0.f;
            if (gr < n) {
                size_t o = (size_t)gr * EMB + kk;
                if (isD) {
                    float wa = g_wdrug[gr], wb = g_wdrel[gr], wc = g_wdsim[gr];
                    float a = wa / (wa + wb + wc);
                    float bq = wb / (a + wb + wc);
                    float c = 1.0f - a - bq;
                    val = a * g_dru_int[o] + bq * g_emb2[o] + c * g_emb4[o];
                } else {
                    float wa = g_wpro[gr], wb = g_wprel[gr];
                    float pa = wa / (wa + wb);
                    val = pa * g_pro_int[o] + (1.0f - pa) * g_emb3[o];
                }
                __nv_bfloat16 h = __float2bfloat16(val);
                float hf = __bfloat162float(h);
                __nv_bfloat16 l = __float2bfloat16(val - hf);
                fh[o] = h;
                fl[o] = l;
                val = hf + __bfloat162float(l);
            }
            sbuf[rr * 132 + kk] = val;
        }
        __syncthreads();
#pragma unroll 4
        for (int r = 0; r < 16; r++) {
            const float* row = &sbuf[r * 132];
            float4 a0 = *(const float4*)(row + k0);
            float4 a1 = *(const float4*)(row + k0 + 4);
            float4 b0 = *(const float4*)(row + l0);
            float4 b1 = *(const float4*)(row + l0 + 4);
            float av[8] = {a0.x, a0.y, a0.z, a0.w, a1.x, a1.y, a1.z, a1.w};
            float bv[8] = {b0.x, b0.y, b0.z, b0.w, b1.x, b1.y, b1.z, b1.w};
#pragma unroll
            for (int i = 0; i < 8; i++)
#pragma unroll
                for (int j = 0; j < 8; j++) accG[i][j] += av[i] * bv[j];
        }
        if (tid < 128) {
            float c = 0.f;
            for (int r = 0; r < 16; r++) c += sbuf[r * 132 + tid];
            cs += c;
        }
    }
#pragma unroll
    for (int i = 0; i < 8; i++)
#pragma unroll
        for (int j = 0; j < 8; j++)
            atomicAdd(&gG[(k0 + i) * EMB + (l0 + j)], accG[i][j]);
    if (tid < 128) atomicAdd(&gS[tid], cs);

    __threadfence();
    __syncthreads();
    __shared__ int slast;
    if (tid == 0) slast = (atomicAdd(&g_done, 1u) == 127u) ? 1 : 0;
    __syncthreads();
    if (slast) {
        double* sd = (double*)sbuf;
        double acc = 0.0;
        for (int i = tid; i < EMB * EMB; i += 256)
            acc += (double)g_gd[i] * (double)g_gp[i];
        sd[tid] = acc; __syncthreads();
        for (int o = 128; o; o >>= 1) { if (tid < o) sd[tid] += sd[tid + o]; __syncthreads(); }
        double sumsq = sd[0]; __syncthreads();
        double a2 = (tid < EMB) ? (double)g_sd[tid] * (double)g_sp[tid] : 0.0;
        sd[tid] = a2; __syncthreads();
        for (int o = 128; o; o >>= 1) { if (tid < o) sd[tid] += sd[tid + o]; __syncthreads(); }
        if (tid == 0) {
            double sumy = sd[0];
            const double nn = (double)D_NUM * (double)P_NUM;
            double mean = sumy / nn;
            double var = (sumsq - sumy * sumy / nn) / (nn - 1.0);
            g_musig = make_float2((float)mean, (float)(1.0 / sqrt(var)));
        }
    }
}

// ====== final GEMM: warp-level bf16 mma.sync, loads precomputed hi/lo ======
#define FS 136
#define SM_AH_OFF 0
#define SM_AL_OFF (128*FS*2)
#define SM_BH_OFF (2*128*FS*2)
#define SM_BL_OFF (3*128*FS*2)
#define SMEM_MMA  (4*128*FS*2)

__device__ __forceinline__ void mma_bf16(
    float& c0, float& c1, float& c2, float& c3,
    uint32_t a0, uint32_t a1, uint32_t a2, uint32_t a3,
    uint32_t b0, uint32_t b1) {
    asm volatile(
        "mma.sync.aligned.m16n8k16.row.col.f32.bf16.bf16.f32 "
        "{%0,%1,%2,%3}, {%4,%5,%6,%7}, {%8,%9}, {%0,%1,%2,%3};"
        : "+f"(c0), "+f"(c1), "+f"(c2), "+f"(c3)
        : "r"(a0), "r"(a1), "r"(a2), "r"(a3), "r"(b0), "r"(b1));
}

__global__ void __launch_bounds__(256) k_final_mma(float* __restrict__ out) {
    extern __shared__ __align__(16) char smem[];
    __nv_bfloat16* Ah = (__nv_bfloat16*)(smem + SM_AH_OFF);
    __nv_bfloat16* Al = (__nv_bfloat16*)(smem + SM_AL_OFF);
    __nv_bfloat16* Bh = (__nv_bfloat16*)(smem + SM_BH_OFF);
    __nv_bfloat16* Bl = (__nv_bfloat16*)(smem + SM_BL_OFF);

    int t = threadIdx.x;
    int bi = blockIdx.y * 128, bj = blockIdx.x * 128;
    float2 ms = g_musig;
    float mu = ms.x, istd = ms.y;

    {
        int row = t >> 1;
        int c0 = (t & 1) * 64;
        int gi = bi + row, gj = bj + row;
        const uint4 z = make_uint4(0u, 0u, 0u, 0u);
        const uint4* sah = (gi < D_NUM) ? (const uint4*)&g_fdh[(size_t)gi * EMB + c0] : 0;
        const uint4* sal = (gi < D_NUM) ? (const uint4*)&g_fdl[(size_t)gi * EMB + c0] : 0;
        const uint4* sbh = (gj < P_NUM) ? (const uint4*)&g_fph[(size_t)gj * EMB + c0] : 0;
        const uint4* sbl = (gj < P_NUM) ? (const uint4*)&g_fpl[(size_t)gj * EMB + c0] : 0;
        int o = row * FS + c0;
#pragma unroll
        for (int q = 0; q < 8; q++) {
            *(uint4*)&Ah[o + q * 8] = sah ? __ldg(&sah[q]) : z;
            *(uint4*)&Al[o + q * 8] = sal ? __ldg(&sal[q]) : z;
            *(uint4*)&Bh[o + q * 8] = sbh ? __ldg(&sbh[q]) : z;
            *(uint4*)&Bl[o + q * 8] = sbl ? __ldg(&sbl[q]) : z;
        }
    }
    __syncthreads();

    int wid = t >> 5, lane = t & 31;
    int wm = wid & 3, wn = wid >> 2;
    int g = lane >> 2, ctid = lane & 3;
    int m_base = wm * 32, n_base = wn * 64;

    float acc[2][8][4];
#pragma unroll
    for (int mt = 0; mt < 2; mt++)
#pragma unroll
        for (int nt = 0; nt < 8; nt++)
#pragma unroll
            for (int e = 0; e < 4; e++) acc[mt][nt][e] = 0.f;

#pragma unroll
    for (int pass = 0; pass < 3; pass++) {
        const __nv_bfloat16* Asel = (pass == 2) ? Al : Ah;
        const __nv_bfloat16* Bsel = (pass == 1) ? Bl : Bh;
#pragma unroll
        for (int ks = 0; ks < 8; ks++) {
            int k0 = ks * 16;
            uint32_t af[2][4];
#pragma unroll
            for (int mt = 0; mt < 2; mt++) {
                int r = m_base + mt * 16;
                const __nv_bfloat16* ap = Asel + (size_t)(r + g) * FS + k0 + ctid * 2;
                af[mt][0] = *(const uint32_t*)ap;
                af[mt][1] = *(const uint32_t*)(ap + 8 * FS);
                af[mt][2] = *(const uint32_t*)(ap + 8);
                af[mt][3] = *(const uint32_t*)(ap + 8 * FS + 8);
            }
            uint32_t bf[8][2];
#pragma unroll
            for (int nt = 0; nt < 8; nt++) {
                int nn = n_base + nt * 8 + g;
                const __nv_bfloat16* bp = Bsel + (size_t)nn * FS + k0 + ctid * 2;
                bf[nt][0] = *(const uint32_t*)bp;
                bf[nt][1] = *(const uint32_t*)(bp + 8);
            }
#pragma unroll
            for (int mt = 0; mt < 2; mt++)
#pragma unroll
                for (int nt = 0; nt < 8; nt++)
                    mma_bf16(acc[mt][nt][0], acc[mt][nt][1], acc[mt][nt][2], acc[mt][nt][3],
                             af[mt][0], af[mt][1], af[mt][2], af[mt][3],
                             bf[nt][0], bf[nt][1]);
        }
    }

#pragma unroll
    for (int mt = 0; mt < 2; mt++) {
#pragma unroll
        for (int nt = 0; nt < 8; nt++) {
            int gj0 = bj + n_base + nt * 8 + ctid * 2;
#pragma unroll
            for (int half = 0; half < 2; half++) {
                int gi = bi + m_base + mt * 16 + g + half * 8;
                if (gi < D_NUM) {
                    float v0 = acc[mt][nt][half * 2 + 0];
                    float v1 = acc[mt][nt][half * 2 + 1];
                    float z0 = (v0 - mu) * istd;
                    float z1 = (v1 - mu) * istd;
                    float s0 = __fdividef(1.0f, 1.0f + __expf(-z0));
                    float s1 = __fdividef(1.0f, 1.0f + __expf(-z1));
                    if (gj0 + 1 < P_NUM) {
                        *(float2*)&out[(size_t)gi * P_NUM + gj0] = make_float2(s0, s1);
                    } else if (gj0 < P_NUM) {
                        out[(size_t)gi * P_NUM + gj0] = s0;
                    }
                }
            }
        }
    }
}

// ---------------- host launcher ----------------
extern "C" void kernel_launch(void* const* d_in, const int* in_sizes, int n_in,
                              void* d_out, int out_size) {
    const float* A                 = (const float*)d_in[0];
    const float* drug_structure    = (const float*)d_in[1];
    const float* protein_structure = (const float*)d_in[2];
    const float* lin_drug_w = (const float*)d_in[3];
    const float* lin_drug_b = (const float*)d_in[4];
    const float* lin_pro_w  = (const float*)d_in[5];
    const float* lin_pro_b  = (const float*)d_in[6];
    const float* p_weight   = (const float*)d_in[7];
    const float* d_weight_i = (const float*)d_in[8];
    const float* pd_weight_p = (const float*)d_in[9];
    const float* pd_weight_d = (const float*)d_in[10];
    const float* dp_weight_p = (const float*)d_in[11];
    const float* WA_drug = (const float*)d_in[12];
    const float* BA_drug = (const float*)d_in[13];
    const float* HA_drug = (const float*)d_in[14];
    const float* WB_drug = (const float*)d_in[15];
    const float* BB_drug = (const float*)d_in[16];
    const float* HB_drug = (const float*)d_in[17];
    const float* WA_pro = (const float*)d_in[18];
    const float* BA_pro = (const float*)d_in[19];
    const float* HA_pro = (const float*)d_in[20];
    const float* WB_pro = (const float*)d_in[21];
    const float* BB_pro = (const float*)d_in[22];
    const float* HB_pro = (const float*)d_in[23];
    const float* WA_sim = (const float*)d_in[24];
    const float* BA_sim = (const float*)d_in[25];
    const float* HA_sim = (const float*)d_in[26];
    float* out = (float*)d_out;
    (void)in_sizes; (void)n_in; (void)out_size;

    void* tp;
    cudaGetSymbolAddress(&tp, g_curRT);
    cudaMemsetAsync(tp, 0, P_NUM * sizeof(int), 0);

    k_ell_all<<<9000, 256>>>(A);
    k_lift<<<97, 256>>>(drug_structure, protein_structure,
                        lin_drug_w, lin_drug_b, lin_pro_w, lin_pro_b,
                        dp_weight_p, pd_weight_d);
    k_gemm2<<<190, 256>>>(d_weight_i, p_weight, pd_weight_d, pd_weight_p);
    k_m1<<<DBK + 18, 256>>>();
    k_m2<<<3 * DBK + 2 * PBK + 18, 256>>>();
    k_m3<<<4 * DBK + 3 * PBK, 256>>>();           // 4 D-ops + 3 P-ops (bdx restored)
    k_m4<<<71 + 3 * DBK + 2 * PBK, 256>>>();      // 3 D-ops + 2 P-ops + 71 GEMM (bp1-accd restored)
    k_m5<<<2 * DBK, 256>>>();
    k_m6<<<2 * PBK, 256>>>();
    k_m7<<<DBK, 256>>>();
    k_att<<<214, 256>>>(WA_drug, BA_drug, HA_drug, WA_pro, BA_pro, HA_pro,
                        WB_drug, BB_drug, HB_drug, WB_pro, BB_pro, HB_pro,
                        WA_sim, BA_sim, HA_sim);
    k_ls<<<5, 1024>>>();
    k_comb_gram<<<128, 256>>>();

    static bool attr_done = false;
    if (!attr_done) {
        cudaFuncSetAttribute(k_final_mma, cudaFuncAttributeMaxDynamicSharedMemorySize, SMEM_MMA);
        attr_done = true;
    }
    dim3 fg((P_NUM + 127) / 128, (D_NUM + 127) / 128);
    k_final_mma<<<fg, 256, SMEM_MMA>>>(out);
}

// round 17
// speedup vs baseline: 2.0226x; 1.0881x over previous
#include <cuda_runtime.h>
#include <cuda_bf16.h>
#include <math.h>
#include <stdint.h>

#define D_NUM 1500
#define P_NUM 4500
#define NTOT  6000
#define EMB   128
#define CAP_DD 64
#define CAP_PP 128
#define DB (D_NUM*EMB)
#define PB (P_NUM*EMB)
#define DBK 188   // ceil(D_NUM/8)
#define PBK 563   // ceil(P_NUM/8)

// ---------------- scratch (static __device__, no allocs) ----------------
__device__ __align__(128) int g_idx2[D_NUM*CAP_DD]; __device__ int g_len2[D_NUM];
__device__ __align__(128) int g_idx4[D_NUM*CAP_DD]; __device__ int g_len4[D_NUM];
__device__ __align__(128) int g_idx3[P_NUM*CAP_PP]; __device__ int g_len3[P_NUM];
__device__ __align__(128) int g_idxR[D_NUM*CAP_PP]; __device__ int g_lenR[D_NUM];
__device__ __align__(128) int g_idxRT[P_NUM*CAP_DD]; __device__ int g_curRT[P_NUM];

__device__ float g_dinv2[D_NUM], g_cinv2[D_NUM];
__device__ float g_dinv3[P_NUM], g_cinv3[P_NUM];
__device__ float g_dinv4[D_NUM];
__device__ float g_dinvRd[D_NUM], g_cinvRd[D_NUM];
__device__ float g_dinvRp[P_NUM], g_cinvRp[P_NUM];

__device__ __align__(128) float g_dru_str[DB], g_pro_str[PB];
__device__ __align__(128) float g_nei2[DB],    g_nei3[PB];
__device__ __align__(128) float g_emb2[DB],    g_emb3[PB],  g_emb4[DB];
__device__ __align__(128) float g_curD[DB],    g_cur3[PB];
__device__ __align__(128) float g_x2a[DB], g_x2b[DB], g_x4a[DB], g_x4b[DB];
__device__ __align__(128) float g_x3a[PB], g_x3b[PB];
__device__ __align__(128) float g_acc2[DB], g_acc3[PB], g_acc4[DB];
__device__ __align__(128) float g_one_emb[DB], g_two_all[PB], g_one_all[DB], g_two_emb[PB];
__device__ __align__(128) float g_bd1[DB],  g_bp1[PB], g_bp2[PB];
__device__ __align__(128) float g_bdx[DB],  g_bpx[PB], g_bdy[DB];
__device__ __align__(128) float g_accd[DB], g_accp[PB];
__device__ __align__(128) float g_dru_int[DB], g_pro_int[PB];
__device__ __align__(128) float g_tmpp[PB], g_Wc[EMB*EMB];
__device__ float g_wdrug[D_NUM], g_wdrel[D_NUM], g_wdsim[D_NUM];
__device__ float g_wpro[P_NUM],  g_wprel[P_NUM];
__device__ __align__(128) float g_gd[EMB*EMB], g_gp[EMB*EMB];
__device__ float g_sd[EMB], g_sp[EMB];
__device__ __align__(128) __nv_bfloat16 g_fdh[DB], g_fdl[DB];
__device__ __align__(128) __nv_bfloat16 g_fph[PB], g_fpl[PB];
__device__ float2 g_musig;
__device__ unsigned g_done;

// ------- ELL extraction + parallel rank-ordering + fused scales/RT-fill ----
__global__ void k_ell_all(const float* __restrict__ A) {
    const size_t NN = (size_t)NTOT * NTOT;
    int b = blockIdx.x;
    const float* base; int r, row0, col0, ncols, cap; int *idx, *len;
    if (b < 1500)      { base = A + 2*NN; r = b;        row0 = 0;     col0 = 0;     ncols = D_NUM; cap = CAP_DD; idx = g_idx2; len = g_len2; }
    else if (b < 6000) { base = A + 3*NN; r = b - 1500; row0 = D_NUM; col0 = D_NUM; ncols = P_NUM; cap = CAP_PP; idx = g_idx3; len = g_len3; }
    else if (b < 7500) { base = A + 4*NN; r = b - 6000; row0 = 0;     col0 = 0;     ncols = D_NUM; cap = CAP_DD; idx = g_idx4; len = g_len4; }
    else               { base = A;        r = b - 7500; row0 = 0;     col0 = D_NUM; ncols = P_NUM; cap = CAP_PP; idx = g_idxR; len = g_lenR; }

    const float4* row4 = (const float4*)(base + (size_t)(row0 + r) * NTOT + col0);
    int nv = ncols >> 2;
    __shared__ int cnt;
    __shared__ int buf[160];
    if (threadIdx.x == 0) cnt = 0;
    __syncthreads();

    float4 v[5];
#pragma unroll
    for (int u = 0; u < 5; u++) {
        int i = threadIdx.x + (u << 8);
        if (i < nv) v[u] = __ldg(&row4[i]);
    }
#pragma unroll
    for (int u = 0; u < 5; u++) {
        int i = threadIdx.x + (u << 8);
        if (i < nv) {
            int c = i << 2;
            if (v[u].x == 1.0f) { int p = atomicAdd(&cnt, 1); if (p < 160) buf[p] = c; }
            if (v[u].y == 1.0f) { int p = atomicAdd(&cnt, 1); if (p < 160) buf[p] = c + 1; }
            if (v[u].z == 1.0f) { int p = atomicAdd(&cnt, 1); if (p < 160) buf[p] = c + 2; }
            if (v[u].w == 1.0f) { int p = atomicAdd(&cnt, 1); if (p < 160) buf[p] = c + 3; }
        }
    }
    __syncthreads();
    int L = min(cnt, cap);

    // parallel rank-ordering: thread i places buf[i] at its sorted position
    if (threadIdx.x < L) {
        int val = buf[threadIdx.x];
        int rank = 0;
        for (int i = 0; i < L; i++) rank += (buf[i] < val) ? 1 : 0;
        idx[(size_t)r * cap + rank] = val;
    }
    if (threadIdx.x == 0) len[r] = L;

    // fused per-row degree scales + (for R) transpose fill
    float di = L > 0 ? rsqrtf((float)L) : 0.0f;
    float ci = L > 0 ? 1.0f / (float)L : 0.0f;
    if (b < 1500) {
        if (threadIdx.x == 0) { g_dinv2[r] = di; g_cinv2[r] = ci; }
    } else if (b < 6000) {
        if (threadIdx.x == 0) { g_dinv3[r] = di; g_cinv3[r] = ci; }
    } else if (b < 7500) {
        if (threadIdx.x == 0) { g_dinv4[r] = di; }
    } else {
        if (threadIdx.x == 0) { g_dinvRd[r] = di; g_cinvRd[r] = ci; }
        if (threadIdx.x < L) {
            int c = buf[threadIdx.x];
            int pos = atomicAdd(&g_curRT[c], 1);
            if (pos < CAP_DD) g_idxRT[c * CAP_DD + pos] = r;
        }
    }
}

// ------------- register-tiled GEMM tile (64 rows x 128 cols) ---------------
__device__ __forceinline__ void gemm64(const float* A, int n, int k,
    const float* W, const float* bias, float* C, float* C2, float* C3,
    int r0, float* As, float* Ws) {
    int t = threadIdx.x;
    int tx = t & 31, ty = t >> 5;
    int m0 = ty << 3, n0 = tx << 2;
    float acc[8][4];
#pragma unroll
    for (int i = 0; i < 8; i++)
#pragma unroll
        for (int j = 0; j < 4; j++) acc[i][j] = 0.f;
    for (int k0 = 0; k0 < k; k0 += 32) {
        __syncthreads();
#pragma unroll
        for (int e = t; e < 512; e += 256) {
            int rr = e >> 3, kv = e & 7;
            int gr = r0 + rr;
            float4 va = (gr < n) ? *(const float4*)&A[(size_t)gr * k + k0 + (kv << 2)]
                                 : make_float4(0.f, 0.f, 0.f, 0.f);
            As[(kv * 4 + 0) * 68 + rr] = va.x;
            As[(kv * 4 + 1) * 68 + rr] = va.y;
            As[(kv * 4 + 2) * 68 + rr] = va.z;
            As[(kv * 4 + 3) * 68 + rr] = va.w;
        }
#pragma unroll
        for (int e = t; e < 1024; e += 256) {
            int kk = e >> 5, cv = e & 31;
            *(float4*)&Ws[kk * 132 + (cv << 2)] =
                *(const float4*)&W[(size_t)(k0 + kk) * EMB + (cv << 2)];
        }
        __syncthreads();
#pragma unroll
        for (int kk = 0; kk < 32; kk++) {
            float4 a0 = *(const float4*)&As[kk * 68 + m0];
            float4 a1 = *(const float4*)&As[kk * 68 + m0 + 4];
            float4 w  = *(const float4*)&Ws[kk * 132 + n0];
            float av[8] = {a0.x, a0.y, a0.z, a0.w, a1.x, a1.y, a1.z, a1.w};
#pragma unroll
            for (int i = 0; i < 8; i++) {
                acc[i][0] += av[i] * w.x;
                acc[i][1] += av[i] * w.y;
                acc[i][2] += av[i] * w.z;
                acc[i][3] += av[i] * w.w;
            }
        }
    }
    float4 bb = bias ? *(const float4*)&bias[n0] : make_float4(0.f, 0.f, 0.f, 0.f);
#pragma unroll
    for (int i = 0; i < 8; i++) {
        int gr = r0 + m0 + i;
        if (gr < n) {
            float4 vv = make_float4(acc[i][0] + bb.x, acc[i][1] + bb.y,
                                    acc[i][2] + bb.z, acc[i][3] + bb.w);
            *(float4*)&C[(size_t)gr * EMB + n0] = vv;
            if (C2) *(float4*)&C2[(size_t)gr * EMB + n0] = vv;
            if (C3) *(float4*)&C3[(size_t)gr * EMB + n0] = vv;
        }
    }
}

__global__ void __launch_bounds__(256) k_lift(
    const float* __restrict__ drug_structure, const float* __restrict__ protein_structure,
    const float* __restrict__ lin_drug_w, const float* __restrict__ lin_drug_b,
    const float* __restrict__ lin_pro_w, const float* __restrict__ lin_pro_b,
    const float* __restrict__ dp_weight_p, const float* __restrict__ pd_weight_d) {
    __shared__ __align__(16) float As[32 * 68];
    __shared__ __align__(16) float Ws[32 * 132];
    int b = blockIdx.x;
    if (b < 24)       gemm64(drug_structure, D_NUM, 160, lin_drug_w, lin_drug_b, g_dru_str, 0, 0, b * 64, As, Ws);
    else if (b < 95)  gemm64(protein_structure, P_NUM, 512, lin_pro_w, lin_pro_b, g_pro_str, 0, 0, (b - 24) * 64, As, Ws);
    else              gemm64(dp_weight_p, 128, 128, pd_weight_d, 0, g_Wc, 0, 0, (b - 95) * 64, As, Ws);
}

__global__ void __launch_bounds__(256) k_gemm2(
    const float* __restrict__ d_weight_i, const float* __restrict__ p_weight,
    const float* __restrict__ pd_weight_d, const float* __restrict__ pd_weight_p) {
    __shared__ __align__(16) float As[32 * 68];
    __shared__ __align__(16) float Ws[32 * 132];
    int b = blockIdx.x;
    if (b < 24)        gemm64(g_dru_str, D_NUM, 128, d_weight_i, 0, g_curD, g_acc2, g_acc4, b * 64, As, Ws);
    else if (b < 95)   gemm64(g_pro_str, P_NUM, 128, p_weight, 0, g_cur3, g_acc3, 0, (b - 24) * 64, As, Ws);
    else if (b < 119)  gemm64(g_dru_str, D_NUM, 128, pd_weight_d, 0, g_one_emb, g_accd, 0, (b - 95) * 64, As, Ws);
    else               gemm64(g_pro_str, P_NUM, 128, pd_weight_p, 0, g_two_emb, g_accp, 0, (b - 119) * 64, As, Ws);
}

// ---------------- warp-per-row SpMM body ----------------
__device__ __forceinline__ void spmm_row(
    const int* __restrict__ idx, const int* __restrict__ len, int cap,
    const float* __restrict__ rs, const float* __restrict__ cs,
    const float* __restrict__ x, float* out, float* acc, float* fin,
    float fscale, const float* mixb, float* mixo, int n, int r) {
    if (r >= n) return;
    int lane = threadIdx.x & 31;
    const float4* x4 = (const float4*)x;
    int L = len[r];
    float4 s = make_float4(0.f, 0.f, 0.f, 0.f);
    for (int p0 = 0; p0 < L; p0 += 32) {
        int j = 0; float f = 0.f;
        if (p0 + lane < L) {
            j = idx[(size_t)r * cap + p0 + lane];
            f = cs ? cs[j] : 1.0f;
        }
        int m = min(32, L - p0);
        int q = 0;
        for (; q + 4 <= m; q += 4) {
            int j0 = __shfl_sync(0xffffffffu, j, q);
            int j1 = __shfl_sync(0xffffffffu, j, q + 1);
            int j2 = __shfl_sync(0xffffffffu, j, q + 2);
            int j3 = __shfl_sync(0xffffffffu, j, q + 3);
            float f0 = __shfl_sync(0xffffffffu, f, q);
            float f1 = __shfl_sync(0xffffffffu, f, q + 1);
            float f2 = __shfl_sync(0xffffffffu, f, q + 2);
            float f3 = __shfl_sync(0xffffffffu, f, q + 3);
            float4 v0 = x4[(size_t)j0 * 32 + lane];
            float4 v1 = x4[(size_t)j1 * 32 + lane];
            float4 v2 = x4[(size_t)j2 * 32 + lane];
            float4 v3 = x4[(size_t)j3 * 32 + lane];
            s.x += f0 * v0.x + f1 * v1.x + f2 * v2.x + f3 * v3.x;
            s.y += f0 * v0.y + f1 * v1.y + f2 * v2.y + f3 * v3.y;
            s.z += f0 * v0.z + f1 * v1.z + f2 * v2.z + f3 * v3.z;
            s.w += f0 * v0.w + f1 * v1.w + f2 * v2.w + f3 * v3.w;
        }
        for (; q < m; q++) {
            int j0 = __shfl_sync(0xffffffffu, j, q);
            float f0 = __shfl_sync(0xffffffffu, f, q);
            float4 v0 = x4[(size_t)j0 * 32 + lane];
            s.x += f0 * v0.x; s.y += f0 * v0.y;
            s.z += f0 * v0.z; s.w += f0 * v0.w;
        }
    }
    float rr = rs[r];
    s.x *= rr; s.y *= rr; s.z *= rr; s.w *= rr;
    size_t o = (size_t)r * 32 + lane;
    if (out) ((float4*)out)[o] = s;
    if (acc) {
        float4 a = ((const float4*)acc)[o];
        a.x += s.x; a.y += s.y; a.z += s.z; a.w += s.w;
        ((float4*)acc)[o] = a;
        if (fin) {
            ((float4*)fin)[o] = make_float4(a.x * fscale, a.y * fscale,
                                            a.z * fscale, a.w * fscale);
        }
    }
    if (mixo) {
        float4 mb = ((const float4*)mixb)[o];
        ((float4*)mixo)[o] = make_float4(
            0.8f * mb.x + 0.2f * s.x, 0.8f * mb.y + 0.2f * s.y,
            0.8f * mb.z + 0.2f * s.z, 0.8f * mb.w + 0.2f * s.w);
    }
}

// Fused two-input SpMM: out1 = S x1; acc += S x1 + S x2 (one gather).
__device__ __forceinline__ void spmm_row2(
    const int* __restrict__ idx, const int* __restrict__ len, int cap,
    const float* __restrict__ rs, const float* __restrict__ cs,
    const float* __restrict__ x1, const float* __restrict__ x2,
    float* out1, float* acc, int n, int r) {
    if (r >= n) return;
    int lane = threadIdx.x & 31;
    const float4* x14 = (const float4*)x1;
    const float4* x24 = (const float4*)x2;
    int L = len[r];
    float4 s1 = make_float4(0.f, 0.f, 0.f, 0.f);
    float4 s2 = make_float4(0.f, 0.f, 0.f, 0.f);
    for (int p0 = 0; p0 < L; p0 += 32) {
        int j = 0; float f = 0.f;
        if (p0 + lane < L) {
            j = idx[(size_t)r * cap + p0 + lane];
            f = cs[j];
        }
        int m = min(32, L - p0);
        for (int q = 0; q < m; q++) {
            int j0 = __shfl_sync(0xffffffffu, j, q);
            float f0 = __shfl_sync(0xffffffffu, f, q);
            float4 a = x14[(size_t)j0 * 32 + lane];
            float4 b = x24[(size_t)j0 * 32 + lane];
            s1.x += f0 * a.x; s1.y += f0 * a.y; s1.z += f0 * a.z; s1.w += f0 * a.w;
            s2.x += f0 * b.x; s2.y += f0 * b.y; s2.z += f0 * b.z; s2.w += f0 * b.w;
        }
    }
    float rr = rs[r];
    s1.x *= rr; s1.y *= rr; s1.z *= rr; s1.w *= rr;
    s2.x *= rr; s2.y *= rr; s2.z *= rr; s2.w *= rr;
    size_t o = (size_t)r * 32 + lane;
    ((float4*)out1)[o] = s1;
    float4 a = ((const float4*)acc)[o];
    a.x += s1.x + s2.x; a.y += s1.y + s2.y;
    a.z += s1.z + s2.z; a.w += s1.w + s2.w;
    ((float4*)acc)[o] = a;
}

// ---- M2: sort R^T + Rp scales; nei2/nei3; GCN layer 1 ----
__global__ void __launch_bounds__(256) k_m2() {
    int b = blockIdx.x;
    int wid = threadIdx.x >> 5;
    if (b < DBK) {
        spmm_row(g_idx2, g_len2, CAP_DD, g_cinv2, 0, g_dru_str, g_nei2, 0, 0, 0.f, 0, 0, D_NUM, b * 8 + wid);
    } else if (b < DBK + PBK) {
        spmm_row(g_idx3, g_len3, CAP_PP, g_cinv3, 0, g_pro_str, g_nei3, 0, 0, 0.f, 0, 0, P_NUM, (b - DBK) * 8 + wid);
    } else if (b < 2 * DBK + PBK) {
        spmm_row(g_idx2, g_len2, CAP_DD, g_dinv2, g_dinv2, g_curD, g_x2a, g_acc2, 0, 0.f, 0, 0, D_NUM, (b - DBK - PBK) * 8 + wid);
    } else if (b < 2 * DBK + 2 * PBK) {
        spmm_row(g_idx3, g_len3, CAP_PP, g_dinv3, g_dinv3, g_cur3, g_x3a, g_acc3, 0, 0.f, 0, 0, P_NUM, (b - 2 * DBK - PBK) * 8 + wid);
    } else if (b < 3 * DBK + 2 * PBK) {
        spmm_row(g_idx4, g_len4, CAP_DD, g_dinv4, g_dinv4, g_curD, g_x4a, g_acc4, 0, 0.f, 0, 0, D_NUM, (b - 2 * DBK - 2 * PBK) * 8 + wid);
    } else {
        int i = (b - 3 * DBK - 2 * PBK) * 256 + threadIdx.x;
        if (i < P_NUM) {
            int L = min(g_curRT[i], CAP_DD);
            g_curRT[i] = L;
            int* a = &g_idxRT[i * CAP_DD];
            for (int q = 1; q < L; q++) {
                int v = a[q]; int jj = q - 1;
                while (jj >= 0 && a[jj] > v) { a[jj + 1] = a[jj]; jj--; }
                a[jj + 1] = v;
            }
            g_dinvRp[i] = L > 0 ? rsqrtf((float)L) : 0.0f;
            g_cinvRp[i] = L > 0 ? 1.0f / (float)L : 0.0f;
        }
    }
}

// ---- M3: GCN layer 2; cross-domain mixes; bp1; bdx  (4 D-ops + 3 P-ops) ----
__global__ void __launch_bounds__(256) k_m3() {
    int b = blockIdx.x;
    int wid = threadIdx.x >> 5;
    if (b < DBK) {
        spmm_row(g_idx2, g_len2, CAP_DD, g_dinv2, g_dinv2, g_x2a, g_x2b, g_acc2, 0, 0.f, 0, 0, D_NUM, b * 8 + wid);
    } else if (b < DBK + PBK) {
        spmm_row(g_idx3, g_len3, CAP_PP, g_dinv3, g_dinv3, g_x3a, g_x3b, g_acc3, 0, 0.f, 0, 0, P_NUM, (b - DBK) * 8 + wid);
    } else if (b < 2 * DBK + PBK) {
        spmm_row(g_idx4, g_len4, CAP_DD, g_dinv4, g_dinv4, g_x4a, g_x4b, g_acc4, 0, 0.f, 0, 0, D_NUM, (b - DBK - PBK) * 8 + wid);
    } else if (b < 3 * DBK + PBK) {
        spmm_row(g_idxR, g_lenR, CAP_PP, g_cinvRd, 0, g_nei3, 0, 0, 0, 0.f, g_dru_str, g_one_all, D_NUM, (b - 2 * DBK - PBK) * 8 + wid);
    } else if (b < 3 * DBK + 2 * PBK) {
        spmm_row(g_idxRT, g_curRT, CAP_DD, g_cinvRp, 0, g_nei2, 0, 0, 0, 0.f, g_pro_str, g_tmpp, P_NUM, (b - 3 * DBK - PBK) * 8 + wid);
    } else if (b < 3 * DBK + 3 * PBK) {
        spmm_row(g_idxRT, g_curRT, CAP_DD, g_dinvRp, g_dinvRd, g_one_emb, g_bp1, 0, 0, 0.f, 0, 0, P_NUM, (b - 3 * DBK - 2 * PBK) * 8 + wid);
    } else {
        spmm_row(g_idxR, g_lenR, CAP_PP, g_dinvRd, g_dinvRp, g_two_emb, g_bdx, 0, 0, 0.f, 0, 0, D_NUM, (b - 3 * DBK - 3 * PBK) * 8 + wid);
    }
}

// ---- M4: GCN layer 3 finalize; two_all GEMM; fused bpx+accp; accd+=S bp1 ---
__global__ void __launch_bounds__(256) k_m4() {
    __shared__ __align__(16) float As[32 * 68];
    __shared__ __align__(16) float Ws[32 * 132];
    int b = blockIdx.x;
    int wid = threadIdx.x >> 5;
    if (b < 71) {
        gemm64(g_tmpp, P_NUM, 128, g_Wc, 0, g_two_all, 0, 0, b * 64, As, Ws);
        return;
    }
    b -= 71;
    if (b < DBK) {
        spmm_row(g_idx2, g_len2, CAP_DD, g_dinv2, g_dinv2, g_x2b, 0, g_acc2, g_emb2, 0.25f, 0, 0, D_NUM, b * 8 + wid);
    } else if (b < DBK + PBK) {
        spmm_row(g_idx3, g_len3, CAP_PP, g_dinv3, g_dinv3, g_x3b, 0, g_acc3, g_emb3, 0.25f, 0, 0, P_NUM, (b - DBK) * 8 + wid);
    } else if (b < 2 * DBK + PBK) {
        spmm_row(g_idx4, g_len4, CAP_DD, g_dinv4, g_dinv4, g_x4b, 0, g_acc4, g_emb4, 0.25f, 0, 0, D_NUM, (b - DBK - PBK) * 8 + wid);
    } else if (b < 2 * DBK + 2 * PBK) {
        spmm_row2(g_idxRT, g_curRT, CAP_DD, g_dinvRp, g_dinvRd,
                  g_one_all, g_bdx, g_bpx, g_accp, P_NUM, (b - 2 * DBK - PBK) * 8 + wid);
    } else {
        spmm_row(g_idxR, g_lenR, CAP_PP, g_dinvRd, g_dinvRp, g_bp1, 0, g_accd, 0, 0.f, 0, 0, D_NUM, (b - 2 * DBK - 2 * PBK) * 8 + wid);
    }
}

// ---- M5: bd1 = S two_all (+accd); bdy = S bpx ----
__global__ void __launch_bounds__(256) k_m5() {
    int b = blockIdx.x;
    int wid = threadIdx.x >> 5;
    if (b < DBK)
        spmm_row(g_idxR, g_lenR, CAP_PP, g_dinvRd, g_dinvRp, g_two_all, g_bd1, g_accd, 0, 0.f, 0, 0, D_NUM, b * 8 + wid);
    else
        spmm_row(g_idxR, g_lenR, CAP_PP, g_dinvRd, g_dinvRp, g_bpx, g_bdy, 0, 0, 0.f, 0, 0, D_NUM, (b - DBK) * 8 + wid);
}

// ---- M6: bp2 = S^T bd1; pro_int finalize ----
__global__ void __launch_bounds__(256) k_m6() {
    int b = blockIdx.x;
    int wid = threadIdx.x >> 5;
    if (b < PBK)
        spmm_row(g_idxRT, g_curRT, CAP_DD, g_dinvRp, g_dinvRd, g_bd1, g_bp2, 0, 0, 0.f, 0, 0, P_NUM, b * 8 + wid);
    else
        spmm_row(g_idxRT, g_curRT, CAP_DD, g_dinvRp, g_dinvRd, g_bdy, 0, g_accp, g_pro_int, 0.25f, 0, 0, P_NUM, (b - PBK) * 8 + wid);
}

// ---- M7: dru_int finalize ----
__global__ void __launch_bounds__(256) k_m7() {
    int wid = threadIdx.x >> 5;
    spmm_row(g_idxR, g_lenR, CAP_PP, g_dinvRd, g_dinvRp, g_bp2, 0, g_accd, g_dru_int, 0.25f, 0, 0, D_NUM, blockIdx.x * 8 + wid);
}

// ---- attention heads (register-tiled); resets g_done ----
__global__ void __launch_bounds__(256) k_att(
    const float* __restrict__ WA_drug, const float* __restrict__ BA_drug, const float* __restrict__ HA_drug,
    const float* __restrict__ WA_pro,  const float* __restrict__ BA_pro,  const float* __restrict__ HA_pro,
    const float* __restrict__ WB_drug, const float* __restrict__ BB_drug, const float* __restrict__ HB_drug,
    const float* __restrict__ WB_pro,  const float* __restrict__ BB_pro,  const float* __restrict__ HB_pro,
    const float* __restrict__ WA_sim,  const float* __restrict__ BA_sim,  const float* __restrict__ HA_sim) {
    __shared__ __align__(16) float As[32 * 68];
    __shared__ __align__(16) float Ws[32 * 132];
    int b = blockIdx.x;
    if (b == 0 && threadIdx.x == 0) g_done = 0;
    const float *emb, *W, *B, *H; float* s; int n, r0;
    if (b < 24)        { emb = g_dru_int; W = WA_drug; B = BA_drug; H = HA_drug; s = g_wdrug; n = D_NUM; r0 = b * 64; }
    else if (b < 95)   { emb = g_pro_int; W = WA_pro;  B = BA_pro;  H = HA_pro;  s = g_wpro;  n = P_NUM; r0 = (b - 24) * 64; }
    else if (b < 119)  { emb = g_emb2;    W = WB_drug; B = BB_drug; H = HB_drug; s = g_wdrel; n = D_NUM; r0 = (b - 95) * 64; }
    else if (b < 190)  { emb = g_emb3;    W = WB_pro;  B = BB_pro;  H = HB_pro;  s = g_wprel; n = P_NUM; r0 = (b - 119) * 64; }
    else               { emb = g_emb4;    W = WA_sim;  B = BA_sim;  H = HA_sim;  s = g_wdsim; n = D_NUM; r0 = (b - 190) * 64; }

    int t = threadIdx.x;
    int tx = t & 31, ty = t >> 5;
    int m0 = ty << 3, n0 = tx << 2;
    float acc[8][4];
#pragma unroll
    for (int i = 0; i < 8; i++)
#pragma unroll
        for (int j = 0; j < 4; j++) acc[i][j] = 0.f;
    for (int k0 = 0; k0 < EMB; k0 += 32) {
        __syncthreads();
#pragma unroll
        for (int e = t; e < 512; e += 256) {
            int rr = e >> 3, kv = e & 7;
            int gr = r0 + rr;
            float4 va = (gr < n) ? *(const float4*)&emb[(size_t)gr * EMB + k0 + (kv << 2)]
                                 : make_float4(0.f, 0.f, 0.f, 0.f);
            As[(kv * 4 + 0) * 68 + rr] = va.x;
            As[(kv * 4 + 1) * 68 + rr] = va.y;
            As[(kv * 4 + 2) * 68 + rr] = va.z;
            As[(kv * 4 + 3) * 68 + rr] = va.w;
        }
#pragma unroll
        for (int e = t; e < 1024; e += 256) {
            int kk = e >> 5, cv = e & 31;
            *(float4*)&Ws[kk * 132 + (cv << 2)] =
                *(const float4*)&W[(size_t)(k0 + kk) * EMB + (cv << 2)];
        }
        __syncthreads();
#pragma unroll
        for (int kk = 0; kk < 32; kk++) {
            float4 a0 = *(const float4*)&As[kk * 68 + m0];
            float4 a1 = *(const float4*)&As[kk * 68 + m0 + 4];
            float4 w  = *(const float4*)&Ws[kk * 132 + n0];
            float av[8] = {a0.x, a0.y, a0.z, a0.w, a1.x, a1.y, a1.z, a1.w};
#pragma unroll
            for (int i = 0; i < 8; i++) {
                acc[i][0] += av[i] * w.x;
                acc[i][1] += av[i] * w.y;
                acc[i][2] += av[i] * w.z;
                acc[i][3] += av[i] * w.w;
            }
        }
    }
    float4 bb = *(const float4*)&B[n0];
    float4 hh = *(const float4*)&H[n0];
#pragma unroll
    for (int i = 0; i < 8; i++) {
        float p = fmaxf(acc[i][0] + bb.x, 0.f) * hh.x
                + fmaxf(acc[i][1] + bb.y, 0.f) * hh.y
                + fmaxf(acc[i][2] + bb.z, 0.f) * hh.z
                + fmaxf(acc[i][3] + bb.w, 0.f) * hh.w;
#pragma unroll
        for (int o = 16; o; o >>= 1) p += __shfl_down_sync(0xffffffffu, p, o);
        if (tx == 0) {
            int gr = r0 + m0 + i;
            if (gr < n) s[gr] = p;
        }
    }
}

// ---- log-softmax (blocks 0..4) + gram/colsum zero (blocks 5..20) ----
__global__ void __launch_bounds__(1024) k_ls() {
    if (blockIdx.x >= 5) {
        int i = (blockIdx.x - 5) * 1024 + threadIdx.x;  // 16*1024 = 16384 = EMB*EMB
        g_gd[i] = 0.f;
        g_gp[i] = 0.f;
        if (i < EMB) { g_sd[i] = 0.f; g_sp[i] = 0.f; }
        return;
    }
    int head = blockIdx.x;
    float* s; int n;
    switch (head) {
        case 0: s = g_wdrug; n = D_NUM; break;
        case 1: s = g_wpro;  n = P_NUM; break;
        case 2: s = g_wdrel; n = D_NUM; break;
        case 3: s = g_wprel; n = P_NUM; break;
        default:s = g_wdsim; n = D_NUM; break;
    }
    __shared__ float sh[1024];
    int t = threadIdx.x;
    float m = -1e30f;
    for (int i = t; i < n; i += 1024) m = fmaxf(m, s[i]);
    sh[t] = m; __syncthreads();
    for (int o = 512; o; o >>= 1) { if (t < o) sh[t] = fmaxf(sh[t], sh[t + o]); __syncthreads(); }
    float mall = sh[0]; __syncthreads();
    float sum = 0.0f;
    for (int i = t; i < n; i += 1024) sum += expf(s[i] - mall);
    sh[t] = sum; __syncthreads();
    for (int o = 512; o; o >>= 1) { if (t < o) sh[t] += sh[t + o]; __syncthreads(); }
    float lse = mall + logf(sh[0]);
    for (int i = t; i < n; i += 1024) s[i] -= lse;
}

// ---- fused combine + bf16 hi/lo write + Gram + colsum + stats ----
__global__ void __launch_bounds__(256) k_comb_gram() {
    __shared__ __align__(16) float sbuf[16 * 132];
    bool isD = blockIdx.x < 32;
    int n    = isD ? D_NUM : P_NUM;
    int brel = isD ? (int)blockIdx.x : (int)blockIdx.x - 32;
    int nblk = isD ? 32 : 96;
    float* gG  = isD ? g_gd : g_gp;
    float* gS  = isD ? g_sd : g_sp;
    __nv_bfloat16* fh = isD ? g_fdh : g_fph;
    __nv_bfloat16* fl = isD ? g_fdl : g_fpl;
    int ntiles = (n + 15) >> 4;
    int tid = threadIdx.x;
    int k0 = (tid & 15) * 8, l0 = (tid >> 4) * 8;
    float accG[8][8];
#pragma unroll
    for (int i = 0; i < 8; i++)
#pragma unroll
        for (int j = 0; j < 8; j++) accG[i][j] = 0.f;
    float cs = 0.f;
    for (int t = brel; t < ntiles; t += nblk) {
        int r0 = t << 4;
        __syncthreads();
        for (int i = tid; i < 16 * 128; i += 256) {
            int rr = i >> 7, kk = i & 127;
            int gr = r0 + rr;
            float val = 0.f;
            if (gr < n) {
                size_t o = (size_t)gr * EMB + kk;
                if (isD) {
                    float wa = g_wdrug[gr], wb = g_wdrel[gr], wc = g_wdsim[gr];
                    float a = wa / (wa + wb + wc);
                    float bq = wb / (a + wb + wc);
                    float c = 1.0f - a - bq;
                    val = a * g_dru_int[o] + bq * g_emb2[o] + c * g_emb4[o];
                } else {
                    float wa = g_wpro[gr], wb = g_wprel[gr];
                    float pa = wa / (wa + wb);
                    val = pa * g_pro_int[o] + (1.0f - pa) * g_emb3[o];
                }
                __nv_bfloat16 h = __float2bfloat16(val);
                float hf = __bfloat162float(h);
                __nv_bfloat16 l = __float2bfloat16(val - hf);
                fh[o] = h;
                fl[o] = l;
                val = hf + __bfloat162float(l);
            }
            sbuf[rr * 132 + kk] = val;
        }
        __syncthreads();
#pragma unroll 4
        for (int r = 0; r < 16; r++) {
            const float* row = &sbuf[r * 132];
            float4 a0 = *(const float4*)(row + k0);
            float4 a1 = *(const float4*)(row + k0 + 4);
            float4 b0 = *(const float4*)(row + l0);
            float4 b1 = *(const float4*)(row + l0 + 4);
            float av[8] = {a0.x, a0.y, a0.z, a0.w, a1.x, a1.y, a1.z, a1.w};
            float bv[8] = {b0.x, b0.y, b0.z, b0.w, b1.x, b1.y, b1.z, b1.w};
#pragma unroll
            for (int i = 0; i < 8; i++)
#pragma unroll
                for (int j = 0; j < 8; j++) accG[i][j] += av[i] * bv[j];
        }
        if (tid < 128) {
            float c = 0.f;
            for (int r = 0; r < 16; r++) c += sbuf[r * 132 + tid];
            cs += c;
        }
    }
#pragma unroll
    for (int i = 0; i < 8; i++)
#pragma unroll
        for (int j = 0; j < 8; j++)
            atomicAdd(&gG[(k0 + i) * EMB + (l0 + j)], accG[i][j]);
    if (tid < 128) atomicAdd(&gS[tid], cs);

    __threadfence();
    __syncthreads();
    __shared__ int slast;
    if (tid == 0) slast = (atomicAdd(&g_done, 1u) == 127u) ? 1 : 0;
    __syncthreads();
    if (slast) {
        double* sd = (double*)sbuf;
        double acc = 0.0;
        for (int i = tid; i < EMB * EMB; i += 256)
            acc += (double)g_gd[i] * (double)g_gp[i];
        sd[tid] = acc; __syncthreads();
        for (int o = 128; o; o >>= 1) { if (tid < o) sd[tid] += sd[tid + o]; __syncthreads(); }
        double sumsq = sd[0]; __syncthreads();
        double a2 = (tid < EMB) ? (double)g_sd[tid] * (double)g_sp[tid] : 0.0;
        sd[tid] = a2; __syncthreads();
        for (int o = 128; o; o >>= 1) { if (tid < o) sd[tid] += sd[tid + o]; __syncthreads(); }
        if (tid == 0) {
            double sumy = sd[0];
            const double nn = (double)D_NUM * (double)P_NUM;
            double mean = sumy / nn;
            double var = (sumsq - sumy * sumy / nn) / (nn - 1.0);
            g_musig = make_float2((float)mean, (float)(1.0 / sqrt(var)));
        }
    }
}

// ====== final GEMM: warp-level bf16 mma.sync, loads precomputed hi/lo ======
#define FS 136
#define SM_AH_OFF 0
#define SM_AL_OFF (128*FS*2)
#define SM_BH_OFF (2*128*FS*2)
#define SM_BL_OFF (3*128*FS*2)
#define SMEM_MMA  (4*128*FS*2)

__device__ __forceinline__ void mma_bf16(
    float& c0, float& c1, float& c2, float& c3,
    uint32_t a0, uint32_t a1, uint32_t a2, uint32_t a3,
    uint32_t b0, uint32_t b1) {
    asm volatile(
        "mma.sync.aligned.m16n8k16.row.col.f32.bf16.bf16.f32 "
        "{%0,%1,%2,%3}, {%4,%5,%6,%7}, {%8,%9}, {%0,%1,%2,%3};"
        : "+f"(c0), "+f"(c1), "+f"(c2), "+f"(c3)
        : "r"(a0), "r"(a1), "r"(a2), "r"(a3), "r"(b0), "r"(b1));
}

__global__ void __launch_bounds__(256) k_final_mma(float* __restrict__ out) {
    extern __shared__ __align__(16) char smem[];
    __nv_bfloat16* Ah = (__nv_bfloat16*)(smem + SM_AH_OFF);
    __nv_bfloat16* Al = (__nv_bfloat16*)(smem + SM_AL_OFF);
    __nv_bfloat16* Bh = (__nv_bfloat16*)(smem + SM_BH_OFF);
    __nv_bfloat16* Bl = (__nv_bfloat16*)(smem + SM_BL_OFF);

    int t = threadIdx.x;
    int bi = blockIdx.y * 128, bj = blockIdx.x * 128;
    float2 ms = g_musig;
    float mu = ms.x, istd = ms.y;

    {
        int row = t >> 1;
        int c0 = (t & 1) * 64;
        int gi = bi + row, gj = bj + row;
        const uint4 z = make_uint4(0u, 0u, 0u, 0u);
        const uint4* sah = (gi < D_NUM) ? (const uint4*)&g_fdh[(size_t)gi * EMB + c0] : 0;
        const uint4* sal = (gi < D_NUM) ? (const uint4*)&g_fdl[(size_t)gi * EMB + c0] : 0;
        const uint4* sbh = (gj < P_NUM) ? (const uint4*)&g_fph[(size_t)gj * EMB + c0] : 0;
        const uint4* sbl = (gj < P_NUM) ? (const uint4*)&g_fpl[(size_t)gj * EMB + c0] : 0;
        int o = row * FS + c0;
#pragma unroll
        for (int q = 0; q < 8; q++) {
            *(uint4*)&Ah[o + q * 8] = sah ? __ldg(&sah[q]) : z;
            *(uint4*)&Al[o + q * 8] = sal ? __ldg(&sal[q]) : z;
            *(uint4*)&Bh[o + q * 8] = sbh ? __ldg(&sbh[q]) : z;
            *(uint4*)&Bl[o + q * 8] = sbl ? __ldg(&sbl[q]) : z;
        }
    }
    __syncthreads();

    int wid = t >> 5, lane = t & 31;
    int wm = wid & 3, wn = wid >> 2;
    int g = lane >> 2, ctid = lane & 3;
    int m_base = wm * 32, n_base = wn * 64;

    float acc[2][8][4];
#pragma unroll
    for (int mt = 0; mt < 2; mt++)
#pragma unroll
        for (int nt = 0; nt < 8; nt++)
#pragma unroll
            for (int e = 0; e < 4; e++) acc[mt][nt][e] = 0.f;

#pragma unroll
    for (int pass = 0; pass < 3; pass++) {
        const __nv_bfloat16* Asel = (pass == 2) ? Al : Ah;
        const __nv_bfloat16* Bsel = (pass == 1) ? Bl : Bh;
#pragma unroll
        for (int ks = 0; ks < 8; ks++) {
            int k0 = ks * 16;
            uint32_t af[2][4];
#pragma unroll
            for (int mt = 0; mt < 2; mt++) {
                int r = m_base + mt * 16;
                const __nv_bfloat16* ap = Asel + (size_t)(r + g) * FS + k0 + ctid * 2;
                af[mt][0] = *(const uint32_t*)ap;
                af[mt][1] = *(const uint32_t*)(ap + 8 * FS);
                af[mt][2] = *(const uint32_t*)(ap + 8);
                af[mt][3] = *(const uint32_t*)(ap + 8 * FS + 8);
            }
            uint32_t bf[8][2];
#pragma unroll
            for (int nt = 0; nt < 8; nt++) {
                int nn = n_base + nt * 8 + g;
                const __nv_bfloat16* bp = Bsel + (size_t)nn * FS + k0 + ctid * 2;
                bf[nt][0] = *(const uint32_t*)bp;
                bf[nt][1] = *(const uint32_t*)(bp + 8);
            }
#pragma unroll
            for (int mt = 0; mt < 2; mt++)
#pragma unroll
                for (int nt = 0; nt < 8; nt++)
                    mma_bf16(acc[mt][nt][0], acc[mt][nt][1], acc[mt][nt][2], acc[mt][nt][3],
                             af[mt][0], af[mt][1], af[mt][2], af[mt][3],
                             bf[nt][0], bf[nt][1]);
        }
    }

#pragma unroll
    for (int mt = 0; mt < 2; mt++) {
#pragma unroll
        for (int nt = 0; nt < 8; nt++) {
            int gj0 = bj + n_base + nt * 8 + ctid * 2;
#pragma unroll
            for (int half = 0; half < 2; half++) {
                int gi = bi + m_base + mt * 16 + g + half * 8;
                if (gi < D_NUM) {
                    float v0 = acc[mt][nt][half * 2 + 0];
                    float v1 = acc[mt][nt][half * 2 + 1];
                    float z0 = (v0 - mu) * istd;
                    float z1 = (v1 - mu) * istd;
                    float s0 = __fdividef(1.0f, 1.0f + __expf(-z0));
                    float s1 = __fdividef(1.0f, 1.0f + __expf(-z1));
                    if (gj0 + 1 < P_NUM) {
                        *(float2*)&out[(size_t)gi * P_NUM + gj0] = make_float2(s0, s1);
                    } else if (gj0 < P_NUM) {
                        out[(size_t)gi * P_NUM + gj0] = s0;
                    }
                }
            }
        }
    }
}

// ---------------- host launcher ----------------
extern "C" void kernel_launch(void* const* d_in, const int* in_sizes, int n_in,
                              void* d_out, int out_size) {
    const float* A                 = (const float*)d_in[0];
    const float* drug_structure    = (const float*)d_in[1];
    const float* protein_structure = (const float*)d_in[2];
    const float* lin_drug_w = (const float*)d_in[3];
    const float* lin_drug_b = (const float*)d_in[4];
    const float* lin_pro_w  = (const float*)d_in[5];
    const float* lin_pro_b  = (const float*)d_in[6];
    const float* p_weight   = (const float*)d_in[7];
    const float* d_weight_i = (const float*)d_in[8];
    const float* pd_weight_p = (const float*)d_in[9];
    const float* pd_weight_d = (const float*)d_in[10];
    const float* dp_weight_p = (const float*)d_in[11];
    const float* WA_drug = (const float*)d_in[12];
    const float* BA_drug = (const float*)d_in[13];
    const float* HA_drug = (const float*)d_in[14];
    const float* WB_drug = (const float*)d_in[15];
    const float* BB_drug = (const float*)d_in[16];
    const float* HB_drug = (const float*)d_in[17];
    const float* WA_pro = (const float*)d_in[18];
    const float* BA_pro = (const float*)d_in[19];
    const float* HA_pro = (const float*)d_in[20];
    const float* WB_pro = (const float*)d_in[21];
    const float* BB_pro = (const float*)d_in[22];
    const float* HB_pro = (const float*)d_in[23];
    const float* WA_sim = (const float*)d_in[24];
    const float* BA_sim = (const float*)d_in[25];
    const float* HA_sim = (const float*)d_in[26];
    float* out = (float*)d_out;
    (void)in_sizes; (void)n_in; (void)out_size;

    void* tp;
    cudaGetSymbolAddress(&tp, g_curRT);
    cudaMemsetAsync(tp, 0, P_NUM * sizeof(int), 0);

    k_ell_all<<<9000, 256>>>(A);
    k_lift<<<97, 256>>>(drug_structure, protein_structure,
                        lin_drug_w, lin_drug_b, lin_pro_w, lin_pro_b,
                        dp_weight_p, pd_weight_d);
    k_gemm2<<<190, 256>>>(d_weight_i, p_weight, pd_weight_d, pd_weight_p);
    k_m2<<<3 * DBK + 2 * PBK + 18, 256>>>();
    k_m3<<<4 * DBK + 3 * PBK, 256>>>();
    k_m4<<<71 + 3 * DBK + 2 * PBK, 256>>>();
    k_m5<<<2 * DBK, 256>>>();
    k_m6<<<2 * PBK, 256>>>();
    k_m7<<<DBK, 256>>>();
    k_att<<<214, 256>>>(WA_drug, BA_drug, HA_drug, WA_pro, BA_pro, HA_pro,
                        WB_drug, BB_drug, HB_drug, WB_pro, BB_pro, HB_pro,
                        WA_sim, BA_sim, HA_sim);
    k_ls<<<21, 1024>>>();
    k_comb_gram<<<128, 256>>>();

    static bool attr_done = false;
    if (!attr_done) {
        cudaFuncSetAttribute(k_final_mma, cudaFuncAttributeMaxDynamicSharedMemorySize, SMEM_MMA);
        attr_done = true;
    }
    dim3 fg((P_NUM + 127) / 128, (D_NUM + 127) / 128);
    k_final_mma<<<fg, 256, SMEM_MMA>>>(out);
}